// round 1
// baseline (speedup 1.0000x reference)
#include <cuda_runtime.h>
#include <math.h>

// ---------------- problem constants ----------------
#define BATCH 8
#define CIN   128
#define COUT  256
#define HH    64
#define WW    64
#define HWSZ  4096          // 64*64
#define KK9   9
#define CK    1152          // CIN*KK9
#define NOC   27            // 18 offset + 9 modulation channels

// ---------------- scratch (static device globals; no runtime alloc) ------
__device__ float g_xT  [BATCH * HWSZ * CIN];          // x channels-last
__device__ float g_off [BATCH * NOC * HWSZ];          // offsets (raw) + modulation (sigmoid)
__device__ float g_Wc  [NOC * CK];                    // conv weights [oc][kk*128+c]
__device__ float g_Wp  [COUT * CK];                   // deform weights [o][kk*128+c]
__device__ float g_V   [BATCH * HWSZ * CK];           // sampled*mod matrix, [b][hw][kk*128+c]
__device__ float g_outT[BATCH * HWSZ * COUT];         // GEMM result, [b][hw][o]
__device__ float g_part[256 * 512];                   // BN partial sums (deterministic)
__device__ float g_scale[COUT];
__device__ float g_shift[COUT];

// ---------------- 1) transpose x -> channels-last ------------------------
__global__ void k_transpose_x(const float* __restrict__ x) {
    __shared__ float tile[32][33];
    int b   = blockIdx.z;
    int hw0 = blockIdx.x * 32;
    int c0  = blockIdx.y * 32;
    int tx = threadIdx.x, ty = threadIdx.y;
    #pragma unroll
    for (int j = 0; j < 4; j++) {
        int c = c0 + ty + j * 8;
        tile[ty + j * 8][tx] = x[((b * CIN) + c) * HWSZ + hw0 + tx];
    }
    __syncthreads();
    #pragma unroll
    for (int j = 0; j < 4; j++) {
        int hw = hw0 + ty + j * 8;
        g_xT[((b * HWSZ) + hw) * CIN + c0 + tx] = tile[tx][ty + j * 8];
    }
}

// ---------------- 2) permute weights -------------------------------------
// g_Wp[o][kk*128+c] = w_dc[o][c][kk] ; g_Wc[oc][kk*128+c] from w_off/w_mod
__global__ void k_permute_w(const float* __restrict__ w_dc,
                            const float* __restrict__ w_off,
                            const float* __restrict__ w_mod) {
    int idx = blockIdx.x * blockDim.x + threadIdx.x;
    const int NWP = COUT * CK;          // 294912
    const int NWC = NOC * CK;           // 31104
    if (idx < NWP) {
        int o  = idx / CK;
        int r  = idx - o * CK;
        int kk = r >> 7;
        int c  = r & 127;
        g_Wp[idx] = w_dc[(o * CIN + c) * KK9 + kk];
    } else if (idx < NWP + NWC) {
        int j  = idx - NWP;
        int oc = j / CK;
        int r  = j - oc * CK;
        int kk = r >> 7;
        int c  = r & 127;
        g_Wc[j] = (oc < 18) ? w_off[(oc * CIN + c) * KK9 + kk]
                            : w_mod[((oc - 18) * CIN + c) * KK9 + kk];
    }
}

// ---------------- 3) offset/modulation conv (3x3, pad 1) -----------------
// block = (b,h) row; smem tile xs[3 rows][66 cols][128 c] padded col-stride 132
__global__ void __launch_bounds__(256)
k_conv_off(const float* __restrict__ b_off, const float* __restrict__ b_mod) {
    extern __shared__ float xs[];   // 3*66*132 floats
    int bx = blockIdx.x;
    int b = bx >> 6;
    int h = bx & 63;
    int t = threadIdx.x;

    const int TILE = 3 * 66 * 128;
    for (int idx = t; idx < TILE; idx += 256) {
        int r   = idx / (66 * 128);
        int rem = idx - r * (66 * 128);
        int col = rem >> 7;
        int c   = rem & 127;
        int hy = h + r - 1;
        int wx = col - 1;
        float v = 0.f;
        if (hy >= 0 && hy < HH && wx >= 0 && wx < WW)
            v = g_xT[((b * HH + hy) * WW + wx) * CIN + c];
        xs[(r * 66 + col) * 132 + c] = v;
    }
    __syncthreads();

    if (t < 216) {
        int oc = t / 8;
        int w0 = (t & 7) * 8;
        float bias = (oc < 18) ? b_off[oc] : b_mod[oc - 18];
        float acc[8];
        #pragma unroll
        for (int p = 0; p < 8; p++) acc[p] = bias;
        const float4* W4 = (const float4*)(g_Wc + oc * CK);
        #pragma unroll
        for (int r = 0; r < 3; r++) {
            for (int c4 = 0; c4 < 32; c4++) {
                float4 xv[10];
                #pragma unroll
                for (int j = 0; j < 10; j++)
                    xv[j] = *(const float4*)&xs[(r * 66 + w0 + j) * 132 + c4 * 4];
                #pragma unroll
                for (int kx = 0; kx < 3; kx++) {
                    float4 wv = W4[(r * 3 + kx) * 32 + c4];
                    #pragma unroll
                    for (int p = 0; p < 8; p++) {
                        float4 xvv = xv[p + kx];
                        acc[p] += wv.x * xvv.x + wv.y * xvv.y
                                + wv.z * xvv.z + wv.w * xvv.w;
                    }
                }
            }
        }
        float* dst = g_off + (b * NOC + oc) * HWSZ + h * WW + w0;
        #pragma unroll
        for (int p = 0; p < 8; p++) {
            float v = acc[p];
            if (oc >= 18) v = 1.f / (1.f + __expf(-v));   // sigmoid for modulation
            dst[p] = v;
        }
    }
}

// ---------------- 4) bilinear sampling -> V -------------------------------
// block (32,8): ty = local position, tx = channel quad; grid (512, 9, 8)
__global__ void k_sample() {
    int tx  = threadIdx.x;
    int pos = blockIdx.x * 8 + threadIdx.y;
    int kk  = blockIdx.y;
    int b   = blockIdx.z;
    int h = pos >> 6, w = pos & 63;

    const float* offb = g_off + (b * NOC) * HWSZ;
    float dy = offb[(2 * kk)     * HWSZ + pos];
    float dx = offb[(2 * kk + 1) * HWSZ + pos];
    float m  = offb[(18 + kk)    * HWSZ + pos];

    float py = dy + (float)(h - 1 + kk / 3);
    float px = dx + (float)(w - 1 + kk % 3);
    float fy = floorf(py), fx = floorf(px);
    int y0 = (int)fy, x0 = (int)fx;
    float wy1 = py - fy, wx1 = px - fx;
    float wy0 = 1.f - wy1, wx0 = 1.f - wx1;

    const float4* xb = (const float4*)g_xT + (size_t)(b * HWSZ) * 32;
    float4 acc = make_float4(0.f, 0.f, 0.f, 0.f);

    #pragma unroll
    for (int cn = 0; cn < 4; cn++) {
        int yi = y0 + (cn >> 1);
        int xi = x0 + (cn & 1);
        float wt = ((cn >> 1) ? wy1 : wy0) * ((cn & 1) ? wx1 : wx0);
        bool valid = (yi >= 0) & (yi < HH) & (xi >= 0) & (xi < WW);
        float wv = valid ? wt : 0.f;
        int yc = min(max(yi, 0), HH - 1);
        int xc = min(max(xi, 0), WW - 1);
        float4 v = xb[(yc * WW + xc) * 32 + tx];
        acc.x += wv * v.x; acc.y += wv * v.y;
        acc.z += wv * v.z; acc.w += wv * v.w;
    }
    acc.x *= m; acc.y *= m; acc.z *= m; acc.w *= m;
    ((float4*)g_V)[(((size_t)(b * HWSZ) + pos) * CK + kk * 128) / 4 + tx] = acc;
}

// ---------------- 5) GEMM: outT[b][hw][o] = V[b][hw][:] . Wp[o][:] -------
// 128x128 block tile, K-step 16, 8x8 microtile with 4+4 split (bank-clean)
__global__ void __launch_bounds__(256, 2)
k_gemm() {
    __shared__ __align__(16) float As[16][132];
    __shared__ __align__(16) float Bs[16][132];
    int b = blockIdx.z;
    const float* Ab = g_V + (size_t)b * HWSZ * CK;
    int rowBlk = blockIdx.x * 128;
    int colBlk = blockIdx.y * 128;
    int t  = threadIdx.x;
    int ty = t >> 4, tx = t & 15;
    int lrow = t >> 1;
    int lk   = (t & 1) << 3;
    const float* Ap = Ab   + (size_t)(rowBlk + lrow) * CK + lk;
    const float* Bp = g_Wp + (size_t)(colBlk + lrow) * CK + lk;

    float acc[8][8];
    #pragma unroll
    for (int i = 0; i < 8; i++)
        #pragma unroll
        for (int j = 0; j < 8; j++) acc[i][j] = 0.f;

    for (int k0 = 0; k0 < CK; k0 += 16) {
        float4 a0 = *(const float4*)(Ap + k0);
        float4 a1 = *(const float4*)(Ap + k0 + 4);
        float4 b0 = *(const float4*)(Bp + k0);
        float4 b1 = *(const float4*)(Bp + k0 + 4);
        __syncthreads();
        As[lk + 0][lrow] = a0.x; As[lk + 1][lrow] = a0.y;
        As[lk + 2][lrow] = a0.z; As[lk + 3][lrow] = a0.w;
        As[lk + 4][lrow] = a1.x; As[lk + 5][lrow] = a1.y;
        As[lk + 6][lrow] = a1.z; As[lk + 7][lrow] = a1.w;
        Bs[lk + 0][lrow] = b0.x; Bs[lk + 1][lrow] = b0.y;
        Bs[lk + 2][lrow] = b0.z; Bs[lk + 3][lrow] = b0.w;
        Bs[lk + 4][lrow] = b1.x; Bs[lk + 5][lrow] = b1.y;
        Bs[lk + 6][lrow] = b1.z; Bs[lk + 7][lrow] = b1.w;
        __syncthreads();
        #pragma unroll
        for (int kk = 0; kk < 16; kk++) {
            float4 al = *(const float4*)&As[kk][ty * 4];
            float4 ah = *(const float4*)&As[kk][64 + ty * 4];
            float4 bl = *(const float4*)&Bs[kk][tx * 4];
            float4 bh = *(const float4*)&Bs[kk][64 + tx * 4];
            float ar[8] = {al.x, al.y, al.z, al.w, ah.x, ah.y, ah.z, ah.w};
            float br[8] = {bl.x, bl.y, bl.z, bl.w, bh.x, bh.y, bh.z, bh.w};
            #pragma unroll
            for (int i = 0; i < 8; i++)
                #pragma unroll
                for (int j = 0; j < 8; j++)
                    acc[i][j] += ar[i] * br[j];
        }
    }
    float* Cb = g_outT + (size_t)b * HWSZ * COUT;
    #pragma unroll
    for (int hi = 0; hi < 2; hi++)
        #pragma unroll
        for (int i = 0; i < 4; i++) {
            int r = rowBlk + hi * 64 + ty * 4 + i;
            float4 o0 = make_float4(acc[hi * 4 + i][0], acc[hi * 4 + i][1],
                                    acc[hi * 4 + i][2], acc[hi * 4 + i][3]);
            float4 o1 = make_float4(acc[hi * 4 + i][4], acc[hi * 4 + i][5],
                                    acc[hi * 4 + i][6], acc[hi * 4 + i][7]);
            *(float4*)&Cb[(size_t)r * COUT + colBlk + tx * 4]      = o0;
            *(float4*)&Cb[(size_t)r * COUT + colBlk + 64 + tx * 4] = o1;
        }
}

// ---------------- 6) BN partial stats (deterministic, no atomics) --------
__global__ void k_bn_stats() {
    int blk = blockIdx.x;           // 256 blocks, 128 rows each
    int t = threadIdx.x;            // channel
    const float* base = g_outT + (size_t)blk * 128 * COUT;
    float s = 0.f, ss = 0.f;
    #pragma unroll 4
    for (int i = 0; i < 128; i++) {
        float v = base[i * COUT + t];
        s += v; ss += v * v;
    }
    g_part[blk * 512 + t]       = s;
    g_part[blk * 512 + 256 + t] = ss;
}

// ---------------- 7) finalize BN scale/shift -----------------------------
__global__ void k_bn_final(const float* __restrict__ gamma,
                           const float* __restrict__ beta) {
    int t = threadIdx.x;
    float s = 0.f, ss = 0.f;
    for (int i = 0; i < 256; i++) {
        s  += g_part[i * 512 + t];
        ss += g_part[i * 512 + 256 + t];
    }
    const float invN = 1.f / 32768.f;
    float mean = s * invN;
    float var  = ss * invN - mean * mean;
    float inv  = rsqrtf(var + 1e-5f);
    float sc   = gamma[t] * inv;
    g_scale[t] = sc;
    g_shift[t] = beta[t] - mean * sc;
}

// ---------------- 8) affine + SiLU + transpose to NCHW -------------------
__global__ void k_epilogue(float* __restrict__ out) {
    __shared__ float tile[32][33];
    int tx = threadIdx.x, ty = threadIdx.y;
    int o0 = blockIdx.y * 32;
    int r0 = blockIdx.x * 32;
    int orq = o0 + tx;
    float sc = g_scale[orq], sh = g_shift[orq];
    #pragma unroll
    for (int j = 0; j < 4; j++) {
        int r = r0 + ty + j * 8;
        float v = g_outT[(size_t)r * COUT + orq] * sc + sh;
        v = v / (1.f + __expf(-v));
        tile[ty + j * 8][tx] = v;
    }
    __syncthreads();
    int rw = r0 + tx;
    int bb = rw >> 12;
    int hw = rw & 4095;
    #pragma unroll
    for (int j = 0; j < 4; j++) {
        int o = o0 + ty + j * 8;
        out[((size_t)(bb * COUT + o)) * HWSZ + hw] = tile[tx][ty + j * 8];
    }
}

// ---------------- launch ---------------------------------------------------
extern "C" void kernel_launch(void* const* d_in, const int* in_sizes, int n_in,
                              void* d_out, int out_size) {
    const float* x     = (const float*)d_in[0];
    const float* w_off = (const float*)d_in[1];
    const float* b_off = (const float*)d_in[2];
    const float* w_mod = (const float*)d_in[3];
    const float* b_mod = (const float*)d_in[4];
    const float* w_dc  = (const float*)d_in[5];
    const float* gamma = (const float*)d_in[6];
    const float* beta  = (const float*)d_in[7];
    float* out = (float*)d_out;

    const int convSmem = 3 * 66 * 132 * sizeof(float);   // 104544 B
    cudaFuncSetAttribute(k_conv_off, cudaFuncAttributeMaxDynamicSharedMemorySize, convSmem);

    k_transpose_x<<<dim3(HWSZ / 32, CIN / 32, BATCH), dim3(32, 8)>>>(x);

    {
        int total = COUT * CK + NOC * CK;
        k_permute_w<<<(total + 255) / 256, 256>>>(w_dc, w_off, w_mod);
    }

    k_conv_off<<<BATCH * HH, 256, convSmem>>>(b_off, b_mod);

    k_sample<<<dim3(HWSZ / 8, KK9, BATCH), dim3(32, 8)>>>();

    k_gemm<<<dim3(HWSZ / 128, COUT / 128, BATCH), 256>>>();

    k_bn_stats<<<256, 256>>>();
    k_bn_final<<<1, 256>>>(gamma, beta);

    k_epilogue<<<dim3((BATCH * HWSZ) / 32, COUT / 32), dim3(32, 8)>>>(out);
}

// round 4
// speedup vs baseline: 1.3393x; 1.3393x over previous
#include <cuda_runtime.h>
#include <cuda_bf16.h>
#include <stdint.h>
#include <math.h>

// ---------------- problem constants ----------------
#define BATCH 8
#define CIN   128
#define COUT  256
#define HH    64
#define WW    64
#define HWSZ  4096
#define KK9   9
#define CK    1152          // CIN*KK9
#define NOC   27            // 18 offset + 9 modulation channels
#define ROWS  (BATCH*HWSZ)  // 32768

// ---------------- scratch ------------------------------------------------
__device__ float g_xT  [BATCH * HWSZ * CIN];
__device__ float g_off [BATCH * NOC * HWSZ];
__device__ float g_Wc  [NOC * CK];
__device__ __nv_bfloat16 g_Wh[COUT * CK];
__device__ __nv_bfloat16 g_Wl[COUT * CK];
__device__ __nv_bfloat16 g_Vh[(size_t)ROWS * CK];
__device__ __nv_bfloat16 g_Vl[(size_t)ROWS * CK];
__device__ float g_outT[(size_t)ROWS * COUT];
__device__ float g_part[256 * 512];
__device__ float g_scale[COUT];
__device__ float g_shift[COUT];

// ---------------- ptx helpers (all plain sm_80+ PTX, no 'a' features) ----
__device__ __forceinline__ uint32_t smem_u32(const void* p) {
    uint32_t a;
    asm("{ .reg .u64 t; cvta.to.shared.u64 t, %1; cvt.u32.u64 %0, t; }"
        : "=r"(a) : "l"(p));
    return a;
}
__device__ __forceinline__ void cp16(uint32_t dst, const void* src) {
    asm volatile("cp.async.cg.shared.global [%0], [%1], 16;" :: "r"(dst), "l"(src));
}
__device__ __forceinline__ void cp_commit() {
    asm volatile("cp.async.commit_group;" ::: "memory");
}
template <int N>
__device__ __forceinline__ void cp_wait() {
    asm volatile("cp.async.wait_group %0;" :: "n"(N) : "memory");
}
__device__ __forceinline__ void ldm_x4(uint32_t* r, uint32_t addr) {
    asm volatile("ldmatrix.sync.aligned.m8n8.x4.shared.b16 {%0,%1,%2,%3}, [%4];"
        : "=r"(r[0]), "=r"(r[1]), "=r"(r[2]), "=r"(r[3]) : "r"(addr));
}
__device__ __forceinline__ void mma16816(float* d, const uint32_t* a,
                                         uint32_t b0, uint32_t b1) {
    asm volatile(
        "mma.sync.aligned.m16n8k16.row.col.f32.bf16.bf16.f32 "
        "{%0,%1,%2,%3}, {%4,%5,%6,%7}, {%8,%9}, {%0,%1,%2,%3};"
        : "+f"(d[0]), "+f"(d[1]), "+f"(d[2]), "+f"(d[3])
        : "r"(a[0]), "r"(a[1]), "r"(a[2]), "r"(a[3]), "r"(b0), "r"(b1));
}
__device__ __forceinline__ unsigned short bf16_bits(float v) {
    __nv_bfloat16 b = __float2bfloat16(v);
    return *reinterpret_cast<unsigned short*>(&b);
}

// ---------------- 1) transpose x -> channels-last ------------------------
__global__ void k_transpose_x(const float* __restrict__ x) {
    __shared__ float tile[32][33];
    int b   = blockIdx.z;
    int hw0 = blockIdx.x * 32;
    int c0  = blockIdx.y * 32;
    int tx = threadIdx.x, ty = threadIdx.y;
    #pragma unroll
    for (int j = 0; j < 4; j++) {
        int c = c0 + ty + j * 8;
        tile[ty + j * 8][tx] = x[((b * CIN) + c) * HWSZ + hw0 + tx];
    }
    __syncthreads();
    #pragma unroll
    for (int j = 0; j < 4; j++) {
        int hw = hw0 + ty + j * 8;
        g_xT[((b * HWSZ) + hw) * CIN + c0 + tx] = tile[tx][ty + j * 8];
    }
}

// ---------------- 2) permute weights (bf16 hi/lo split for deform W) -----
__global__ void k_permute_w(const float* __restrict__ w_dc,
                            const float* __restrict__ w_off,
                            const float* __restrict__ w_mod) {
    int idx = blockIdx.x * blockDim.x + threadIdx.x;
    const int NWP = COUT * CK;
    const int NWC = NOC * CK;
    if (idx < NWP) {
        int o  = idx / CK;
        int r  = idx - o * CK;
        int kk = r >> 7;
        int c  = r & 127;
        float w = w_dc[(o * CIN + c) * KK9 + kk];
        __nv_bfloat16 hi = __float2bfloat16(w);
        float lo = w - __bfloat162float(hi);
        g_Wh[idx] = hi;
        g_Wl[idx] = __float2bfloat16(lo);
    } else if (idx < NWP + NWC) {
        int j  = idx - NWP;
        int oc = j / CK;
        int r  = j - oc * CK;
        int kk = r >> 7;
        int c  = r & 127;
        g_Wc[j] = (oc < 18) ? w_off[(oc * CIN + c) * KK9 + kk]
                            : w_mod[((oc - 18) * CIN + c) * KK9 + kk];
    }
}

// ---------------- 3) offset/modulation conv (3x3, pad 1) -----------------
__global__ void __launch_bounds__(256)
k_conv_off(const float* __restrict__ b_off, const float* __restrict__ b_mod) {
    extern __shared__ float xs[];   // 3*66*132 floats
    int bx = blockIdx.x;
    int b = bx >> 6;
    int h = bx & 63;
    int t = threadIdx.x;

    const int TILE = 3 * 66 * 128;
    for (int idx = t; idx < TILE; idx += 256) {
        int r   = idx / (66 * 128);
        int rem = idx - r * (66 * 128);
        int col = rem >> 7;
        int c   = rem & 127;
        int hy = h + r - 1;
        int wx = col - 1;
        float v = 0.f;
        if (hy >= 0 && hy < HH && wx >= 0 && wx < WW)
            v = g_xT[((b * HH + hy) * WW + wx) * CIN + c];
        xs[(r * 66 + col) * 132 + c] = v;
    }
    __syncthreads();

    if (t < 216) {
        int oc = t / 8;
        int w0 = (t & 7) * 8;
        float bias = (oc < 18) ? b_off[oc] : b_mod[oc - 18];
        float acc[8];
        #pragma unroll
        for (int p = 0; p < 8; p++) acc[p] = bias;
        const float4* W4 = (const float4*)(g_Wc + oc * CK);
        #pragma unroll
        for (int r = 0; r < 3; r++) {
            for (int c4 = 0; c4 < 32; c4++) {
                float4 xv[10];
                #pragma unroll
                for (int j = 0; j < 10; j++)
                    xv[j] = *(const float4*)&xs[(r * 66 + w0 + j) * 132 + c4 * 4];
                #pragma unroll
                for (int kx = 0; kx < 3; kx++) {
                    float4 wv = W4[(r * 3 + kx) * 32 + c4];
                    #pragma unroll
                    for (int p = 0; p < 8; p++) {
                        float4 xvv = xv[p + kx];
                        acc[p] += wv.x * xvv.x + wv.y * xvv.y
                                + wv.z * xvv.z + wv.w * xvv.w;
                    }
                }
            }
        }
        float* dst = g_off + (b * NOC + oc) * HWSZ + h * WW + w0;
        #pragma unroll
        for (int p = 0; p < 8; p++) {
            float v = acc[p];
            if (oc >= 18) v = 1.f / (1.f + __expf(-v));
            dst[p] = v;
        }
    }
}

// ---------------- 4) bilinear sampling -> Vh/Vl (bf16 split) -------------
__global__ void k_sample() {
    int tx  = threadIdx.x;
    int pos = blockIdx.x * 8 + threadIdx.y;
    int kk  = blockIdx.y;
    int b   = blockIdx.z;
    int h = pos >> 6, w = pos & 63;

    const float* offb = g_off + (b * NOC) * HWSZ;
    float dy = offb[(2 * kk)     * HWSZ + pos];
    float dx = offb[(2 * kk + 1) * HWSZ + pos];
    float m  = offb[(18 + kk)    * HWSZ + pos];

    float py = dy + (float)(h - 1 + kk / 3);
    float px = dx + (float)(w - 1 + kk % 3);
    float fy = floorf(py), fx = floorf(px);
    int y0 = (int)fy, x0 = (int)fx;
    float wy1 = py - fy, wx1 = px - fx;
    float wy0 = 1.f - wy1, wx0 = 1.f - wx1;

    const float4* xb = (const float4*)g_xT + (size_t)(b * HWSZ) * 32;
    float4 acc = make_float4(0.f, 0.f, 0.f, 0.f);

    #pragma unroll
    for (int cn = 0; cn < 4; cn++) {
        int yi = y0 + (cn >> 1);
        int xi = x0 + (cn & 1);
        float wt = ((cn >> 1) ? wy1 : wy0) * ((cn & 1) ? wx1 : wx0);
        bool valid = (yi >= 0) & (yi < HH) & (xi >= 0) & (xi < WW);
        float wv = valid ? wt : 0.f;
        int yc = min(max(yi, 0), HH - 1);
        int xc = min(max(xi, 0), WW - 1);
        float4 v = xb[(yc * WW + xc) * 32 + tx];
        acc.x += wv * v.x; acc.y += wv * v.y;
        acc.z += wv * v.z; acc.w += wv * v.w;
    }
    acc.x *= m; acc.y *= m; acc.z *= m; acc.w *= m;

    unsigned short h0 = bf16_bits(acc.x), h1 = bf16_bits(acc.y);
    unsigned short h2 = bf16_bits(acc.z), h3 = bf16_bits(acc.w);
    __nv_bfloat16 bh0 = *reinterpret_cast<__nv_bfloat16*>(&h0);
    __nv_bfloat16 bh1 = *reinterpret_cast<__nv_bfloat16*>(&h1);
    __nv_bfloat16 bh2 = *reinterpret_cast<__nv_bfloat16*>(&h2);
    __nv_bfloat16 bh3 = *reinterpret_cast<__nv_bfloat16*>(&h3);
    unsigned short l0 = bf16_bits(acc.x - __bfloat162float(bh0));
    unsigned short l1 = bf16_bits(acc.y - __bfloat162float(bh1));
    unsigned short l2 = bf16_bits(acc.z - __bfloat162float(bh2));
    unsigned short l3 = bf16_bits(acc.w - __bfloat162float(bh3));

    uint2 uh, ul;
    uh.x = (uint32_t)h0 | ((uint32_t)h1 << 16);
    uh.y = (uint32_t)h2 | ((uint32_t)h3 << 16);
    ul.x = (uint32_t)l0 | ((uint32_t)l1 << 16);
    ul.y = (uint32_t)l2 | ((uint32_t)l3 << 16);

    size_t e = ((size_t)(b * HWSZ) + pos) * CK + kk * 128 + tx * 4;
    *reinterpret_cast<uint2*>((char*)g_Vh + e * 2) = uh;
    *reinterpret_cast<uint2*>((char*)g_Vl + e * 2) = ul;
}

// ---------------- 5) mma.sync bf16-split GEMM -----------------------------
// C[ROWS,256] = V[ROWS,1152] . W^T ;  3 passes: Ah*Bh + Al*Bh + Ah*Bl.
// CTA tile 128x128, K chunk 32, double-buffered cp.async.
// smem row stride 80B -> ldmatrix wavefronts hit all 32 banks.
#define ROWB       80
#define MAT_BYTES  (128 * ROWB)        // 10240
#define STAGE_B    (4 * MAT_BYTES)     // 40960
#define GEMM_SMEM  (2 * STAGE_B)       // 81920

__device__ __forceinline__ void gemm_load_stage(uint32_t buf, int c,
                                                int rowBlk, int colBlk, int tid) {
    #pragma unroll
    for (int it = 0; it < 8; it++) {
        const int mat = it >> 1;                     // 0=Ah 1=Al 2=Bh 3=Bl
        int rem = ((it & 1) << 8) + tid;             // 0..511
        int row = rem >> 2;
        int cc  = rem & 3;
        const char* gsrc;
        size_t off;
        if (mat < 2) off = ((size_t)(rowBlk + row) * CK + c * 32) * 2 + cc * 16;
        else         off = ((size_t)(colBlk + row) * CK + c * 32) * 2 + cc * 16;
        if      (mat == 0) gsrc = (const char*)g_Vh + off;
        else if (mat == 1) gsrc = (const char*)g_Vl + off;
        else if (mat == 2) gsrc = (const char*)g_Wh + off;
        else               gsrc = (const char*)g_Wl + off;
        cp16(buf + mat * MAT_BYTES + row * ROWB + cc * 16, gsrc);
    }
}

__global__ void __launch_bounds__(256, 2) k_gemm_mma() {
    extern __shared__ __align__(128) char sm[];
    const uint32_t base = smem_u32(sm);
    const int tid  = threadIdx.x;
    const int lane = tid & 31;
    const int wid  = tid >> 5;
    const int rowBlk = blockIdx.x * 128;
    const int colBlk = blockIdx.y * 128;

    const int warpRow  = (wid >> 1) * 32;   // 4 m-warps
    const int warpColN = (wid & 1) * 64;    // 2 n-warps
    const int lrow  = lane & 15;
    const int lhalf = (lane >> 4) * 16;     // +16B for k8-15 matrices

    float acc[2][8][4];
    #pragma unroll
    for (int i = 0; i < 2; i++)
        #pragma unroll
        for (int j = 0; j < 8; j++)
            #pragma unroll
            for (int q = 0; q < 4; q++) acc[i][j][q] = 0.f;

    gemm_load_stage(base, 0, rowBlk, colBlk, tid);
    cp_commit();

    for (int c = 0; c < 36; c++) {
        int s = c & 1;
        if (c + 1 < 36) {
            gemm_load_stage(base + ((c + 1) & 1) * STAGE_B, c + 1, rowBlk, colBlk, tid);
            cp_commit();
            cp_wait<1>();
        } else {
            cp_wait<0>();
        }
        __syncthreads();

        uint32_t bufA_h = base + s * STAGE_B;
        uint32_t bufA_l = bufA_h + MAT_BYTES;
        uint32_t bufB_h = bufA_h + 2 * MAT_BYTES;
        uint32_t bufB_l = bufA_h + 3 * MAT_BYTES;

        #pragma unroll
        for (int ks = 0; ks < 2; ks++) {
            uint32_t aoff = (uint32_t)(warpRow + lrow) * ROWB + ks * 32 + lhalf;
            uint32_t ah0[4], ah1[4], al0[4], al1[4];
            ldm_x4(ah0, bufA_h + aoff);
            ldm_x4(ah1, bufA_h + aoff + 16 * ROWB);
            ldm_x4(al0, bufA_l + aoff);
            ldm_x4(al1, bufA_l + aoff + 16 * ROWB);

            #pragma unroll
            for (int pr = 0; pr < 4; pr++) {
                uint32_t boff = (uint32_t)(warpColN + pr * 16 + lrow) * ROWB
                              + ks * 32 + lhalf;
                uint32_t bh[4];
                ldm_x4(bh, bufB_h + boff);
                // tile n=2*pr uses {bh[0],bh[2]}, n=2*pr+1 uses {bh[1],bh[3]}
                mma16816(acc[0][2 * pr],     ah0, bh[0], bh[2]);
                mma16816(acc[0][2 * pr + 1], ah0, bh[1], bh[3]);
                mma16816(acc[1][2 * pr],     ah1, bh[0], bh[2]);
                mma16816(acc[1][2 * pr + 1], ah1, bh[1], bh[3]);
                mma16816(acc[0][2 * pr],     al0, bh[0], bh[2]);
                mma16816(acc[0][2 * pr + 1], al0, bh[1], bh[3]);
                mma16816(acc[1][2 * pr],     al1, bh[0], bh[2]);
                mma16816(acc[1][2 * pr + 1], al1, bh[1], bh[3]);
                uint32_t bl[4];
                ldm_x4(bl, bufB_l + boff);
                mma16816(acc[0][2 * pr],     ah0, bl[0], bl[2]);
                mma16816(acc[0][2 * pr + 1], ah0, bl[1], bl[3]);
                mma16816(acc[1][2 * pr],     ah1, bl[0], bl[2]);
                mma16816(acc[1][2 * pr + 1], ah1, bl[1], bl[3]);
            }
        }
        __syncthreads();
    }

    // ---- store accumulators to g_outT (row-major [ROWS][COUT])
    #pragma unroll
    for (int mi = 0; mi < 2; mi++) {
        int r0 = rowBlk + warpRow + mi * 16 + lane / 4;
        #pragma unroll
        for (int ni = 0; ni < 8; ni++) {
            int c0 = colBlk + warpColN + ni * 8 + (lane & 3) * 2;
            float2 v0 = make_float2(acc[mi][ni][0], acc[mi][ni][1]);
            float2 v1 = make_float2(acc[mi][ni][2], acc[mi][ni][3]);
            *(float2*)&g_outT[(size_t)r0 * COUT + c0]       = v0;
            *(float2*)&g_outT[(size_t)(r0 + 8) * COUT + c0] = v1;
        }
    }
}

// ---------------- 6) BN partial stats (deterministic) --------------------
__global__ void k_bn_stats() {
    int blk = blockIdx.x;
    int t = threadIdx.x;
    const float* bb = g_outT + (size_t)blk * 128 * COUT;
    float s = 0.f, ss = 0.f;
    #pragma unroll 4
    for (int i = 0; i < 128; i++) {
        float v = bb[i * COUT + t];
        s += v; ss += v * v;
    }
    g_part[blk * 512 + t]       = s;
    g_part[blk * 512 + 256 + t] = ss;
}

// ---------------- 7) finalize BN scale/shift -----------------------------
__global__ void k_bn_final(const float* __restrict__ gamma,
                           const float* __restrict__ beta) {
    int t = threadIdx.x;
    float s = 0.f, ss = 0.f;
    for (int i = 0; i < 256; i++) {
        s  += g_part[i * 512 + t];
        ss += g_part[i * 512 + 256 + t];
    }
    const float invN = 1.f / 32768.f;
    float mean = s * invN;
    float var  = ss * invN - mean * mean;
    float inv  = rsqrtf(var + 1e-5f);
    float sc   = gamma[t] * inv;
    g_scale[t] = sc;
    g_shift[t] = beta[t] - mean * sc;
}

// ---------------- 8) affine + SiLU + transpose to NCHW -------------------
__global__ void k_epilogue(float* __restrict__ out) {
    __shared__ float tile[32][33];
    int tx = threadIdx.x, ty = threadIdx.y;
    int o0 = blockIdx.y * 32;
    int r0 = blockIdx.x * 32;
    int orq = o0 + tx;
    float sc = g_scale[orq], sh = g_shift[orq];
    #pragma unroll
    for (int j = 0; j < 4; j++) {
        int r = r0 + ty + j * 8;
        float v = g_outT[(size_t)r * COUT + orq] * sc + sh;
        v = v / (1.f + __expf(-v));
        tile[ty + j * 8][tx] = v;
    }
    __syncthreads();
    int rw = r0 + tx;
    int bb = rw >> 12;
    int hw = rw & 4095;
    #pragma unroll
    for (int j = 0; j < 4; j++) {
        int o = o0 + ty + j * 8;
        out[((size_t)(bb * COUT + o)) * HWSZ + hw] = tile[tx][ty + j * 8];
    }
}

// ---------------- launch ---------------------------------------------------
extern "C" void kernel_launch(void* const* d_in, const int* in_sizes, int n_in,
                              void* d_out, int out_size) {
    const float* x     = (const float*)d_in[0];
    const float* w_off = (const float*)d_in[1];
    const float* b_off = (const float*)d_in[2];
    const float* w_mod = (const float*)d_in[3];
    const float* b_mod = (const float*)d_in[4];
    const float* w_dc  = (const float*)d_in[5];
    const float* gamma = (const float*)d_in[6];
    const float* beta  = (const float*)d_in[7];
    float* out = (float*)d_out;

    const int convSmem = 3 * 66 * 132 * sizeof(float);
    cudaFuncSetAttribute(k_conv_off, cudaFuncAttributeMaxDynamicSharedMemorySize, convSmem);
    cudaFuncSetAttribute(k_gemm_mma, cudaFuncAttributeMaxDynamicSharedMemorySize, GEMM_SMEM);

    k_transpose_x<<<dim3(HWSZ / 32, CIN / 32, BATCH), dim3(32, 8)>>>(x);

    {
        int total = COUT * CK + NOC * CK;
        k_permute_w<<<(total + 255) / 256, 256>>>(w_dc, w_off, w_mod);
    }

    k_conv_off<<<BATCH * HH, 256, convSmem>>>(b_off, b_mod);

    k_sample<<<dim3(HWSZ / 8, KK9, BATCH), dim3(32, 8)>>>();

    k_gemm_mma<<<dim3(ROWS / 128, COUT / 128), 256, GEMM_SMEM>>>();

    k_bn_stats<<<256, 256>>>();
    k_bn_final<<<1, 256>>>(gamma, beta);

    k_epilogue<<<dim3((BATCH * HWSZ) / 32, COUT / 32), dim3(32, 8)>>>(out);
}

// round 5
// speedup vs baseline: 1.4494x; 1.0822x over previous
#include <cuda_runtime.h>
#include <cuda_bf16.h>
#include <stdint.h>
#include <math.h>

// ---------------- problem constants ----------------
#define BATCH 8
#define CIN   128
#define COUT  256
#define HH    64
#define WW    64
#define HWSZ  4096
#define KK9   9
#define CK    1152          // CIN*KK9
#define NOC   27            // 18 offset + 9 modulation channels
#define ROWS  (BATCH*HWSZ)  // 32768

// ---------------- scratch ------------------------------------------------
__device__ float g_xT  [BATCH * HWSZ * CIN];
__device__ float g_off [BATCH * NOC * HWSZ];
__device__ float g_Wc  [NOC * CK];
__device__ __nv_bfloat16 g_Wh[COUT * CK];
__device__ __nv_bfloat16 g_Wl[COUT * CK];
__device__ __nv_bfloat16 g_Vh[(size_t)ROWS * CK];
__device__ __nv_bfloat16 g_Vl[(size_t)ROWS * CK];
__device__ float g_outT[(size_t)ROWS * COUT];
__device__ float g_part[256 * 512];
__device__ float g_scale[COUT];
__device__ float g_shift[COUT];

// ---------------- ptx helpers (plain sm_80+ PTX only) --------------------
__device__ __forceinline__ uint32_t smem_u32(const void* p) {
    uint32_t a;
    asm("{ .reg .u64 t; cvta.to.shared.u64 t, %1; cvt.u32.u64 %0, t; }"
        : "=r"(a) : "l"(p));
    return a;
}
__device__ __forceinline__ void cp16(uint32_t dst, const void* src) {
    asm volatile("cp.async.cg.shared.global [%0], [%1], 16;" :: "r"(dst), "l"(src));
}
__device__ __forceinline__ void cp_commit() {
    asm volatile("cp.async.commit_group;" ::: "memory");
}
template <int N>
__device__ __forceinline__ void cp_wait() {
    asm volatile("cp.async.wait_group %0;" :: "n"(N) : "memory");
}
__device__ __forceinline__ void ldm_x4(uint32_t* r, uint32_t addr) {
    asm volatile("ldmatrix.sync.aligned.m8n8.x4.shared.b16 {%0,%1,%2,%3}, [%4];"
        : "=r"(r[0]), "=r"(r[1]), "=r"(r[2]), "=r"(r[3]) : "r"(addr));
}
__device__ __forceinline__ void mma16816(float* d, const uint32_t* a,
                                         uint32_t b0, uint32_t b1) {
    asm volatile(
        "mma.sync.aligned.m16n8k16.row.col.f32.bf16.bf16.f32 "
        "{%0,%1,%2,%3}, {%4,%5,%6,%7}, {%8,%9}, {%0,%1,%2,%3};"
        : "+f"(d[0]), "+f"(d[1]), "+f"(d[2]), "+f"(d[3])
        : "r"(a[0]), "r"(a[1]), "r"(a[2]), "r"(a[3]), "r"(b0), "r"(b1));
}
__device__ __forceinline__ unsigned short bf16_bits(float v) {
    __nv_bfloat16 b = __float2bfloat16(v);
    return *reinterpret_cast<unsigned short*>(&b);
}
__device__ __forceinline__ float2 bf2_to_f2(uint32_t u) {
    __nv_bfloat162 h = *reinterpret_cast<__nv_bfloat162*>(&u);
    return __bfloat1622float2(h);
}

// ---------------- 1) prep: transpose x + permute/split weights -----------
__global__ void k_prep(const float* __restrict__ x,
                       const float* __restrict__ w_dc,
                       const float* __restrict__ w_off,
                       const float* __restrict__ w_mod) {
    if (blockIdx.z < 8) {
        __shared__ float tile[32][33];
        int b   = blockIdx.z;
        int hw0 = blockIdx.x * 32;
        int c0  = blockIdx.y * 32;
        int tx = threadIdx.x, ty = threadIdx.y;
        #pragma unroll
        for (int j = 0; j < 4; j++) {
            int c = c0 + ty + j * 8;
            tile[ty + j * 8][tx] = x[((b * CIN) + c) * HWSZ + hw0 + tx];
        }
        __syncthreads();
        #pragma unroll
        for (int j = 0; j < 4; j++) {
            int hw = hw0 + ty + j * 8;
            g_xT[((b * HWSZ) + hw) * CIN + c0 + tx] = tile[tx][ty + j * 8];
        }
    } else {
        const int NWP = COUT * CK;
        const int NWC = NOC * CK;
        int t = threadIdx.y * 32 + threadIdx.x;
        int gidx = (blockIdx.y * 128 + blockIdx.x) * 256 + t;
        for (int idx = gidx; idx < NWP + NWC; idx += 512 * 256) {
            if (idx < NWP) {
                int o  = idx / CK;
                int r  = idx - o * CK;
                int kk = r >> 7;
                int c  = r & 127;
                float w = w_dc[(o * CIN + c) * KK9 + kk];
                __nv_bfloat16 hi = __float2bfloat16(w);
                float lo = w - __bfloat162float(hi);
                g_Wh[idx] = hi;
                g_Wl[idx] = __float2bfloat16(lo);
            } else {
                int j  = idx - NWP;
                int oc = j / CK;
                int r  = j - oc * CK;
                int kk = r >> 7;
                int c  = r & 127;
                g_Wc[j] = (oc < 18) ? w_off[(oc * CIN + c) * KK9 + kk]
                                    : w_mod[((oc - 18) * CIN + c) * KK9 + kk];
            }
        }
    }
}

// ---------------- 2) offset/modulation conv (3x3, pad 1) -----------------
// lane mapping: oc = t/8, w0 = t&7, px = w0 + 8p  -> conflict-free LDS
__global__ void __launch_bounds__(256)
k_conv_off(const float* __restrict__ b_off, const float* __restrict__ b_mod) {
    extern __shared__ float xs[];   // [3*66][132] floats
    int bx = blockIdx.x;
    int b = bx >> 6;
    int h = bx & 63;
    int t = threadIdx.x;

    const int TILE = 3 * 66 * 128;
    for (int idx = t; idx < TILE; idx += 256) {
        int r   = idx / (66 * 128);
        int rem = idx - r * (66 * 128);
        int col = rem >> 7;
        int c   = rem & 127;
        int hy = h + r - 1;
        int wx = col - 1;
        float v = 0.f;
        if (hy >= 0 && hy < HH && wx >= 0 && wx < WW)
            v = g_xT[((b * HH + hy) * WW + wx) * CIN + c];
        xs[(r * 66 + col) * 132 + c] = v;
    }
    __syncthreads();

    if (t < 216) {
        int oc = t / 8;
        int w0 = t & 7;
        float bias = (oc < 18) ? b_off[oc] : b_mod[oc - 18];
        float acc[8];
        #pragma unroll
        for (int p = 0; p < 8; p++) acc[p] = bias;
        const float4* W4  = (const float4*)(g_Wc + oc * CK);
        const float4* xs4 = (const float4*)xs;
        #pragma unroll
        for (int r = 0; r < 3; r++) {
            for (int c4 = 0; c4 < 32; c4++) {
                float4 wv0 = W4[(r * 3 + 0) * 32 + c4];
                float4 wv1 = W4[(r * 3 + 1) * 32 + c4];
                float4 wv2 = W4[(r * 3 + 2) * 32 + c4];
                #pragma unroll
                for (int p = 0; p < 8; p++) {
                    int base = (r * 66 + w0 + 8 * p) * 33 + c4;
                    float4 x0 = xs4[base];
                    float4 x1 = xs4[base + 33];
                    float4 x2 = xs4[base + 66];
                    acc[p] += wv0.x * x0.x + wv0.y * x0.y + wv0.z * x0.z + wv0.w * x0.w
                            + wv1.x * x1.x + wv1.y * x1.y + wv1.z * x1.z + wv1.w * x1.w
                            + wv2.x * x2.x + wv2.y * x2.y + wv2.z * x2.z + wv2.w * x2.w;
                }
            }
        }
        float* dst = g_off + (b * NOC + oc) * HWSZ + h * WW;
        #pragma unroll
        for (int p = 0; p < 8; p++) {
            float v = acc[p];
            if (oc >= 18) v = 1.f / (1.f + __expf(-v));
            dst[w0 + 8 * p] = v;
        }
    }
}

// ---------------- 3) bilinear sampling -> Vh/Vl (bf16 split) -------------
__global__ void k_sample() {
    int tx  = threadIdx.x;
    int pos = blockIdx.x * 8 + threadIdx.y;
    int kk  = blockIdx.y;
    int b   = blockIdx.z;
    int h = pos >> 6, w = pos & 63;

    const float* offb = g_off + (b * NOC) * HWSZ;
    float dy = offb[(2 * kk)     * HWSZ + pos];
    float dx = offb[(2 * kk + 1) * HWSZ + pos];
    float m  = offb[(18 + kk)    * HWSZ + pos];

    float py = dy + (float)(h - 1 + kk / 3);
    float px = dx + (float)(w - 1 + kk % 3);
    float fy = floorf(py), fx = floorf(px);
    int y0 = (int)fy, x0 = (int)fx;
    float wy1 = py - fy, wx1 = px - fx;
    float wy0 = 1.f - wy1, wx0 = 1.f - wx1;

    const float4* xb = (const float4*)g_xT + (size_t)(b * HWSZ) * 32;
    float4 acc = make_float4(0.f, 0.f, 0.f, 0.f);

    #pragma unroll
    for (int cn = 0; cn < 4; cn++) {
        int yi = y0 + (cn >> 1);
        int xi = x0 + (cn & 1);
        float wt = ((cn >> 1) ? wy1 : wy0) * ((cn & 1) ? wx1 : wx0);
        bool valid = (yi >= 0) & (yi < HH) & (xi >= 0) & (xi < WW);
        float wv = valid ? wt : 0.f;
        int yc = min(max(yi, 0), HH - 1);
        int xc = min(max(xi, 0), WW - 1);
        float4 v = xb[(yc * WW + xc) * 32 + tx];
        acc.x += wv * v.x; acc.y += wv * v.y;
        acc.z += wv * v.z; acc.w += wv * v.w;
    }
    acc.x *= m; acc.y *= m; acc.z *= m; acc.w *= m;

    unsigned short h0 = bf16_bits(acc.x), h1 = bf16_bits(acc.y);
    unsigned short h2 = bf16_bits(acc.z), h3 = bf16_bits(acc.w);
    __nv_bfloat16 bh0 = *reinterpret_cast<__nv_bfloat16*>(&h0);
    __nv_bfloat16 bh1 = *reinterpret_cast<__nv_bfloat16*>(&h1);
    __nv_bfloat16 bh2 = *reinterpret_cast<__nv_bfloat16*>(&h2);
    __nv_bfloat16 bh3 = *reinterpret_cast<__nv_bfloat16*>(&h3);
    unsigned short l0 = bf16_bits(acc.x - __bfloat162float(bh0));
    unsigned short l1 = bf16_bits(acc.y - __bfloat162float(bh1));
    unsigned short l2 = bf16_bits(acc.z - __bfloat162float(bh2));
    unsigned short l3 = bf16_bits(acc.w - __bfloat162float(bh3));

    uint2 uh, ul;
    uh.x = (uint32_t)h0 | ((uint32_t)h1 << 16);
    uh.y = (uint32_t)h2 | ((uint32_t)h3 << 16);
    ul.x = (uint32_t)l0 | ((uint32_t)l1 << 16);
    ul.y = (uint32_t)l2 | ((uint32_t)l3 << 16);

    size_t e = ((size_t)(b * HWSZ) + pos) * CK + kk * 128 + tx * 4;
    *reinterpret_cast<uint2*>((char*)g_Vh + e * 2) = uh;
    *reinterpret_cast<uint2*>((char*)g_Vl + e * 2) = ul;
}

// ---------------- 4) hybrid GEMM: tensor tiles + fp32 FFMA tiles ----------
// 512 tiles of 128x128 over C[32768, 256].  (tile&15)<10 -> tensor (bf16
// 3-pass split on HMMA pipe), else fp32 SIMT tile on FMA pipe. Both block
// types co-resident per SM -> pipes overlap.
#define ROWB       80
#define MAT_BYTES  (128 * ROWB)        // 10240
#define STAGE_B    (4 * MAT_BYTES)     // 40960
#define GEMM_SMEM  (2 * STAGE_B)       // 81920

__device__ __forceinline__ void gemm_load_stage(uint32_t buf, int c,
                                                int rowBlk, int colBlk, int tid) {
    #pragma unroll
    for (int it = 0; it < 8; it++) {
        const int mat = it >> 1;                     // 0=Ah 1=Al 2=Bh 3=Bl
        int rem = ((it & 1) << 8) + tid;             // 0..511
        int row = rem >> 2;
        int cc  = rem & 3;
        const char* gsrc;
        size_t off;
        if (mat < 2) off = ((size_t)(rowBlk + row) * CK + c * 32) * 2 + cc * 16;
        else         off = ((size_t)(colBlk + row) * CK + c * 32) * 2 + cc * 16;
        if      (mat == 0) gsrc = (const char*)g_Vh + off;
        else if (mat == 1) gsrc = (const char*)g_Vl + off;
        else if (mat == 2) gsrc = (const char*)g_Wh + off;
        else               gsrc = (const char*)g_Wl + off;
        cp16(buf + mat * MAT_BYTES + row * ROWB + cc * 16, gsrc);
    }
}

__device__ void gemm_tensor_tile(char* sm, int rowBlk, int colBlk) {
    const uint32_t base = smem_u32(sm);
    const int tid  = threadIdx.x;
    const int lane = tid & 31;
    const int wid  = tid >> 5;

    const int warpRow  = (wid >> 1) * 32;
    const int warpColN = (wid & 1) * 64;
    const int lrow  = lane & 15;
    const int lhalf = (lane >> 4) * 16;

    float acc[2][8][4];
    #pragma unroll
    for (int i = 0; i < 2; i++)
        #pragma unroll
        for (int j = 0; j < 8; j++)
            #pragma unroll
            for (int q = 0; q < 4; q++) acc[i][j][q] = 0.f;

    gemm_load_stage(base, 0, rowBlk, colBlk, tid);
    cp_commit();

    for (int c = 0; c < 36; c++) {
        int s = c & 1;
        if (c + 1 < 36) {
            gemm_load_stage(base + ((c + 1) & 1) * STAGE_B, c + 1, rowBlk, colBlk, tid);
            cp_commit();
            cp_wait<1>();
        } else {
            cp_wait<0>();
        }
        __syncthreads();

        uint32_t bufA_h = base + s * STAGE_B;
        uint32_t bufA_l = bufA_h + MAT_BYTES;
        uint32_t bufB_h = bufA_h + 2 * MAT_BYTES;
        uint32_t bufB_l = bufA_h + 3 * MAT_BYTES;

        #pragma unroll
        for (int ks = 0; ks < 2; ks++) {
            uint32_t aoff = (uint32_t)(warpRow + lrow) * ROWB + ks * 32 + lhalf;
            uint32_t ah0[4], ah1[4], al0[4], al1[4];
            ldm_x4(ah0, bufA_h + aoff);
            ldm_x4(ah1, bufA_h + aoff + 16 * ROWB);
            ldm_x4(al0, bufA_l + aoff);
            ldm_x4(al1, bufA_l + aoff + 16 * ROWB);

            #pragma unroll
            for (int pr = 0; pr < 4; pr++) {
                uint32_t boff = (uint32_t)(warpColN + pr * 16 + lrow) * ROWB
                              + ks * 32 + lhalf;
                uint32_t bh[4];
                ldm_x4(bh, bufB_h + boff);
                mma16816(acc[0][2 * pr],     ah0, bh[0], bh[2]);
                mma16816(acc[0][2 * pr + 1], ah0, bh[1], bh[3]);
                mma16816(acc[1][2 * pr],     ah1, bh[0], bh[2]);
                mma16816(acc[1][2 * pr + 1], ah1, bh[1], bh[3]);
                mma16816(acc[0][2 * pr],     al0, bh[0], bh[2]);
                mma16816(acc[0][2 * pr + 1], al0, bh[1], bh[3]);
                mma16816(acc[1][2 * pr],     al1, bh[0], bh[2]);
                mma16816(acc[1][2 * pr + 1], al1, bh[1], bh[3]);
                uint32_t bl[4];
                ldm_x4(bl, bufB_l + boff);
                mma16816(acc[0][2 * pr],     ah0, bl[0], bl[2]);
                mma16816(acc[0][2 * pr + 1], ah0, bl[1], bl[3]);
                mma16816(acc[1][2 * pr],     ah1, bl[0], bl[2]);
                mma16816(acc[1][2 * pr + 1], ah1, bl[1], bl[3]);
            }
        }
        __syncthreads();
    }

    #pragma unroll
    for (int mi = 0; mi < 2; mi++) {
        int r0 = rowBlk + warpRow + mi * 16 + lane / 4;
        #pragma unroll
        for (int ni = 0; ni < 8; ni++) {
            int c0 = colBlk + warpColN + ni * 8 + (lane & 3) * 2;
            float2 v0 = make_float2(acc[mi][ni][0], acc[mi][ni][1]);
            float2 v1 = make_float2(acc[mi][ni][2], acc[mi][ni][3]);
            *(float2*)&g_outT[(size_t)r0 * COUT + c0]       = v0;
            *(float2*)&g_outT[(size_t)(r0 + 8) * COUT + c0] = v1;
        }
    }
}

__device__ void gemm_ffma_tile(char* sm, int rowBlk, int colBlk) {
    float* As = (float*)sm;                 // [16][132]
    float* Bs = As + 16 * 132;              // [16][132]
    int t  = threadIdx.x;
    int ty = t >> 4, tx = t & 15;
    int lrow = t >> 1;
    int lk   = (t & 1) << 3;

    const size_t abase = (size_t)(rowBlk + lrow) * CK + lk;
    const size_t bbase = (size_t)(colBlk + lrow) * CK + lk;

    float acc[8][8];
    #pragma unroll
    for (int i = 0; i < 8; i++)
        #pragma unroll
        for (int j = 0; j < 8; j++) acc[i][j] = 0.f;

    for (int k0 = 0; k0 < CK; k0 += 16) {
        uint4 ahv = *(const uint4*)((const char*)g_Vh + (abase + k0) * 2);
        uint4 alv = *(const uint4*)((const char*)g_Vl + (abase + k0) * 2);
        uint4 bhv = *(const uint4*)((const char*)g_Wh + (bbase + k0) * 2);
        uint4 blv = *(const uint4*)((const char*)g_Wl + (bbase + k0) * 2);
        float a[8], bb[8];
        {
            float2 h0 = bf2_to_f2(ahv.x), l0 = bf2_to_f2(alv.x);
            float2 h1 = bf2_to_f2(ahv.y), l1 = bf2_to_f2(alv.y);
            float2 h2 = bf2_to_f2(ahv.z), l2 = bf2_to_f2(alv.z);
            float2 h3 = bf2_to_f2(ahv.w), l3 = bf2_to_f2(alv.w);
            a[0] = h0.x + l0.x; a[1] = h0.y + l0.y;
            a[2] = h1.x + l1.x; a[3] = h1.y + l1.y;
            a[4] = h2.x + l2.x; a[5] = h2.y + l2.y;
            a[6] = h3.x + l3.x; a[7] = h3.y + l3.y;
            h0 = bf2_to_f2(bhv.x); l0 = bf2_to_f2(blv.x);
            h1 = bf2_to_f2(bhv.y); l1 = bf2_to_f2(blv.y);
            h2 = bf2_to_f2(bhv.z); l2 = bf2_to_f2(blv.z);
            h3 = bf2_to_f2(bhv.w); l3 = bf2_to_f2(blv.w);
            bb[0] = h0.x + l0.x; bb[1] = h0.y + l0.y;
            bb[2] = h1.x + l1.x; bb[3] = h1.y + l1.y;
            bb[4] = h2.x + l2.x; bb[5] = h2.y + l2.y;
            bb[6] = h3.x + l3.x; bb[7] = h3.y + l3.y;
        }
        __syncthreads();
        #pragma unroll
        for (int i = 0; i < 8; i++) {
            As[(lk + i) * 132 + lrow] = a[i];
            Bs[(lk + i) * 132 + lrow] = bb[i];
        }
        __syncthreads();
        #pragma unroll
        for (int kk = 0; kk < 16; kk++) {
            float4 al = *(const float4*)&As[kk * 132 + ty * 4];
            float4 ah = *(const float4*)&As[kk * 132 + 64 + ty * 4];
            float4 bl = *(const float4*)&Bs[kk * 132 + tx * 4];
            float4 bh = *(const float4*)&Bs[kk * 132 + 64 + tx * 4];
            float ar[8] = {al.x, al.y, al.z, al.w, ah.x, ah.y, ah.z, ah.w};
            float br[8] = {bl.x, bl.y, bl.z, bl.w, bh.x, bh.y, bh.z, bh.w};
            #pragma unroll
            for (int i = 0; i < 8; i++)
                #pragma unroll
                for (int j = 0; j < 8; j++)
                    acc[i][j] += ar[i] * br[j];
        }
    }
    #pragma unroll
    for (int hi = 0; hi < 2; hi++)
        #pragma unroll
        for (int i = 0; i < 4; i++) {
            int r = rowBlk + hi * 64 + ty * 4 + i;
            float4 o0 = make_float4(acc[hi * 4 + i][0], acc[hi * 4 + i][1],
                                    acc[hi * 4 + i][2], acc[hi * 4 + i][3]);
            float4 o1 = make_float4(acc[hi * 4 + i][4], acc[hi * 4 + i][5],
                                    acc[hi * 4 + i][6], acc[hi * 4 + i][7]);
            *(float4*)&g_outT[(size_t)r * COUT + colBlk + tx * 4]      = o0;
            *(float4*)&g_outT[(size_t)r * COUT + colBlk + 64 + tx * 4] = o1;
        }
}

__global__ void __launch_bounds__(256, 2) k_gemm_hyb() {
    extern __shared__ __align__(128) char sm[];
    int tile = blockIdx.x;                 // 0..511
    int rowBlk = (tile >> 1) * 128;
    int colBlk = (tile & 1) * 128;
    if ((tile & 15) < 10) gemm_tensor_tile(sm, rowBlk, colBlk);
    else                  gemm_ffma_tile(sm, rowBlk, colBlk);
}

// ---------------- 5) BN partial stats (deterministic) --------------------
__global__ void k_bn_stats() {
    int blk = blockIdx.x;
    int t = threadIdx.x;
    const float* bb = g_outT + (size_t)blk * 128 * COUT;
    float s = 0.f, ss = 0.f;
    #pragma unroll 4
    for (int i = 0; i < 128; i++) {
        float v = bb[i * COUT + t];
        s += v; ss += v * v;
    }
    g_part[blk * 512 + t]       = s;
    g_part[blk * 512 + 256 + t] = ss;
}

// ---------------- 6) finalize BN scale/shift -----------------------------
__global__ void k_bn_final(const float* __restrict__ gamma,
                           const float* __restrict__ beta) {
    int t = threadIdx.x;
    float s = 0.f, ss = 0.f;
    for (int i = 0; i < 256; i++) {
        s  += g_part[i * 512 + t];
        ss += g_part[i * 512 + 256 + t];
    }
    const float invN = 1.f / 32768.f;
    float mean = s * invN;
    float var  = ss * invN - mean * mean;
    float inv  = rsqrtf(var + 1e-5f);
    float sc   = gamma[t] * inv;
    g_scale[t] = sc;
    g_shift[t] = beta[t] - mean * sc;
}

// ---------------- 7) affine + SiLU + transpose to NCHW -------------------
__global__ void k_epilogue(float* __restrict__ out) {
    __shared__ float tile[32][33];
    int tx = threadIdx.x, ty = threadIdx.y;
    int o0 = blockIdx.y * 32;
    int r0 = blockIdx.x * 32;
    int orq = o0 + tx;
    float sc = g_scale[orq], sh = g_shift[orq];
    #pragma unroll
    for (int j = 0; j < 4; j++) {
        int r = r0 + ty + j * 8;
        float v = g_outT[(size_t)r * COUT + orq] * sc + sh;
        v = v / (1.f + __expf(-v));
        tile[ty + j * 8][tx] = v;
    }
    __syncthreads();
    int rw = r0 + tx;
    int bb = rw >> 12;
    int hw = rw & 4095;
    #pragma unroll
    for (int j = 0; j < 4; j++) {
        int o = o0 + ty + j * 8;
        out[((size_t)(bb * COUT + o)) * HWSZ + hw] = tile[tx][ty + j * 8];
    }
}

// ---------------- launch ---------------------------------------------------
extern "C" void kernel_launch(void* const* d_in, const int* in_sizes, int n_in,
                              void* d_out, int out_size) {
    const float* x     = (const float*)d_in[0];
    const float* w_off = (const float*)d_in[1];
    const float* b_off = (const float*)d_in[2];
    const float* w_mod = (const float*)d_in[3];
    const float* b_mod = (const float*)d_in[4];
    const float* w_dc  = (const float*)d_in[5];
    const float* gamma = (const float*)d_in[6];
    const float* beta  = (const float*)d_in[7];
    float* out = (float*)d_out;

    const int convSmem = 3 * 66 * 132 * sizeof(float);
    cudaFuncSetAttribute(k_conv_off, cudaFuncAttributeMaxDynamicSharedMemorySize, convSmem);
    cudaFuncSetAttribute(k_gemm_hyb, cudaFuncAttributeMaxDynamicSharedMemorySize, GEMM_SMEM);

    k_prep<<<dim3(HWSZ / 32, CIN / 32, 9), dim3(32, 8)>>>(x, w_dc, w_off, w_mod);

    k_conv_off<<<BATCH * HH, 256, convSmem>>>(b_off, b_mod);

    k_sample<<<dim3(HWSZ / 8, KK9, BATCH), dim3(32, 8)>>>();

    k_gemm_hyb<<<512, 256, GEMM_SMEM>>>();

    k_bn_stats<<<256, 256>>>();
    k_bn_final<<<1, 256>>>(gamma, beta);

    k_epilogue<<<dim3((BATCH * HWSZ) / 32, COUT / 32), dim3(32, 8)>>>(out);
}

// round 6
// speedup vs baseline: 2.5106x; 1.7322x over previous
#include <cuda_runtime.h>
#include <cuda_fp16.h>
#include <stdint.h>
#include <math.h>

// ---------------- problem constants ----------------
#define BATCH 8
#define CIN   128
#define COUT  256
#define HH    64
#define WW    64
#define HWSZ  4096
#define KK9   9
#define CK    1152          // CIN*KK9
#define NOC   27            // 18 offset + 9 modulation channels
#define ROWS  (BATCH*HWSZ)  // 32768

// ---------------- scratch ------------------------------------------------
__device__ float g_xT  [BATCH * HWSZ * CIN];
__device__ float g_off [BATCH * NOC * HWSZ];
__device__ float g_Wc  [NOC * CK];
__device__ __half g_Wh[COUT * CK];              // weight hi (fp16)
__device__ __half g_Wl[COUT * CK];              // weight lo (fp16 residual)
__device__ __half g_V [(size_t)ROWS * CK];      // sampled*mod (fp16)
__device__ float g_outT[(size_t)ROWS * COUT];
__device__ float g_part[256 * 512];
__device__ float g_scale[COUT];
__device__ float g_shift[COUT];

// ---------------- ptx helpers (plain sm_80+ PTX only) --------------------
__device__ __forceinline__ uint32_t smem_u32(const void* p) {
    uint32_t a;
    asm("{ .reg .u64 t; cvta.to.shared.u64 t, %1; cvt.u32.u64 %0, t; }"
        : "=r"(a) : "l"(p));
    return a;
}
__device__ __forceinline__ void cp16(uint32_t dst, const void* src) {
    asm volatile("cp.async.cg.shared.global [%0], [%1], 16;" :: "r"(dst), "l"(src));
}
__device__ __forceinline__ void cp_commit() {
    asm volatile("cp.async.commit_group;" ::: "memory");
}
template <int N>
__device__ __forceinline__ void cp_wait() {
    asm volatile("cp.async.wait_group %0;" :: "n"(N) : "memory");
}
__device__ __forceinline__ void ldm_x4(uint32_t* r, uint32_t addr) {
    asm volatile("ldmatrix.sync.aligned.m8n8.x4.shared.b16 {%0,%1,%2,%3}, [%4];"
        : "=r"(r[0]), "=r"(r[1]), "=r"(r[2]), "=r"(r[3]) : "r"(addr));
}
__device__ __forceinline__ void mma_f16(float* d, const uint32_t* a,
                                        uint32_t b0, uint32_t b1) {
    asm volatile(
        "mma.sync.aligned.m16n8k16.row.col.f32.f16.f16.f32 "
        "{%0,%1,%2,%3}, {%4,%5,%6,%7}, {%8,%9}, {%0,%1,%2,%3};"
        : "+f"(d[0]), "+f"(d[1]), "+f"(d[2]), "+f"(d[3])
        : "r"(a[0]), "r"(a[1]), "r"(a[2]), "r"(a[3]), "r"(b0), "r"(b1));
}

// ---------------- 1) prep: transpose x + permute/split weights -----------
__global__ void k_prep(const float* __restrict__ x,
                       const float* __restrict__ w_dc,
                       const float* __restrict__ w_off,
                       const float* __restrict__ w_mod) {
    if (blockIdx.z < 8) {
        __shared__ float tile[32][33];
        int b   = blockIdx.z;
        int hw0 = blockIdx.x * 32;
        int c0  = blockIdx.y * 32;
        int tx = threadIdx.x, ty = threadIdx.y;
        #pragma unroll
        for (int j = 0; j < 4; j++) {
            int c = c0 + ty + j * 8;
            tile[ty + j * 8][tx] = x[((b * CIN) + c) * HWSZ + hw0 + tx];
        }
        __syncthreads();
        #pragma unroll
        for (int j = 0; j < 4; j++) {
            int hw = hw0 + ty + j * 8;
            g_xT[((b * HWSZ) + hw) * CIN + c0 + tx] = tile[tx][ty + j * 8];
        }
    } else {
        const int NWP = COUT * CK;
        const int NWC = NOC * CK;
        int t = threadIdx.y * 32 + threadIdx.x;
        int gidx = (blockIdx.y * 128 + blockIdx.x) * 256 + t;
        for (int idx = gidx; idx < NWP + NWC; idx += 512 * 256) {
            if (idx < NWP) {
                int o  = idx / CK;
                int r  = idx - o * CK;
                int kk = r >> 7;
                int c  = r & 127;
                float w = w_dc[(o * CIN + c) * KK9 + kk];
                __half hi = __float2half(w);
                float lo = w - __half2float(hi);
                g_Wh[idx] = hi;
                g_Wl[idx] = __float2half(lo);
            } else {
                int j  = idx - NWP;
                int oc = j / CK;
                int r  = j - oc * CK;
                int kk = r >> 7;
                int c  = r & 127;
                g_Wc[j] = (oc < 18) ? w_off[(oc * CIN + c) * KK9 + kk]
                                    : w_mod[((oc - 18) * CIN + c) * KK9 + kk];
            }
        }
    }
}

// ---------------- 2) offset/modulation conv (3x3, pad 1) -----------------
__global__ void __launch_bounds__(256)
k_conv_off(const float* __restrict__ b_off, const float* __restrict__ b_mod) {
    extern __shared__ float xs[];   // [3*66][132] floats
    int bx = blockIdx.x;
    int b = bx >> 6;
    int h = bx & 63;
    int t = threadIdx.x;

    const int TILE = 3 * 66 * 128;
    for (int idx = t; idx < TILE; idx += 256) {
        int r   = idx / (66 * 128);
        int rem = idx - r * (66 * 128);
        int col = rem >> 7;
        int c   = rem & 127;
        int hy = h + r - 1;
        int wx = col - 1;
        float v = 0.f;
        if (hy >= 0 && hy < HH && wx >= 0 && wx < WW)
            v = g_xT[((b * HH + hy) * WW + wx) * CIN + c];
        xs[(r * 66 + col) * 132 + c] = v;
    }
    __syncthreads();

    if (t < 216) {
        int oc = t / 8;
        int w0 = t & 7;
        float bias = (oc < 18) ? b_off[oc] : b_mod[oc - 18];
        float acc[8];
        #pragma unroll
        for (int p = 0; p < 8; p++) acc[p] = bias;
        const float4* W4  = (const float4*)(g_Wc + oc * CK);
        const float4* xs4 = (const float4*)xs;
        #pragma unroll
        for (int r = 0; r < 3; r++) {
            for (int c4 = 0; c4 < 32; c4++) {
                float4 wv0 = W4[(r * 3 + 0) * 32 + c4];
                float4 wv1 = W4[(r * 3 + 1) * 32 + c4];
                float4 wv2 = W4[(r * 3 + 2) * 32 + c4];
                #pragma unroll
                for (int p = 0; p < 8; p++) {
                    int base = (r * 66 + w0 + 8 * p) * 33 + c4;
                    float4 x0 = xs4[base];
                    float4 x1 = xs4[base + 33];
                    float4 x2 = xs4[base + 66];
                    acc[p] += wv0.x * x0.x + wv0.y * x0.y + wv0.z * x0.z + wv0.w * x0.w
                            + wv1.x * x1.x + wv1.y * x1.y + wv1.z * x1.z + wv1.w * x1.w
                            + wv2.x * x2.x + wv2.y * x2.y + wv2.z * x2.z + wv2.w * x2.w;
                }
            }
        }
        float* dst = g_off + (b * NOC + oc) * HWSZ + h * WW;
        #pragma unroll
        for (int p = 0; p < 8; p++) {
            float v = acc[p];
            if (oc >= 18) v = 1.f / (1.f + __expf(-v));
            dst[w0 + 8 * p] = v;
        }
    }
}

// ---------------- 3) bilinear sampling -> V (fp16) ------------------------
__global__ void k_sample() {
    int tx  = threadIdx.x;
    int pos = blockIdx.x * 8 + threadIdx.y;
    int kk  = blockIdx.y;
    int b   = blockIdx.z;
    int h = pos >> 6, w = pos & 63;

    const float* offb = g_off + (b * NOC) * HWSZ;
    float dy = offb[(2 * kk)     * HWSZ + pos];
    float dx = offb[(2 * kk + 1) * HWSZ + pos];
    float m  = offb[(18 + kk)    * HWSZ + pos];

    float py = dy + (float)(h - 1 + kk / 3);
    float px = dx + (float)(w - 1 + kk % 3);
    float fy = floorf(py), fx = floorf(px);
    int y0 = (int)fy, x0 = (int)fx;
    float wy1 = py - fy, wx1 = px - fx;
    float wy0 = 1.f - wy1, wx0 = 1.f - wx1;

    const float4* xb = (const float4*)g_xT + (size_t)(b * HWSZ) * 32;
    float4 acc = make_float4(0.f, 0.f, 0.f, 0.f);

    #pragma unroll
    for (int cn = 0; cn < 4; cn++) {
        int yi = y0 + (cn >> 1);
        int xi = x0 + (cn & 1);
        float wt = ((cn >> 1) ? wy1 : wy0) * ((cn & 1) ? wx1 : wx0);
        bool valid = (yi >= 0) & (yi < HH) & (xi >= 0) & (xi < WW);
        float wv = valid ? wt : 0.f;
        int yc = min(max(yi, 0), HH - 1);
        int xc = min(max(xi, 0), WW - 1);
        float4 v = xb[(yc * WW + xc) * 32 + tx];
        acc.x += wv * v.x; acc.y += wv * v.y;
        acc.z += wv * v.z; acc.w += wv * v.w;
    }
    acc.x *= m; acc.y *= m; acc.z *= m; acc.w *= m;

    __half2 p0 = __floats2half2_rn(acc.x, acc.y);
    __half2 p1 = __floats2half2_rn(acc.z, acc.w);
    uint2 u;
    u.x = *reinterpret_cast<uint32_t*>(&p0);
    u.y = *reinterpret_cast<uint32_t*>(&p1);

    size_t e = ((size_t)(b * HWSZ) + pos) * CK + kk * 128 + tx * 4;
    *reinterpret_cast<uint2*>((char*)g_V + e * 2) = u;
}

// ---------------- 4) fp16 tensor GEMM, 2-pass (A * (Bh + Bl)) -------------
// C[ROWS,256] = V . W^T.  CTA tile 128x128, K chunk 32, double buffer.
// Per chunk: 32 MMAs/warp, accumulator reuse distance 16.
#define ROWB       80
#define MAT_BYTES  (128 * ROWB)        // 10240
#define STAGE_B    (3 * MAT_BYTES)     // 30720 (A, Bh, Bl)
#define GEMM_SMEM  (2 * STAGE_B)       // 61440

__device__ __forceinline__ void gemm_load_stage(uint32_t buf, int c,
                                                int rowBlk, int colBlk, int tid) {
    #pragma unroll
    for (int it = 0; it < 6; it++) {
        const int mat = it >> 1;                     // 0=A 1=Bh 2=Bl
        int rem = ((it & 1) << 8) + tid;             // 0..511
        int row = rem >> 2;
        int cc  = rem & 3;
        const char* gsrc;
        size_t off;
        if (mat == 0) off = ((size_t)(rowBlk + row) * CK + c * 32) * 2 + cc * 16;
        else          off = ((size_t)(colBlk + row) * CK + c * 32) * 2 + cc * 16;
        if      (mat == 0) gsrc = (const char*)g_V  + off;
        else if (mat == 1) gsrc = (const char*)g_Wh + off;
        else               gsrc = (const char*)g_Wl + off;
        cp16(buf + mat * MAT_BYTES + row * ROWB + cc * 16, gsrc);
    }
}

__global__ void __launch_bounds__(256, 2) k_gemm_f16() {
    extern __shared__ __align__(128) char sm[];
    const uint32_t base = smem_u32(sm);
    const int tid  = threadIdx.x;
    const int lane = tid & 31;
    const int wid  = tid >> 5;
    const int tile = blockIdx.x;
    const int rowBlk = (tile >> 1) * 128;
    const int colBlk = (tile & 1) * 128;

    const int warpRow  = (wid >> 1) * 32;   // 4 m-warps
    const int warpColN = (wid & 1) * 64;    // 2 n-warps
    const int lrow  = lane & 15;
    const int lhalf = (lane >> 4) * 16;

    float acc[2][8][4];
    #pragma unroll
    for (int i = 0; i < 2; i++)
        #pragma unroll
        for (int j = 0; j < 8; j++)
            #pragma unroll
            for (int q = 0; q < 4; q++) acc[i][j][q] = 0.f;

    gemm_load_stage(base, 0, rowBlk, colBlk, tid);
    cp_commit();

    for (int c = 0; c < 36; c++) {
        int s = c & 1;
        if (c + 1 < 36) {
            gemm_load_stage(base + ((c + 1) & 1) * STAGE_B, c + 1, rowBlk, colBlk, tid);
            cp_commit();
            cp_wait<1>();
        } else {
            cp_wait<0>();
        }
        __syncthreads();

        uint32_t bufA  = base + s * STAGE_B;
        uint32_t bufBh = bufA + MAT_BYTES;
        uint32_t bufBl = bufA + 2 * MAT_BYTES;

        #pragma unroll
        for (int ks = 0; ks < 2; ks++) {
            uint32_t aoff = (uint32_t)(warpRow + lrow) * ROWB + ks * 32 + lhalf;
            uint32_t a0[4], a1[4];
            ldm_x4(a0, bufA + aoff);
            ldm_x4(a1, bufA + aoff + 16 * ROWB);

            uint32_t boffs[4];
            #pragma unroll
            for (int pr = 0; pr < 4; pr++)
                boffs[pr] = (uint32_t)(warpColN + pr * 16 + lrow) * ROWB
                          + ks * 32 + lhalf;

            // pass 1: A * Bh  (16 independent accumulators)
            uint32_t bh[4][4];
            #pragma unroll
            for (int pr = 0; pr < 4; pr++) ldm_x4(bh[pr], bufBh + boffs[pr]);
            #pragma unroll
            for (int pr = 0; pr < 4; pr++) {
                mma_f16(acc[0][2 * pr],     a0, bh[pr][0], bh[pr][2]);
                mma_f16(acc[0][2 * pr + 1], a0, bh[pr][1], bh[pr][3]);
                mma_f16(acc[1][2 * pr],     a1, bh[pr][0], bh[pr][2]);
                mma_f16(acc[1][2 * pr + 1], a1, bh[pr][1], bh[pr][3]);
            }
            // pass 2: A * Bl  (same accs, reuse distance 16)
            uint32_t bl[4][4];
            #pragma unroll
            for (int pr = 0; pr < 4; pr++) ldm_x4(bl[pr], bufBl + boffs[pr]);
            #pragma unroll
            for (int pr = 0; pr < 4; pr++) {
                mma_f16(acc[0][2 * pr],     a0, bl[pr][0], bl[pr][2]);
                mma_f16(acc[0][2 * pr + 1], a0, bl[pr][1], bl[pr][3]);
                mma_f16(acc[1][2 * pr],     a1, bl[pr][0], bl[pr][2]);
                mma_f16(acc[1][2 * pr + 1], a1, bl[pr][1], bl[pr][3]);
            }
        }
        __syncthreads();
    }

    #pragma unroll
    for (int mi = 0; mi < 2; mi++) {
        int r0 = rowBlk + warpRow + mi * 16 + lane / 4;
        #pragma unroll
        for (int ni = 0; ni < 8; ni++) {
            int c0 = colBlk + warpColN + ni * 8 + (lane & 3) * 2;
            float2 v0 = make_float2(acc[mi][ni][0], acc[mi][ni][1]);
            float2 v1 = make_float2(acc[mi][ni][2], acc[mi][ni][3]);
            *(float2*)&g_outT[(size_t)r0 * COUT + c0]       = v0;
            *(float2*)&g_outT[(size_t)(r0 + 8) * COUT + c0] = v1;
        }
    }
}

// ---------------- 5) BN partial stats (deterministic) --------------------
__global__ void k_bn_stats() {
    int blk = blockIdx.x;
    int t = threadIdx.x;
    const float* bb = g_outT + (size_t)blk * 128 * COUT;
    float s = 0.f, ss = 0.f;
    #pragma unroll 4
    for (int i = 0; i < 128; i++) {
        float v = bb[i * COUT + t];
        s += v; ss += v * v;
    }
    g_part[blk * 512 + t]       = s;
    g_part[blk * 512 + 256 + t] = ss;
}

// ---------------- 6) finalize BN scale/shift -----------------------------
__global__ void k_bn_final(const float* __restrict__ gamma,
                           const float* __restrict__ beta) {
    int t = threadIdx.x;
    float s = 0.f, ss = 0.f;
    for (int i = 0; i < 256; i++) {
        s  += g_part[i * 512 + t];
        ss += g_part[i * 512 + 256 + t];
    }
    const float invN = 1.f / 32768.f;
    float mean = s * invN;
    float var  = ss * invN - mean * mean;
    float inv  = rsqrtf(var + 1e-5f);
    float sc   = gamma[t] * inv;
    g_scale[t] = sc;
    g_shift[t] = beta[t] - mean * sc;
}

// ---------------- 7) affine + SiLU + transpose to NCHW -------------------
__global__ void k_epilogue(float* __restrict__ out) {
    __shared__ float tile[32][33];
    int tx = threadIdx.x, ty = threadIdx.y;
    int o0 = blockIdx.y * 32;
    int r0 = blockIdx.x * 32;
    int orq = o0 + tx;
    float sc = g_scale[orq], sh = g_shift[orq];
    #pragma unroll
    for (int j = 0; j < 4; j++) {
        int r = r0 + ty + j * 8;
        float v = g_outT[(size_t)r * COUT + orq] * sc + sh;
        v = v / (1.f + __expf(-v));
        tile[ty + j * 8][tx] = v;
    }
    __syncthreads();
    int rw = r0 + tx;
    int bb = rw >> 12;
    int hw = rw & 4095;
    #pragma unroll
    for (int j = 0; j < 4; j++) {
        int o = o0 + ty + j * 8;
        out[((size_t)(bb * COUT + o)) * HWSZ + hw] = tile[tx][ty + j * 8];
    }
}

// ---------------- launch ---------------------------------------------------
extern "C" void kernel_launch(void* const* d_in, const int* in_sizes, int n_in,
                              void* d_out, int out_size) {
    const float* x     = (const float*)d_in[0];
    const float* w_off = (const float*)d_in[1];
    const float* b_off = (const float*)d_in[2];
    const float* w_mod = (const float*)d_in[3];
    const float* b_mod = (const float*)d_in[4];
    const float* w_dc  = (const float*)d_in[5];
    const float* gamma = (const float*)d_in[6];
    const float* beta  = (const float*)d_in[7];
    float* out = (float*)d_out;

    const int convSmem = 3 * 66 * 132 * sizeof(float);
    cudaFuncSetAttribute(k_conv_off, cudaFuncAttributeMaxDynamicSharedMemorySize, convSmem);
    cudaFuncSetAttribute(k_gemm_f16, cudaFuncAttributeMaxDynamicSharedMemorySize, GEMM_SMEM);

    k_prep<<<dim3(HWSZ / 32, CIN / 32, 9), dim3(32, 8)>>>(x, w_dc, w_off, w_mod);

    k_conv_off<<<BATCH * HH, 256, convSmem>>>(b_off, b_mod);

    k_sample<<<dim3(HWSZ / 8, KK9, BATCH), dim3(32, 8)>>>();

    k_gemm_f16<<<512, 256, GEMM_SMEM>>>();

    k_bn_stats<<<256, 256>>>();
    k_bn_final<<<1, 256>>>(gamma, beta);

    k_epilogue<<<dim3((BATCH * HWSZ) / 32, COUT / 32), dim3(32, 8)>>>(out);
}

// round 7
// speedup vs baseline: 3.5009x; 1.3944x over previous
#include <cuda_runtime.h>
#include <cuda_fp16.h>
#include <stdint.h>
#include <math.h>

// ---------------- problem constants ----------------
#define BATCH 8
#define CIN   128
#define COUT  256
#define HH    64
#define WW    64
#define HWSZ  4096
#define KK9   9
#define CK    1152          // CIN*KK9
#define NOC   27            // 18 offset + 9 modulation channels
#define ROWS  (BATCH*HWSZ)  // 32768

// ---------------- scratch ------------------------------------------------
__device__ float  g_xT [BATCH * HWSZ * CIN];        // x channels-last fp32 (sampling)
__device__ __half g_xTh[BATCH * HWSZ * CIN];        // x channels-last fp16 (conv GEMM)
__device__ float  g_off[BATCH * NOC * HWSZ];        // offsets + modulation(sigmoid)
__device__ __half g_Wch[32 * CK];                   // conv weights fp16, padded to 32 oc
__device__ __half g_Wh [COUT * CK];                 // deform weights fp16
__device__ __half g_V  [(size_t)ROWS * CK];         // sampled*mod fp16
__device__ float  g_outT[(size_t)ROWS * COUT];
__device__ float  g_part[256 * 512];
__device__ float  g_scale[COUT];
__device__ float  g_shift[COUT];

// ---------------- ptx helpers (plain sm_80+ PTX only) --------------------
__device__ __forceinline__ uint32_t smem_u32(const void* p) {
    uint32_t a;
    asm("{ .reg .u64 t; cvta.to.shared.u64 t, %1; cvt.u32.u64 %0, t; }"
        : "=r"(a) : "l"(p));
    return a;
}
__device__ __forceinline__ void cp16(uint32_t dst, const void* src) {
    asm volatile("cp.async.cg.shared.global [%0], [%1], 16;" :: "r"(dst), "l"(src));
}
__device__ __forceinline__ void cp16z(uint32_t dst, const void* src, uint32_t sz) {
    asm volatile("cp.async.cg.shared.global [%0], [%1], 16, %2;"
                 :: "r"(dst), "l"(src), "r"(sz));
}
__device__ __forceinline__ void cp_commit() {
    asm volatile("cp.async.commit_group;" ::: "memory");
}
template <int N>
__device__ __forceinline__ void cp_wait() {
    asm volatile("cp.async.wait_group %0;" :: "n"(N) : "memory");
}
__device__ __forceinline__ void ldm_x4(uint32_t* r, uint32_t addr) {
    asm volatile("ldmatrix.sync.aligned.m8n8.x4.shared.b16 {%0,%1,%2,%3}, [%4];"
        : "=r"(r[0]), "=r"(r[1]), "=r"(r[2]), "=r"(r[3]) : "r"(addr));
}
__device__ __forceinline__ void mma_f16(float* d, const uint32_t* a,
                                        uint32_t b0, uint32_t b1) {
    asm volatile(
        "mma.sync.aligned.m16n8k16.row.col.f32.f16.f16.f32 "
        "{%0,%1,%2,%3}, {%4,%5,%6,%7}, {%8,%9}, {%0,%1,%2,%3};"
        : "+f"(d[0]), "+f"(d[1]), "+f"(d[2]), "+f"(d[3])
        : "r"(a[0]), "r"(a[1]), "r"(a[2]), "r"(a[3]), "r"(b0), "r"(b1));
}

// ---------------- 1) prep: transpose x (fp32+fp16) + weights -------------
__global__ void k_prep(const float* __restrict__ x,
                       const float* __restrict__ w_dc,
                       const float* __restrict__ w_off,
                       const float* __restrict__ w_mod) {
    if (blockIdx.z < 8) {
        __shared__ float tile[32][33];
        int b   = blockIdx.z;
        int hw0 = blockIdx.x * 32;
        int c0  = blockIdx.y * 32;
        int tx = threadIdx.x, ty = threadIdx.y;
        #pragma unroll
        for (int j = 0; j < 4; j++) {
            int c = c0 + ty + j * 8;
            tile[ty + j * 8][tx] = x[((b * CIN) + c) * HWSZ + hw0 + tx];
        }
        __syncthreads();
        #pragma unroll
        for (int j = 0; j < 4; j++) {
            int hw = hw0 + ty + j * 8;
            float v = tile[tx][ty + j * 8];
            size_t o = ((size_t)(b * HWSZ) + hw) * CIN + c0 + tx;
            g_xT[o]  = v;
            g_xTh[o] = __float2half(v);
        }
    } else {
        const int NWP  = COUT * CK;         // 294912
        const int NWC2 = 32 * CK;           // 36864
        int t = threadIdx.y * 32 + threadIdx.x;
        int gidx = (blockIdx.y * 128 + blockIdx.x) * 256 + t;
        for (int idx = gidx; idx < NWP + NWC2; idx += 512 * 256) {
            if (idx < NWP) {
                int o  = idx / CK;
                int r  = idx - o * CK;
                int kk = r >> 7;
                int c  = r & 127;
                g_Wh[idx] = __float2half(w_dc[(o * CIN + c) * KK9 + kk]);
            } else {
                int j  = idx - NWP;
                int oc = j / CK;
                int r  = j - oc * CK;
                int kk = r >> 7;
                int c  = r & 127;
                float v = 0.f;
                if (oc < 18)      v = w_off[(oc * CIN + c) * KK9 + kk];
                else if (oc < 27) v = w_mod[((oc - 18) * CIN + c) * KK9 + kk];
                g_Wch[j] = __float2half(v);
            }
        }
    }
}

// ---------------- 2) conv offsets/mod via tensor cores --------------------
// C2[32768, 27] = im2col(xTh)[32768, 1152] . Wch^T, then bias/sigmoid.
#define RCWB   80
#define A2_B   (128 * RCWB)                 // 10240
#define B2_B   (32 * RCWB)                  // 2560
#define CSTG   (A2_B + B2_B)                // 12800
#define CONV_SMEM (2 * CSTG)                // 25600

__device__ __forceinline__ void conv_load_stage(uint32_t buf, int cn,
                                                int rowBlk, int tid) {
    int kk  = cn >> 2;
    int c0k = (cn & 3) * 32;
    int dy = kk / 3 - 1;
    int dx = kk % 3 - 1;
    // A: 128 rows x 64B
    {
        int row  = tid >> 1;
        int half = tid & 1;
        int pix = rowBlk * 128 + row;
        int b = pix >> 12;
        int h = (pix >> 6) & 63;
        int w = pix & 63;
        int h2 = h + dy, w2 = w + dx;
        bool valid = ((unsigned)h2 < 64u) & ((unsigned)w2 < 64u);
        size_t srcoff = valid
            ? (((size_t)b * HWSZ + h2 * 64 + w2) * CIN + c0k) * 2 : 0;
        uint32_t sz = valid ? 16u : 0u;
        const char* src = (const char*)g_xTh + srcoff + half * 32;
        uint32_t dst = buf + row * RCWB + half * 32;
        cp16z(dst,      src,      sz);
        cp16z(dst + 16, src + 16, sz);
    }
    // B: 32 rows x 64B
    if (tid < 128) {
        int row = tid >> 2;
        int q   = tid & 3;
        const char* src = (const char*)g_Wch + ((size_t)row * CK + cn * 32) * 2 + q * 16;
        cp16(buf + A2_B + row * RCWB + q * 16, src);
    }
}

__global__ void __launch_bounds__(256) k_conv_tc(const float* __restrict__ b_off,
                                                 const float* __restrict__ b_mod) {
    extern __shared__ __align__(128) char sm[];
    const uint32_t base = smem_u32(sm);
    const int tid  = threadIdx.x;
    const int lane = tid & 31;
    const int wid  = tid >> 5;
    const int rowBlk = blockIdx.x;       // 256 tiles of 128 pixels

    const int lrow  = lane & 15;
    const int lhalf = (lane >> 4) * 16;

    float acc[4][4];
    #pragma unroll
    for (int i = 0; i < 4; i++)
        #pragma unroll
        for (int q = 0; q < 4; q++) acc[i][q] = 0.f;

    conv_load_stage(base, 0, rowBlk, tid);
    cp_commit();

    for (int cn = 0; cn < 36; cn++) {
        int s = cn & 1;
        if (cn + 1 < 36) {
            conv_load_stage(base + ((cn + 1) & 1) * CSTG, cn + 1, rowBlk, tid);
            cp_commit();
            cp_wait<1>();
        } else {
            cp_wait<0>();
        }
        __syncthreads();

        uint32_t bufA = base + s * CSTG;
        uint32_t bufB = bufA + A2_B;

        #pragma unroll
        for (int ks = 0; ks < 2; ks++) {
            uint32_t a[4];
            ldm_x4(a, bufA + (uint32_t)(wid * 16 + lrow) * RCWB + ks * 32 + lhalf);
            uint32_t bfr[2][4];
            #pragma unroll
            for (int pr = 0; pr < 2; pr++)
                ldm_x4(bfr[pr], bufB + (uint32_t)(pr * 16 + lrow) * RCWB + ks * 32 + lhalf);
            #pragma unroll
            for (int pr = 0; pr < 2; pr++) {
                mma_f16(acc[2 * pr],     a, bfr[pr][0], bfr[pr][2]);
                mma_f16(acc[2 * pr + 1], a, bfr[pr][1], bfr[pr][3]);
            }
        }
        __syncthreads();
    }

    // epilogue: bias + (sigmoid for oc>=18), store transposed to g_off
    int pix0 = rowBlk * 128 + wid * 16 + (lane >> 2);
    int b = pix0 >> 12;
    #pragma unroll
    for (int ni = 0; ni < 4; ni++) {
        #pragma unroll
        for (int q = 0; q < 4; q++) {
            int oc = ni * 8 + (lane & 3) * 2 + (q & 1);
            if (oc >= NOC) continue;
            int pix = pix0 + (q >> 1) * 8;
            float bias = (oc < 18) ? b_off[oc] : b_mod[oc - 18];
            float v = acc[ni][q] + bias;
            if (oc >= 18) v = 1.f / (1.f + __expf(-v));
            g_off[((size_t)b * NOC + oc) * HWSZ + (pix & 4095)] = v;
        }
    }
}

// ---------------- 3) bilinear sampling -> V (fp16) ------------------------
__global__ void k_sample() {
    int tx  = threadIdx.x;
    int pos = blockIdx.x * 8 + threadIdx.y;
    int kk  = blockIdx.y;
    int b   = blockIdx.z;
    int h = pos >> 6, w = pos & 63;

    const float* offb = g_off + (b * NOC) * HWSZ;
    float dy = offb[(2 * kk)     * HWSZ + pos];
    float dx = offb[(2 * kk + 1) * HWSZ + pos];
    float m  = offb[(18 + kk)    * HWSZ + pos];

    float py = dy + (float)(h - 1 + kk / 3);
    float px = dx + (float)(w - 1 + kk % 3);
    float fy = floorf(py), fx = floorf(px);
    int y0 = (int)fy, x0 = (int)fx;
    float wy1 = py - fy, wx1 = px - fx;
    float wy0 = 1.f - wy1, wx0 = 1.f - wx1;

    const float4* xb = (const float4*)g_xT + (size_t)(b * HWSZ) * 32;
    float4 acc = make_float4(0.f, 0.f, 0.f, 0.f);

    #pragma unroll
    for (int cn = 0; cn < 4; cn++) {
        int yi = y0 + (cn >> 1);
        int xi = x0 + (cn & 1);
        float wt = ((cn >> 1) ? wy1 : wy0) * ((cn & 1) ? wx1 : wx0);
        bool valid = (yi >= 0) & (yi < HH) & (xi >= 0) & (xi < WW);
        float wv = valid ? wt : 0.f;
        int yc = min(max(yi, 0), HH - 1);
        int xc = min(max(xi, 0), WW - 1);
        float4 v = xb[(yc * WW + xc) * 32 + tx];
        acc.x += wv * v.x; acc.y += wv * v.y;
        acc.z += wv * v.z; acc.w += wv * v.w;
    }
    acc.x *= m; acc.y *= m; acc.z *= m; acc.w *= m;

    __half2 p0 = __floats2half2_rn(acc.x, acc.y);
    __half2 p1 = __floats2half2_rn(acc.z, acc.w);
    uint2 u;
    u.x = *reinterpret_cast<uint32_t*>(&p0);
    u.y = *reinterpret_cast<uint32_t*>(&p1);

    size_t e = ((size_t)(b * HWSZ) + pos) * CK + kk * 128 + tx * 4;
    *reinterpret_cast<uint2*>((char*)g_V + e * 2) = u;
}

// ---------------- 4) fp16 tensor GEMM single-pass + fused BN --------------
#define ROWB       80
#define MAT_BYTES  (128 * ROWB)        // 10240
#define STAGE_B    (2 * MAT_BYTES)     // 20480 (A, B)
#define GEMM_SMEM  (2 * STAGE_B)       // 40960

__device__ __forceinline__ void gemm_load_stage(uint32_t buf, int c,
                                                int rowBlk, int colBlk, int tid) {
    #pragma unroll
    for (int it = 0; it < 4; it++) {
        const int mat = it >> 1;                     // 0=A 1=B
        int rem = ((it & 1) << 8) + tid;             // 0..511
        int row = rem >> 2;
        int cc  = rem & 3;
        size_t off;
        const char* gsrc;
        if (mat == 0) {
            off  = ((size_t)(rowBlk + row) * CK + c * 32) * 2 + cc * 16;
            gsrc = (const char*)g_V + off;
        } else {
            off  = ((size_t)(colBlk + row) * CK + c * 32) * 2 + cc * 16;
            gsrc = (const char*)g_Wh + off;
        }
        cp16(buf + mat * MAT_BYTES + row * ROWB + cc * 16, gsrc);
    }
}

__global__ void __launch_bounds__(256, 2) k_gemm_f16() {
    extern __shared__ __align__(128) char sm[];
    const uint32_t base = smem_u32(sm);
    const int tid  = threadIdx.x;
    const int lane = tid & 31;
    const int wid  = tid >> 5;
    const int tile = blockIdx.x;
    const int rowBlk = (tile >> 1) * 128;
    const int colBlk = (tile & 1) * 128;

    const int warpRow  = (wid >> 1) * 32;   // 4 m-warps
    const int warpColN = (wid & 1) * 64;    // 2 n-warps
    const int lrow  = lane & 15;
    const int lhalf = (lane >> 4) * 16;

    float acc[2][8][4];
    #pragma unroll
    for (int i = 0; i < 2; i++)
        #pragma unroll
        for (int j = 0; j < 8; j++)
            #pragma unroll
            for (int q = 0; q < 4; q++) acc[i][j][q] = 0.f;

    gemm_load_stage(base, 0, rowBlk, colBlk, tid);
    cp_commit();

    for (int c = 0; c < 36; c++) {
        int s = c & 1;
        if (c + 1 < 36) {
            gemm_load_stage(base + ((c + 1) & 1) * STAGE_B, c + 1, rowBlk, colBlk, tid);
            cp_commit();
            cp_wait<1>();
        } else {
            cp_wait<0>();
        }
        __syncthreads();

        uint32_t bufA = base + s * STAGE_B;
        uint32_t bufB = bufA + MAT_BYTES;

        #pragma unroll
        for (int ks = 0; ks < 2; ks++) {
            uint32_t aoff = (uint32_t)(warpRow + lrow) * ROWB + ks * 32 + lhalf;
            uint32_t a0[4], a1[4];
            ldm_x4(a0, bufA + aoff);
            ldm_x4(a1, bufA + aoff + 16 * ROWB);

            uint32_t bfr[4][4];
            #pragma unroll
            for (int pr = 0; pr < 4; pr++) {
                uint32_t boff = (uint32_t)(warpColN + pr * 16 + lrow) * ROWB
                              + ks * 32 + lhalf;
                ldm_x4(bfr[pr], bufB + boff);
            }
            #pragma unroll
            for (int pr = 0; pr < 4; pr++) {
                mma_f16(acc[0][2 * pr],     a0, bfr[pr][0], bfr[pr][2]);
                mma_f16(acc[0][2 * pr + 1], a0, bfr[pr][1], bfr[pr][3]);
                mma_f16(acc[1][2 * pr],     a1, bfr[pr][0], bfr[pr][2]);
                mma_f16(acc[1][2 * pr + 1], a1, bfr[pr][1], bfr[pr][3]);
            }
        }
        __syncthreads();
    }

    // ---- store C
    #pragma unroll
    for (int mi = 0; mi < 2; mi++) {
        int r0 = rowBlk + warpRow + mi * 16 + lane / 4;
        #pragma unroll
        for (int ni = 0; ni < 8; ni++) {
            int c0 = colBlk + warpColN + ni * 8 + (lane & 3) * 2;
            float2 v0 = make_float2(acc[mi][ni][0], acc[mi][ni][1]);
            float2 v1 = make_float2(acc[mi][ni][2], acc[mi][ni][3]);
            *(float2*)&g_outT[(size_t)r0 * COUT + c0]       = v0;
            *(float2*)&g_outT[(size_t)(r0 + 8) * COUT + c0] = v1;
        }
    }

    // ---- fused BN partials (deterministic)
    float* red_s  = (float*)sm;            // [8][64]
    float* red_ss = red_s + 8 * 64;        // [8][64]
    float sl[16], ssl[16];
    #pragma unroll
    for (int ni = 0; ni < 8; ni++) {
        #pragma unroll
        for (int j = 0; j < 2; j++) {
            float v0 = acc[0][ni][j],     v1 = acc[0][ni][2 + j];
            float v2 = acc[1][ni][j],     v3 = acc[1][ni][2 + j];
            sl [ni * 2 + j] = v0 + v1 + v2 + v3;
            ssl[ni * 2 + j] = v0 * v0 + v1 * v1 + v2 * v2 + v3 * v3;
        }
    }
    #pragma unroll
    for (int k = 0; k < 16; k++) {
        #pragma unroll
        for (int o = 4; o < 32; o <<= 1) {
            sl [k] += __shfl_down_sync(0xFFFFFFFFu, sl [k], o);
            ssl[k] += __shfl_down_sync(0xFFFFFFFFu, ssl[k], o);
        }
    }
    if (lane < 4) {
        #pragma unroll
        for (int ni = 0; ni < 8; ni++) {
            #pragma unroll
            for (int j = 0; j < 2; j++) {
                int cl = ni * 8 + lane * 2 + j;     // 0..63
                red_s [wid * 64 + cl] = sl [ni * 2 + j];
                red_ss[wid * 64 + cl] = ssl[ni * 2 + j];
            }
        }
    }
    __syncthreads();
    if (tid < 128) {
        int g   = tid >> 6;       // col group (warpColN/64)
        int col = tid & 63;
        float s  = red_s [(g + 0) * 64 + col] + red_s [(g + 2) * 64 + col]
                 + red_s [(g + 4) * 64 + col] + red_s [(g + 6) * 64 + col];
        float ss = red_ss[(g + 0) * 64 + col] + red_ss[(g + 2) * 64 + col]
                 + red_ss[(g + 4) * 64 + col] + red_ss[(g + 6) * 64 + col];
        int rt = tile >> 1;
        int ch = colBlk + g * 64 + col;
        g_part[rt * 512 + ch]       = s;
        g_part[rt * 512 + 256 + ch] = ss;
    }
}

// ---------------- 5) finalize BN scale/shift -----------------------------
__global__ void k_bn_final(const float* __restrict__ gamma,
                           const float* __restrict__ beta) {
    int t = threadIdx.x;
    float s = 0.f, ss = 0.f;
    for (int i = 0; i < 256; i++) {
        s  += g_part[i * 512 + t];
        ss += g_part[i * 512 + 256 + t];
    }
    const float invN = 1.f / 32768.f;
    float mean = s * invN;
    float var  = ss * invN - mean * mean;
    float inv  = rsqrtf(var + 1e-5f);
    float sc   = gamma[t] * inv;
    g_scale[t] = sc;
    g_shift[t] = beta[t] - mean * sc;
}

// ---------------- 6) affine + SiLU + transpose to NCHW -------------------
__global__ void k_epilogue(float* __restrict__ out) {
    __shared__ float tile[32][33];
    int tx = threadIdx.x, ty = threadIdx.y;
    int o0 = blockIdx.y * 32;
    int r0 = blockIdx.x * 32;
    int orq = o0 + tx;
    float sc = g_scale[orq], sh = g_shift[orq];
    #pragma unroll
    for (int j = 0; j < 4; j++) {
        int r = r0 + ty + j * 8;
        float v = g_outT[(size_t)r * COUT + orq] * sc + sh;
        v = v / (1.f + __expf(-v));
        tile[ty + j * 8][tx] = v;
    }
    __syncthreads();
    int rw = r0 + tx;
    int bb = rw >> 12;
    int hw = rw & 4095;
    #pragma unroll
    for (int j = 0; j < 4; j++) {
        int o = o0 + ty + j * 8;
        out[((size_t)(bb * COUT + o)) * HWSZ + hw] = tile[tx][ty + j * 8];
    }
}

// ---------------- launch ---------------------------------------------------
extern "C" void kernel_launch(void* const* d_in, const int* in_sizes, int n_in,
                              void* d_out, int out_size) {
    const float* x     = (const float*)d_in[0];
    const float* w_off = (const float*)d_in[1];
    const float* b_off = (const float*)d_in[2];
    const float* w_mod = (const float*)d_in[3];
    const float* b_mod = (const float*)d_in[4];
    const float* w_dc  = (const float*)d_in[5];
    const float* gamma = (const float*)d_in[6];
    const float* beta  = (const float*)d_in[7];
    float* out = (float*)d_out;

    cudaFuncSetAttribute(k_conv_tc,  cudaFuncAttributeMaxDynamicSharedMemorySize, CONV_SMEM);
    cudaFuncSetAttribute(k_gemm_f16, cudaFuncAttributeMaxDynamicSharedMemorySize, GEMM_SMEM);

    k_prep<<<dim3(HWSZ / 32, CIN / 32, 9), dim3(32, 8)>>>(x, w_dc, w_off, w_mod);

    k_conv_tc<<<256, 256, CONV_SMEM>>>(b_off, b_mod);

    k_sample<<<dim3(HWSZ / 8, KK9, BATCH), dim3(32, 8)>>>();

    k_gemm_f16<<<512, 256, GEMM_SMEM>>>();

    k_bn_final<<<1, 256>>>(gamma, beta);

    k_epilogue<<<dim3((BATCH * HWSZ) / 32, COUT / 32), dim3(32, 8)>>>(out);
}

// round 8
// speedup vs baseline: 4.6310x; 1.3228x over previous
#include <cuda_runtime.h>
#include <cuda_fp16.h>
#include <stdint.h>
#include <math.h>

// ---------------- problem constants ----------------
#define BATCH 8
#define CIN   128
#define COUT  256
#define HH    64
#define WW    64
#define HWSZ  4096
#define KK9   9
#define CK    1152          // CIN*KK9
#define NOC   27            // 18 offset + 9 modulation channels
#define ROWS  (BATCH*HWSZ)  // 32768

// ---------------- scratch ------------------------------------------------
__device__ float  g_xT [BATCH * HWSZ * CIN];        // x channels-last fp32 (sampling)
__device__ __half g_xTh[BATCH * HWSZ * CIN];        // x channels-last fp16 (conv GEMM)
__device__ float  g_off[BATCH * NOC * HWSZ];        // offsets + modulation(sigmoid)
__device__ __half g_Wch[32 * CK];                   // conv weights fp16, padded to 32 oc
__device__ __half g_Wh [COUT * CK];                 // deform weights fp16
__device__ __half g_V  [(size_t)ROWS * CK];         // sampled*mod fp16
__device__ float  g_outT[(size_t)ROWS * COUT];
__device__ float  g_part[512 * 512];
__device__ float  g_scale[COUT];
__device__ float  g_shift[COUT];

// ---------------- ptx helpers (plain sm_80+ PTX only) --------------------
__device__ __forceinline__ uint32_t smem_u32(const void* p) {
    uint32_t a;
    asm("{ .reg .u64 t; cvta.to.shared.u64 t, %1; cvt.u32.u64 %0, t; }"
        : "=r"(a) : "l"(p));
    return a;
}
__device__ __forceinline__ void cp16(uint32_t dst, const void* src) {
    asm volatile("cp.async.cg.shared.global [%0], [%1], 16;" :: "r"(dst), "l"(src));
}
__device__ __forceinline__ void cp16z(uint32_t dst, const void* src, uint32_t sz) {
    asm volatile("cp.async.cg.shared.global [%0], [%1], 16, %2;"
                 :: "r"(dst), "l"(src), "r"(sz));
}
__device__ __forceinline__ void cp_commit() {
    asm volatile("cp.async.commit_group;" ::: "memory");
}
template <int N>
__device__ __forceinline__ void cp_wait() {
    asm volatile("cp.async.wait_group %0;" :: "n"(N) : "memory");
}
__device__ __forceinline__ void ldm_x4(uint32_t* r, uint32_t addr) {
    asm volatile("ldmatrix.sync.aligned.m8n8.x4.shared.b16 {%0,%1,%2,%3}, [%4];"
        : "=r"(r[0]), "=r"(r[1]), "=r"(r[2]), "=r"(r[3]) : "r"(addr));
}
__device__ __forceinline__ void mma_f16(float* d, const uint32_t* a,
                                        uint32_t b0, uint32_t b1) {
    asm volatile(
        "mma.sync.aligned.m16n8k16.row.col.f32.f16.f16.f32 "
        "{%0,%1,%2,%3}, {%4,%5,%6,%7}, {%8,%9}, {%0,%1,%2,%3};"
        : "+f"(d[0]), "+f"(d[1]), "+f"(d[2]), "+f"(d[3])
        : "r"(a[0]), "r"(a[1]), "r"(a[2]), "r"(a[3]), "r"(b0), "r"(b1));
}

// ---------------- 1) prep: transpose x (fp32+fp16) + weights -------------
__global__ void k_prep(const float* __restrict__ x,
                       const float* __restrict__ w_dc,
                       const float* __restrict__ w_off,
                       const float* __restrict__ w_mod) {
    if (blockIdx.z < 8) {
        __shared__ float tile[32][33];
        int b   = blockIdx.z;
        int hw0 = blockIdx.x * 32;
        int c0  = blockIdx.y * 32;
        int tx = threadIdx.x, ty = threadIdx.y;
        #pragma unroll
        for (int j = 0; j < 4; j++) {
            int c = c0 + ty + j * 8;
            tile[ty + j * 8][tx] = x[((b * CIN) + c) * HWSZ + hw0 + tx];
        }
        __syncthreads();
        #pragma unroll
        for (int j = 0; j < 4; j++) {
            int hw = hw0 + ty + j * 8;
            float v = tile[tx][ty + j * 8];
            size_t o = ((size_t)(b * HWSZ) + hw) * CIN + c0 + tx;
            g_xT[o]  = v;
            g_xTh[o] = __float2half(v);
        }
    } else {
        const int NWP  = COUT * CK;         // 294912
        const int NWC2 = 32 * CK;           // 36864
        int t = threadIdx.y * 32 + threadIdx.x;
        int gidx = (blockIdx.y * 128 + blockIdx.x) * 256 + t;
        for (int idx = gidx; idx < NWP + NWC2; idx += 512 * 256) {
            if (idx < NWP) {
                int o  = idx / CK;
                int r  = idx - o * CK;
                int kk = r >> 7;
                int c  = r & 127;
                g_Wh[idx] = __float2half(w_dc[(o * CIN + c) * KK9 + kk]);
            } else {
                int j  = idx - NWP;
                int oc = j / CK;
                int r  = j - oc * CK;
                int kk = r >> 7;
                int c  = r & 127;
                float v = 0.f;
                if (oc < 18)      v = w_off[(oc * CIN + c) * KK9 + kk];
                else if (oc < 27) v = w_mod[((oc - 18) * CIN + c) * KK9 + kk];
                g_Wch[j] = __float2half(v);
            }
        }
    }
}

// ---------------- 2) conv offsets/mod via tensor cores --------------------
#define RCWB   80
#define A2_B   (128 * RCWB)                 // 10240
#define B2_B   (32 * RCWB)                  // 2560
#define CSTG   (A2_B + B2_B)                // 12800
#define CONV_SMEM (2 * CSTG)                // 25600

__device__ __forceinline__ void conv_load_stage(uint32_t buf, int cn,
                                                int rowBlk, int tid) {
    int kk  = cn >> 2;
    int c0k = (cn & 3) * 32;
    int dy = kk / 3 - 1;
    int dx = kk % 3 - 1;
    {
        int row  = tid >> 1;
        int half = tid & 1;
        int pix = rowBlk * 128 + row;
        int b = pix >> 12;
        int h = (pix >> 6) & 63;
        int w = pix & 63;
        int h2 = h + dy, w2 = w + dx;
        bool valid = ((unsigned)h2 < 64u) & ((unsigned)w2 < 64u);
        size_t srcoff = valid
            ? (((size_t)b * HWSZ + h2 * 64 + w2) * CIN + c0k) * 2 : 0;
        uint32_t sz = valid ? 16u : 0u;
        const char* src = (const char*)g_xTh + srcoff + half * 32;
        uint32_t dst = buf + row * RCWB + half * 32;
        cp16z(dst,      src,      sz);
        cp16z(dst + 16, src + 16, sz);
    }
    if (tid < 128) {
        int row = tid >> 2;
        int q   = tid & 3;
        const char* src = (const char*)g_Wch + ((size_t)row * CK + cn * 32) * 2 + q * 16;
        cp16(buf + A2_B + row * RCWB + q * 16, src);
    }
}

__global__ void __launch_bounds__(256) k_conv_tc(const float* __restrict__ b_off,
                                                 const float* __restrict__ b_mod) {
    extern __shared__ __align__(128) char sm[];
    const uint32_t base = smem_u32(sm);
    const int tid  = threadIdx.x;
    const int lane = tid & 31;
    const int wid  = tid >> 5;
    const int rowBlk = blockIdx.x;

    const int lrow  = lane & 15;
    const int lhalf = (lane >> 4) * 16;

    float acc[4][4];
    #pragma unroll
    for (int i = 0; i < 4; i++)
        #pragma unroll
        for (int q = 0; q < 4; q++) acc[i][q] = 0.f;

    conv_load_stage(base, 0, rowBlk, tid);
    cp_commit();

    for (int cn = 0; cn < 36; cn++) {
        int s = cn & 1;
        if (cn + 1 < 36) {
            conv_load_stage(base + ((cn + 1) & 1) * CSTG, cn + 1, rowBlk, tid);
            cp_commit();
            cp_wait<1>();
        } else {
            cp_wait<0>();
        }
        __syncthreads();

        uint32_t bufA = base + s * CSTG;
        uint32_t bufB = bufA + A2_B;

        #pragma unroll
        for (int ks = 0; ks < 2; ks++) {
            uint32_t a[4];
            ldm_x4(a, bufA + (uint32_t)(wid * 16 + lrow) * RCWB + ks * 32 + lhalf);
            uint32_t bfr[2][4];
            #pragma unroll
            for (int pr = 0; pr < 2; pr++)
                ldm_x4(bfr[pr], bufB + (uint32_t)(pr * 16 + lrow) * RCWB + ks * 32 + lhalf);
            #pragma unroll
            for (int pr = 0; pr < 2; pr++) {
                mma_f16(acc[2 * pr],     a, bfr[pr][0], bfr[pr][2]);
                mma_f16(acc[2 * pr + 1], a, bfr[pr][1], bfr[pr][3]);
            }
        }
        __syncthreads();
    }

    int pix0 = rowBlk * 128 + wid * 16 + (lane >> 2);
    int b = pix0 >> 12;
    #pragma unroll
    for (int ni = 0; ni < 4; ni++) {
        #pragma unroll
        for (int q = 0; q < 4; q++) {
            int oc = ni * 8 + (lane & 3) * 2 + (q & 1);
            if (oc >= NOC) continue;
            int pix = pix0 + (q >> 1) * 8;
            float bias = (oc < 18) ? b_off[oc] : b_mod[oc - 18];
            float v = acc[ni][q] + bias;
            if (oc >= 18) v = 1.f / (1.f + __expf(-v));
            g_off[((size_t)b * NOC + oc) * HWSZ + (pix & 4095)] = v;
        }
    }
}

// ---------------- 3) bilinear sampling -> V (fp16) ------------------------
__global__ void k_sample() {
    int tx  = threadIdx.x;
    int pos = blockIdx.x * 8 + threadIdx.y;
    int kk  = blockIdx.y;
    int b   = blockIdx.z;
    int h = pos >> 6, w = pos & 63;

    const float* offb = g_off + (b * NOC) * HWSZ;
    float dy = offb[(2 * kk)     * HWSZ + pos];
    float dx = offb[(2 * kk + 1) * HWSZ + pos];
    float m  = offb[(18 + kk)    * HWSZ + pos];

    float py = dy + (float)(h - 1 + kk / 3);
    float px = dx + (float)(w - 1 + kk % 3);
    float fy = floorf(py), fx = floorf(px);
    int y0 = (int)fy, x0 = (int)fx;
    float wy1 = py - fy, wx1 = px - fx;
    float wy0 = 1.f - wy1, wx0 = 1.f - wx1;

    const float4* xb = (const float4*)g_xT + (size_t)(b * HWSZ) * 32;
    float4 acc = make_float4(0.f, 0.f, 0.f, 0.f);

    #pragma unroll
    for (int cn = 0; cn < 4; cn++) {
        int yi = y0 + (cn >> 1);
        int xi = x0 + (cn & 1);
        float wt = ((cn >> 1) ? wy1 : wy0) * ((cn & 1) ? wx1 : wx0);
        bool valid = (yi >= 0) & (yi < HH) & (xi >= 0) & (xi < WW);
        float wv = valid ? wt : 0.f;
        int yc = min(max(yi, 0), HH - 1);
        int xc = min(max(xi, 0), WW - 1);
        float4 v = xb[(yc * WW + xc) * 32 + tx];
        acc.x += wv * v.x; acc.y += wv * v.y;
        acc.z += wv * v.z; acc.w += wv * v.w;
    }
    acc.x *= m; acc.y *= m; acc.z *= m; acc.w *= m;

    __half2 p0 = __floats2half2_rn(acc.x, acc.y);
    __half2 p1 = __floats2half2_rn(acc.z, acc.w);
    uint2 u;
    u.x = *reinterpret_cast<uint32_t*>(&p0);
    u.y = *reinterpret_cast<uint32_t*>(&p1);

    size_t e = ((size_t)(b * HWSZ) + pos) * CK + kk * 128 + tx * 4;
    *reinterpret_cast<uint2*>((char*)g_V + e * 2) = u;
}

// ---------------- 4) fp16 GEMM, 64x128 tiles, 4 CTAs/SM + fused BN --------
#define ROWB       80
#define A_BYTES    (64 * ROWB)         // 5120
#define B_BYTES    (128 * ROWB)        // 10240
#define STAGE_B    (A_BYTES + B_BYTES) // 15360
#define GEMM_SMEM  (2 * STAGE_B)       // 30720

__device__ __forceinline__ void gemm_load_stage(uint32_t buf, int c,
                                                int rowBlk, int colBlk, int tid) {
    // A: 64 rows x 64B (256 cp16)
    {
        int row = tid >> 2;
        int cc  = tid & 3;
        const char* src = (const char*)g_V
            + ((size_t)(rowBlk + row) * CK + c * 32) * 2 + cc * 16;
        cp16(buf + row * ROWB + cc * 16, src);
    }
    // B: 128 rows x 64B (512 cp16)
    #pragma unroll
    for (int j = 0; j < 2; j++) {
        int rem = (j << 8) + tid;
        int row = rem >> 2;
        int cc  = rem & 3;
        const char* src = (const char*)g_Wh
            + ((size_t)(colBlk + row) * CK + c * 32) * 2 + cc * 16;
        cp16(buf + A_BYTES + row * ROWB + cc * 16, src);
    }
}

__global__ void __launch_bounds__(256, 4) k_gemm_f16() {
    extern __shared__ __align__(128) char sm[];
    const uint32_t base = smem_u32(sm);
    const int tid  = threadIdx.x;
    const int lane = tid & 31;
    const int wid  = tid >> 5;
    const int rowBlk = blockIdx.x * 64;
    const int colBlk = blockIdx.y * 128;

    const int warpRow = (wid & 3) * 16;     // 4 m-warps
    const int warpCol = (wid >> 2) * 64;    // 2 n-warp groups
    const int lrow  = lane & 15;
    const int lhalf = (lane >> 4) * 16;

    float acc[8][4];
    #pragma unroll
    for (int j = 0; j < 8; j++)
        #pragma unroll
        for (int q = 0; q < 4; q++) acc[j][q] = 0.f;

    gemm_load_stage(base, 0, rowBlk, colBlk, tid);
    cp_commit();

    for (int c = 0; c < 36; c++) {
        int s = c & 1;
        if (c + 1 < 36) {
            gemm_load_stage(base + ((c + 1) & 1) * STAGE_B, c + 1, rowBlk, colBlk, tid);
            cp_commit();
            cp_wait<1>();
        } else {
            cp_wait<0>();
        }
        __syncthreads();

        uint32_t bufA = base + s * STAGE_B;
        uint32_t bufB = bufA + A_BYTES;

        #pragma unroll
        for (int ks = 0; ks < 2; ks++) {
            uint32_t a[4];
            ldm_x4(a, bufA + (uint32_t)(warpRow + lrow) * ROWB + ks * 32 + lhalf);
            #pragma unroll
            for (int pr = 0; pr < 4; pr++) {
                uint32_t bfr[4];
                ldm_x4(bfr, bufB + (uint32_t)(warpCol + pr * 16 + lrow) * ROWB
                            + ks * 32 + lhalf);
                mma_f16(acc[2 * pr],     a, bfr[0], bfr[2]);
                mma_f16(acc[2 * pr + 1], a, bfr[1], bfr[3]);
            }
        }
        __syncthreads();
    }

    // ---- store C (warp m16 x n64)
    {
        int r0 = rowBlk + warpRow + lane / 4;
        #pragma unroll
        for (int ni = 0; ni < 8; ni++) {
            int c0 = colBlk + warpCol + ni * 8 + (lane & 3) * 2;
            float2 v0 = make_float2(acc[ni][0], acc[ni][1]);
            float2 v1 = make_float2(acc[ni][2], acc[ni][3]);
            *(float2*)&g_outT[(size_t)r0 * COUT + c0]       = v0;
            *(float2*)&g_outT[(size_t)(r0 + 8) * COUT + c0] = v1;
        }
    }

    // ---- fused BN partials (deterministic)
    float* red_s  = (float*)sm;            // [8][64]
    float* red_ss = red_s + 8 * 64;        // [8][64]
    float sl[16], ssl[16];
    #pragma unroll
    for (int ni = 0; ni < 8; ni++) {
        #pragma unroll
        for (int j = 0; j < 2; j++) {
            float v0 = acc[ni][j], v1 = acc[ni][2 + j];
            sl [ni * 2 + j] = v0 + v1;
            ssl[ni * 2 + j] = v0 * v0 + v1 * v1;
        }
    }
    #pragma unroll
    for (int k = 0; k < 16; k++) {
        #pragma unroll
        for (int o = 4; o < 32; o <<= 1) {
            sl [k] += __shfl_down_sync(0xFFFFFFFFu, sl [k], o);
            ssl[k] += __shfl_down_sync(0xFFFFFFFFu, ssl[k], o);
        }
    }
    if (lane < 4) {
        #pragma unroll
        for (int ni = 0; ni < 8; ni++) {
            #pragma unroll
            for (int j = 0; j < 2; j++) {
                int cl = ni * 8 + (lane & 3) * 2 + j;   // 0..63
                red_s [wid * 64 + cl] = sl [ni * 2 + j];
                red_ss[wid * 64 + cl] = ssl[ni * 2 + j];
            }
        }
    }
    __syncthreads();
    if (tid < 128) {
        int g   = tid >> 6;       // n-warp group
        int col = tid & 63;
        float s  = red_s [(g * 4 + 0) * 64 + col] + red_s [(g * 4 + 1) * 64 + col]
                 + red_s [(g * 4 + 2) * 64 + col] + red_s [(g * 4 + 3) * 64 + col];
        float ss = red_ss[(g * 4 + 0) * 64 + col] + red_ss[(g * 4 + 1) * 64 + col]
                 + red_ss[(g * 4 + 2) * 64 + col] + red_ss[(g * 4 + 3) * 64 + col];
        int ch = colBlk + g * 64 + col;
        g_part[blockIdx.x * 512 + ch]       = s;
        g_part[blockIdx.x * 512 + 256 + ch] = ss;
    }
}

// ---------------- 5) finalize BN scale/shift -----------------------------
__global__ void k_bn_final(const float* __restrict__ gamma,
                           const float* __restrict__ beta) {
    int t = threadIdx.x;
    float s = 0.f, ss = 0.f;
    for (int i = 0; i < 512; i++) {
        s  += g_part[i * 512 + t];
        ss += g_part[i * 512 + 256 + t];
    }
    const float invN = 1.f / 32768.f;
    float mean = s * invN;
    float var  = ss * invN - mean * mean;
    float inv  = rsqrtf(var + 1e-5f);
    float sc   = gamma[t] * inv;
    g_scale[t] = sc;
    g_shift[t] = beta[t] - mean * sc;
}

// ---------------- 6) affine + SiLU + transpose to NCHW -------------------
__global__ void k_epilogue(float* __restrict__ out) {
    __shared__ float tile[32][33];
    int tx = threadIdx.x, ty = threadIdx.y;
    int o0 = blockIdx.y * 32;
    int r0 = blockIdx.x * 32;
    int orq = o0 + tx;
    float sc = g_scale[orq], sh = g_shift[orq];
    #pragma unroll
    for (int j = 0; j < 4; j++) {
        int r = r0 + ty + j * 8;
        float v = g_outT[(size_t)r * COUT + orq] * sc + sh;
        v = v / (1.f + __expf(-v));
        tile[ty + j * 8][tx] = v;
    }
    __syncthreads();
    int rw = r0 + tx;
    int bb = rw >> 12;
    int hw = rw & 4095;
    #pragma unroll
    for (int j = 0; j < 4; j++) {
        int o = o0 + ty + j * 8;
        out[((size_t)(bb * COUT + o)) * HWSZ + hw] = tile[tx][ty + j * 8];
    }
}

// ---------------- launch ---------------------------------------------------
extern "C" void kernel_launch(void* const* d_in, const int* in_sizes, int n_in,
                              void* d_out, int out_size) {
    const float* x     = (const float*)d_in[0];
    const float* w_off = (const float*)d_in[1];
    const float* b_off = (const float*)d_in[2];
    const float* w_mod = (const float*)d_in[3];
    const float* b_mod = (const float*)d_in[4];
    const float* w_dc  = (const float*)d_in[5];
    const float* gamma = (const float*)d_in[6];
    const float* beta  = (const float*)d_in[7];
    float* out = (float*)d_out;

    cudaFuncSetAttribute(k_conv_tc,  cudaFuncAttributeMaxDynamicSharedMemorySize, CONV_SMEM);
    cudaFuncSetAttribute(k_gemm_f16, cudaFuncAttributeMaxDynamicSharedMemorySize, GEMM_SMEM);

    k_prep<<<dim3(HWSZ / 32, CIN / 32, 9), dim3(32, 8)>>>(x, w_dc, w_off, w_mod);

    k_conv_tc<<<256, 256, CONV_SMEM>>>(b_off, b_mod);

    k_sample<<<dim3(HWSZ / 8, KK9, BATCH), dim3(32, 8)>>>();

    k_gemm_f16<<<dim3(ROWS / 64, 2), 256, GEMM_SMEM>>>();

    k_bn_final<<<1, 256>>>(gamma, beta);

    k_epilogue<<<dim3((BATCH * HWSZ) / 32, COUT / 32), dim3(32, 8)>>>(out);
}

// round 9
// speedup vs baseline: 4.7488x; 1.0254x over previous
#include <cuda_runtime.h>
#include <cuda_fp16.h>
#include <stdint.h>
#include <math.h>

// ---------------- problem constants ----------------
#define BATCH 8
#define CIN   128
#define COUT  256
#define HH    64
#define WW    64
#define HWSZ  4096
#define KK9   9
#define CK    1152          // CIN*KK9
#define NOC   27            // 18 offset + 9 modulation channels
#define ROWS  (BATCH*HWSZ)  // 32768

// ---------------- scratch ------------------------------------------------
__device__ float  g_xT [BATCH * HWSZ * CIN];        // x channels-last fp32 (sampling)
__device__ __half g_xTh[BATCH * HWSZ * CIN];        // x channels-last fp16 (conv GEMM)
__device__ float  g_off[BATCH * NOC * HWSZ];        // offsets + modulation(sigmoid)
__device__ __half g_Wch[32 * CK];                   // conv weights fp16, padded to 32 oc
__device__ __half g_Wh [COUT * CK];                 // deform weights fp16
__device__ __half g_V  [(size_t)ROWS * CK];         // sampled*mod fp16
__device__ float  g_outT[(size_t)ROWS * COUT];
__device__ float  g_part[512 * 512];
__device__ float  g_scale[COUT];
__device__ float  g_shift[COUT];

// ---------------- ptx helpers (plain sm_80+ PTX only) --------------------
__device__ __forceinline__ uint32_t smem_u32(const void* p) {
    uint32_t a;
    asm("{ .reg .u64 t; cvta.to.shared.u64 t, %1; cvt.u32.u64 %0, t; }"
        : "=r"(a) : "l"(p));
    return a;
}
__device__ __forceinline__ void cp16(uint32_t dst, const void* src) {
    asm volatile("cp.async.cg.shared.global [%0], [%1], 16;" :: "r"(dst), "l"(src));
}
__device__ __forceinline__ void cp16z(uint32_t dst, const void* src, uint32_t sz) {
    asm volatile("cp.async.cg.shared.global [%0], [%1], 16, %2;"
                 :: "r"(dst), "l"(src), "r"(sz));
}
__device__ __forceinline__ void cp_commit() {
    asm volatile("cp.async.commit_group;" ::: "memory");
}
template <int N>
__device__ __forceinline__ void cp_wait() {
    asm volatile("cp.async.wait_group %0;" :: "n"(N) : "memory");
}
__device__ __forceinline__ void ldm_x4(uint32_t* r, uint32_t addr) {
    asm volatile("ldmatrix.sync.aligned.m8n8.x4.shared.b16 {%0,%1,%2,%3}, [%4];"
        : "=r"(r[0]), "=r"(r[1]), "=r"(r[2]), "=r"(r[3]) : "r"(addr));
}
__device__ __forceinline__ void mma_f16(float* d, const uint32_t* a,
                                        uint32_t b0, uint32_t b1) {
    asm volatile(
        "mma.sync.aligned.m16n8k16.row.col.f32.f16.f16.f32 "
        "{%0,%1,%2,%3}, {%4,%5,%6,%7}, {%8,%9}, {%0,%1,%2,%3};"
        : "+f"(d[0]), "+f"(d[1]), "+f"(d[2]), "+f"(d[3])
        : "r"(a[0]), "r"(a[1]), "r"(a[2]), "r"(a[3]), "r"(b0), "r"(b1));
}

// ---------------- 1) prep: transpose x (fp32+fp16) + weights -------------
__global__ void k_prep(const float* __restrict__ x,
                       const float* __restrict__ w_dc,
                       const float* __restrict__ w_off,
                       const float* __restrict__ w_mod) {
    if (blockIdx.z < 8) {
        __shared__ float tile[32][33];
        int b   = blockIdx.z;
        int hw0 = blockIdx.x * 32;
        int c0  = blockIdx.y * 32;
        int tx = threadIdx.x, ty = threadIdx.y;
        #pragma unroll
        for (int j = 0; j < 4; j++) {
            int c = c0 + ty + j * 8;
            tile[ty + j * 8][tx] = x[((b * CIN) + c) * HWSZ + hw0 + tx];
        }
        __syncthreads();
        #pragma unroll
        for (int j = 0; j < 4; j++) {
            int hw = hw0 + ty + j * 8;
            float v = tile[tx][ty + j * 8];
            size_t o = ((size_t)(b * HWSZ) + hw) * CIN + c0 + tx;
            g_xT[o]  = v;
            g_xTh[o] = __float2half(v);
        }
    } else {
        const int NWP  = COUT * CK;         // 294912
        const int NWC2 = 32 * CK;           // 36864
        int t = threadIdx.y * 32 + threadIdx.x;
        int gidx = (blockIdx.y * 128 + blockIdx.x) * 256 + t;
        for (int idx = gidx; idx < NWP + NWC2; idx += 512 * 256) {
            if (idx < NWP) {
                int o  = idx / CK;
                int r  = idx - o * CK;
                int kk = r >> 7;
                int c  = r & 127;
                g_Wh[idx] = __float2half(w_dc[(o * CIN + c) * KK9 + kk]);
            } else {
                int j  = idx - NWP;
                int oc = j / CK;
                int r  = j - oc * CK;
                int kk = r >> 7;
                int c  = r & 127;
                float v = 0.f;
                if (oc < 18)      v = w_off[(oc * CIN + c) * KK9 + kk];
                else if (oc < 27) v = w_mod[((oc - 18) * CIN + c) * KK9 + kk];
                g_Wch[j] = __float2half(v);
            }
        }
    }
}

// ---------------- 2) conv offsets/mod via tensor cores --------------------
#define RCWB   80
#define A2_B   (128 * RCWB)                 // 10240
#define B2_B   (32 * RCWB)                  // 2560
#define CSTG   (A2_B + B2_B)                // 12800
#define CONV_SMEM (2 * CSTG)                // 25600

__device__ __forceinline__ void conv_load_stage(uint32_t buf, int cn,
                                                int rowBlk, int tid) {
    int kk  = cn >> 2;
    int c0k = (cn & 3) * 32;
    int dy = kk / 3 - 1;
    int dx = kk % 3 - 1;
    {
        int row  = tid >> 1;
        int half = tid & 1;
        int pix = rowBlk * 128 + row;
        int b = pix >> 12;
        int h = (pix >> 6) & 63;
        int w = pix & 63;
        int h2 = h + dy, w2 = w + dx;
        bool valid = ((unsigned)h2 < 64u) & ((unsigned)w2 < 64u);
        size_t srcoff = valid
            ? (((size_t)b * HWSZ + h2 * 64 + w2) * CIN + c0k) * 2 : 0;
        uint32_t sz = valid ? 16u : 0u;
        const char* src = (const char*)g_xTh + srcoff + half * 32;
        uint32_t dst = buf + row * RCWB + half * 32;
        cp16z(dst,      src,      sz);
        cp16z(dst + 16, src + 16, sz);
    }
    if (tid < 128) {
        int row = tid >> 2;
        int q   = tid & 3;
        const char* src = (const char*)g_Wch + ((size_t)row * CK + cn * 32) * 2 + q * 16;
        cp16(buf + A2_B + row * RCWB + q * 16, src);
    }
}

__global__ void __launch_bounds__(256) k_conv_tc(const float* __restrict__ b_off,
                                                 const float* __restrict__ b_mod) {
    extern __shared__ __align__(128) char sm[];
    const uint32_t base = smem_u32(sm);
    const int tid  = threadIdx.x;
    const int lane = tid & 31;
    const int wid  = tid >> 5;
    const int rowBlk = blockIdx.x;

    const int lrow  = lane & 15;
    const int lhalf = (lane >> 4) * 16;

    float acc[4][4];
    #pragma unroll
    for (int i = 0; i < 4; i++)
        #pragma unroll
        for (int q = 0; q < 4; q++) acc[i][q] = 0.f;

    conv_load_stage(base, 0, rowBlk, tid);
    cp_commit();

    for (int cn = 0; cn < 36; cn++) {
        int s = cn & 1;
        if (cn + 1 < 36) {
            conv_load_stage(base + ((cn + 1) & 1) * CSTG, cn + 1, rowBlk, tid);
            cp_commit();
            cp_wait<1>();
        } else {
            cp_wait<0>();
        }
        __syncthreads();

        uint32_t bufA = base + s * CSTG;
        uint32_t bufB = bufA + A2_B;

        #pragma unroll
        for (int ks = 0; ks < 2; ks++) {
            uint32_t a[4];
            ldm_x4(a, bufA + (uint32_t)(wid * 16 + lrow) * RCWB + ks * 32 + lhalf);
            uint32_t bfr[2][4];
            #pragma unroll
            for (int pr = 0; pr < 2; pr++)
                ldm_x4(bfr[pr], bufB + (uint32_t)(pr * 16 + lrow) * RCWB + ks * 32 + lhalf);
            #pragma unroll
            for (int pr = 0; pr < 2; pr++) {
                mma_f16(acc[2 * pr],     a, bfr[pr][0], bfr[pr][2]);
                mma_f16(acc[2 * pr + 1], a, bfr[pr][1], bfr[pr][3]);
            }
        }
        __syncthreads();
    }

    int pix0 = rowBlk * 128 + wid * 16 + (lane >> 2);
    int b = pix0 >> 12;
    #pragma unroll
    for (int ni = 0; ni < 4; ni++) {
        #pragma unroll
        for (int q = 0; q < 4; q++) {
            int oc = ni * 8 + (lane & 3) * 2 + (q & 1);
            if (oc >= NOC) continue;
            int pix = pix0 + (q >> 1) * 8;
            float bias = (oc < 18) ? b_off[oc] : b_mod[oc - 18];
            float v = acc[ni][q] + bias;
            if (oc >= 18) v = 1.f / (1.f + __expf(-v));
            g_off[((size_t)b * NOC + oc) * HWSZ + (pix & 4095)] = v;
        }
    }
}

// ---------------- 3) bilinear sampling -> V (fp16) ------------------------
__global__ void k_sample() {
    int tx  = threadIdx.x;
    int pos = blockIdx.x * 8 + threadIdx.y;
    int kk  = blockIdx.y;
    int b   = blockIdx.z;
    int h = pos >> 6, w = pos & 63;

    const float* offb = g_off + (b * NOC) * HWSZ;
    float dy = offb[(2 * kk)     * HWSZ + pos];
    float dx = offb[(2 * kk + 1) * HWSZ + pos];
    float m  = offb[(18 + kk)    * HWSZ + pos];

    float py = dy + (float)(h - 1 + kk / 3);
    float px = dx + (float)(w - 1 + kk % 3);
    float fy = floorf(py), fx = floorf(px);
    int y0 = (int)fy, x0 = (int)fx;
    float wy1 = py - fy, wx1 = px - fx;
    float wy0 = 1.f - wy1, wx0 = 1.f - wx1;

    const float4* xb = (const float4*)g_xT + (size_t)(b * HWSZ) * 32;
    float4 acc = make_float4(0.f, 0.f, 0.f, 0.f);

    #pragma unroll
    for (int cn = 0; cn < 4; cn++) {
        int yi = y0 + (cn >> 1);
        int xi = x0 + (cn & 1);
        float wt = ((cn >> 1) ? wy1 : wy0) * ((cn & 1) ? wx1 : wx0);
        bool valid = (yi >= 0) & (yi < HH) & (xi >= 0) & (xi < WW);
        float wv = valid ? wt : 0.f;
        int yc = min(max(yi, 0), HH - 1);
        int xc = min(max(xi, 0), WW - 1);
        float4 v = xb[(yc * WW + xc) * 32 + tx];
        acc.x += wv * v.x; acc.y += wv * v.y;
        acc.z += wv * v.z; acc.w += wv * v.w;
    }
    acc.x *= m; acc.y *= m; acc.z *= m; acc.w *= m;

    __half2 p0 = __floats2half2_rn(acc.x, acc.y);
    __half2 p1 = __floats2half2_rn(acc.z, acc.w);
    uint2 u;
    u.x = *reinterpret_cast<uint32_t*>(&p0);
    u.y = *reinterpret_cast<uint32_t*>(&p1);

    size_t e = ((size_t)(b * HWSZ) + pos) * CK + kk * 128 + tx * 4;
    *reinterpret_cast<uint2*>((char*)g_V + e * 2) = u;
}

// ---------------- 4) fp16 GEMM, 64x128 tiles, 3-stage ring, B pipelined ---
#define ROWB       80
#define A_BYTES    (64 * ROWB)         // 5120
#define B_BYTES    (128 * ROWB)        // 10240
#define STAGE_B    (A_BYTES + B_BYTES) // 15360
#define NSTG       3
#define GEMM_SMEM  (NSTG * STAGE_B)    // 46080

__device__ __forceinline__ void gemm_load_stage(uint32_t buf, int c,
                                                int rowBlk, int colBlk, int tid) {
    // A: 64 rows x 64B (256 cp16)
    {
        int row = tid >> 2;
        int cc  = tid & 3;
        const char* src = (const char*)g_V
            + ((size_t)(rowBlk + row) * CK + c * 32) * 2 + cc * 16;
        cp16(buf + row * ROWB + cc * 16, src);
    }
    // B: 128 rows x 64B (512 cp16)
    #pragma unroll
    for (int j = 0; j < 2; j++) {
        int rem = (j << 8) + tid;
        int row = rem >> 2;
        int cc  = rem & 3;
        const char* src = (const char*)g_Wh
            + ((size_t)(colBlk + row) * CK + c * 32) * 2 + cc * 16;
        cp16(buf + A_BYTES + row * ROWB + cc * 16, src);
    }
}

__global__ void __launch_bounds__(256, 4) k_gemm_f16() {
    extern __shared__ __align__(128) char sm[];
    const uint32_t base = smem_u32(sm);
    const int tid  = threadIdx.x;
    const int lane = tid & 31;
    const int wid  = tid >> 5;
    const int rowBlk = blockIdx.x * 64;
    const int colBlk = blockIdx.y * 128;

    const int warpRow = (wid & 3) * 16;     // 4 m-warps
    const int warpCol = (wid >> 2) * 64;    // 2 n-warp groups
    const int lrow  = lane & 15;
    const int lhalf = (lane >> 4) * 16;

    float acc[8][4];
    #pragma unroll
    for (int j = 0; j < 8; j++)
        #pragma unroll
        for (int q = 0; q < 4; q++) acc[j][q] = 0.f;

    gemm_load_stage(base, 0, rowBlk, colBlk, tid);
    cp_commit();
    gemm_load_stage(base + STAGE_B, 1, rowBlk, colBlk, tid);
    cp_commit();

    int st = 0;
    for (int c = 0; c < 36; c++) {
        if (c + 1 < 36) cp_wait<1>(); else cp_wait<0>();
        __syncthreads();

        if (c + 2 < 36) {
            int nst = st + 2; if (nst >= NSTG) nst -= NSTG;
            gemm_load_stage(base + nst * STAGE_B, c + 2, rowBlk, colBlk, tid);
            cp_commit();
        }

        uint32_t bufA = base + st * STAGE_B;
        uint32_t bufB = bufA + A_BYTES;
        uint32_t arow = bufA + (uint32_t)(warpRow + lrow) * ROWB + lhalf;

        uint32_t a0[4], a1[4];
        ldm_x4(a0, arow);
        ldm_x4(a1, arow + 32);

        // software-pipelined B: load next fragment before using current
        uint32_t bcur[4], bnxt[4];
        ldm_x4(bcur, bufB + (uint32_t)(warpCol + lrow) * ROWB + lhalf);
        #pragma unroll
        for (int ks = 0; ks < 2; ks++) {
            const uint32_t* a = ks ? a1 : a0;
            #pragma unroll
            for (int pr = 0; pr < 4; pr++) {
                if (!(ks == 1 && pr == 3)) {
                    int nks = (pr < 3) ? ks : 1;
                    int npr = (pr < 3) ? pr + 1 : 0;
                    ldm_x4(bnxt, bufB + (uint32_t)(warpCol + npr * 16 + lrow) * ROWB
                                 + nks * 32 + lhalf);
                }
                mma_f16(acc[2 * pr],     a, bcur[0], bcur[2]);
                mma_f16(acc[2 * pr + 1], a, bcur[1], bcur[3]);
                #pragma unroll
                for (int q = 0; q < 4; q++) bcur[q] = bnxt[q];
            }
        }

        st++; if (st >= NSTG) st = 0;
    }
    __syncthreads();

    // ---- store C (warp m16 x n64)
    {
        int r0 = rowBlk + warpRow + lane / 4;
        #pragma unroll
        for (int ni = 0; ni < 8; ni++) {
            int c0 = colBlk + warpCol + ni * 8 + (lane & 3) * 2;
            float2 v0 = make_float2(acc[ni][0], acc[ni][1]);
            float2 v1 = make_float2(acc[ni][2], acc[ni][3]);
            *(float2*)&g_outT[(size_t)r0 * COUT + c0]       = v0;
            *(float2*)&g_outT[(size_t)(r0 + 8) * COUT + c0] = v1;
        }
    }

    // ---- fused BN partials (deterministic)
    float* red_s  = (float*)sm;            // [8][64]
    float* red_ss = red_s + 8 * 64;        // [8][64]
    float sl[16], ssl[16];
    #pragma unroll
    for (int ni = 0; ni < 8; ni++) {
        #pragma unroll
        for (int j = 0; j < 2; j++) {
            float v0 = acc[ni][j], v1 = acc[ni][2 + j];
            sl [ni * 2 + j] = v0 + v1;
            ssl[ni * 2 + j] = v0 * v0 + v1 * v1;
        }
    }
    #pragma unroll
    for (int k = 0; k < 16; k++) {
        #pragma unroll
        for (int o = 4; o < 32; o <<= 1) {
            sl [k] += __shfl_down_sync(0xFFFFFFFFu, sl [k], o);
            ssl[k] += __shfl_down_sync(0xFFFFFFFFu, ssl[k], o);
        }
    }
    if (lane < 4) {
        #pragma unroll
        for (int ni = 0; ni < 8; ni++) {
            #pragma unroll
            for (int j = 0; j < 2; j++) {
                int cl = ni * 8 + (lane & 3) * 2 + j;   // 0..63
                red_s [wid * 64 + cl] = sl [ni * 2 + j];
                red_ss[wid * 64 + cl] = ssl[ni * 2 + j];
            }
        }
    }
    __syncthreads();
    if (tid < 128) {
        int g   = tid >> 6;       // n-warp group
        int col = tid & 63;
        float s  = red_s [(g * 4 + 0) * 64 + col] + red_s [(g * 4 + 1) * 64 + col]
                 + red_s [(g * 4 + 2) * 64 + col] + red_s [(g * 4 + 3) * 64 + col];
        float ss = red_ss[(g * 4 + 0) * 64 + col] + red_ss[(g * 4 + 1) * 64 + col]
                 + red_ss[(g * 4 + 2) * 64 + col] + red_ss[(g * 4 + 3) * 64 + col];
        int ch = colBlk + g * 64 + col;
        g_part[blockIdx.x * 512 + ch]       = s;
        g_part[blockIdx.x * 512 + 256 + ch] = ss;
    }
}

// ---------------- 5) finalize BN scale/shift -----------------------------
__global__ void k_bn_final(const float* __restrict__ gamma,
                           const float* __restrict__ beta) {
    int t = threadIdx.x;
    float s = 0.f, ss = 0.f;
    for (int i = 0; i < 512; i++) {
        s  += g_part[i * 512 + t];
        ss += g_part[i * 512 + 256 + t];
    }
    const float invN = 1.f / 32768.f;
    float mean = s * invN;
    float var  = ss * invN - mean * mean;
    float inv  = rsqrtf(var + 1e-5f);
    float sc   = gamma[t] * inv;
    g_scale[t] = sc;
    g_shift[t] = beta[t] - mean * sc;
}

// ---------------- 6) affine + SiLU + transpose to NCHW -------------------
__global__ void k_epilogue(float* __restrict__ out) {
    __shared__ float tile[32][33];
    int tx = threadIdx.x, ty = threadIdx.y;
    int o0 = blockIdx.y * 32;
    int r0 = blockIdx.x * 32;
    int orq = o0 + tx;
    float sc = g_scale[orq], sh = g_shift[orq];
    #pragma unroll
    for (int j = 0; j < 4; j++) {
        int r = r0 + ty + j * 8;
        float v = g_outT[(size_t)r * COUT + orq] * sc + sh;
        v = v / (1.f + __expf(-v));
        tile[ty + j * 8][tx] = v;
    }
    __syncthreads();
    int rw = r0 + tx;
    int bb = rw >> 12;
    int hw = rw & 4095;
    #pragma unroll
    for (int j = 0; j < 4; j++) {
        int o = o0 + ty + j * 8;
        out[((size_t)(bb * COUT + o)) * HWSZ + hw] = tile[tx][ty + j * 8];
    }
}

// ---------------- launch ---------------------------------------------------
extern "C" void kernel_launch(void* const* d_in, const int* in_sizes, int n_in,
                              void* d_out, int out_size) {
    const float* x     = (const float*)d_in[0];
    const float* w_off = (const float*)d_in[1];
    const float* b_off = (const float*)d_in[2];
    const float* w_mod = (const float*)d_in[3];
    const float* b_mod = (const float*)d_in[4];
    const float* w_dc  = (const float*)d_in[5];
    const float* gamma = (const float*)d_in[6];
    const float* beta  = (const float*)d_in[7];
    float* out = (float*)d_out;

    cudaFuncSetAttribute(k_conv_tc,  cudaFuncAttributeMaxDynamicSharedMemorySize, CONV_SMEM);
    cudaFuncSetAttribute(k_gemm_f16, cudaFuncAttributeMaxDynamicSharedMemorySize, GEMM_SMEM);

    k_prep<<<dim3(HWSZ / 32, CIN / 32, 9), dim3(32, 8)>>>(x, w_dc, w_off, w_mod);

    k_conv_tc<<<256, 256, CONV_SMEM>>>(b_off, b_mod);

    k_sample<<<dim3(HWSZ / 8, KK9, BATCH), dim3(32, 8)>>>();

    k_gemm_f16<<<dim3(ROWS / 64, 2), 256, GEMM_SMEM>>>();

    k_bn_final<<<1, 256>>>(gamma, beta);

    k_epilogue<<<dim3((BATCH * HWSZ) / 32, COUT / 32), dim3(32, 8)>>>(out);
}

// round 10
// speedup vs baseline: 5.1049x; 1.0750x over previous
#include <cuda_runtime.h>
#include <cuda_fp16.h>
#include <stdint.h>
#include <math.h>

// ---------------- problem constants ----------------
#define BATCH 8
#define CIN   128
#define COUT  256
#define HH    64
#define WW    64
#define HWSZ  4096
#define KK9   9
#define CK    1152          // CIN*KK9
#define NOC   27            // 18 offset + 9 modulation channels
#define ROWS  (BATCH*HWSZ)  // 32768

// ---------------- scratch ------------------------------------------------
__device__ __half g_xTh[BATCH * HWSZ * CIN];        // x channels-last fp16
__device__ float  g_off[BATCH * NOC * HWSZ];        // offsets + modulation(sigmoid)
__device__ __half g_Wch[32 * CK];                   // conv weights fp16, padded to 32 oc
__device__ __half g_Wh [COUT * CK];                 // deform weights fp16
__device__ __half g_V  [(size_t)ROWS * CK];         // sampled*mod fp16
__device__ float  g_outT[(size_t)ROWS * COUT];
__device__ float  g_part[512 * 512];
__device__ float  g_scale[COUT];
__device__ float  g_shift[COUT];

// ---------------- ptx helpers (plain sm_80+ PTX only) --------------------
__device__ __forceinline__ uint32_t smem_u32(const void* p) {
    uint32_t a;
    asm("{ .reg .u64 t; cvta.to.shared.u64 t, %1; cvt.u32.u64 %0, t; }"
        : "=r"(a) : "l"(p));
    return a;
}
__device__ __forceinline__ void cp16(uint32_t dst, const void* src) {
    asm volatile("cp.async.cg.shared.global [%0], [%1], 16;" :: "r"(dst), "l"(src));
}
__device__ __forceinline__ void cp16z(uint32_t dst, const void* src, uint32_t sz) {
    asm volatile("cp.async.cg.shared.global [%0], [%1], 16, %2;"
                 :: "r"(dst), "l"(src), "r"(sz));
}
__device__ __forceinline__ void cp_commit() {
    asm volatile("cp.async.commit_group;" ::: "memory");
}
template <int N>
__device__ __forceinline__ void cp_wait() {
    asm volatile("cp.async.wait_group %0;" :: "n"(N) : "memory");
}
__device__ __forceinline__ void ldm_x4(uint32_t* r, uint32_t addr) {
    asm volatile("ldmatrix.sync.aligned.m8n8.x4.shared.b16 {%0,%1,%2,%3}, [%4];"
        : "=r"(r[0]), "=r"(r[1]), "=r"(r[2]), "=r"(r[3]) : "r"(addr));
}
__device__ __forceinline__ void mma_f16(float* d, const uint32_t* a,
                                        uint32_t b0, uint32_t b1) {
    asm volatile(
        "mma.sync.aligned.m16n8k16.row.col.f32.f16.f16.f32 "
        "{%0,%1,%2,%3}, {%4,%5,%6,%7}, {%8,%9}, {%0,%1,%2,%3};"
        : "+f"(d[0]), "+f"(d[1]), "+f"(d[2]), "+f"(d[3])
        : "r"(a[0]), "r"(a[1]), "r"(a[2]), "r"(a[3]), "r"(b0), "r"(b1));
}

// ---------------- 1) prep: transpose x -> fp16 channels-last + weights ---
__global__ void k_prep(const float* __restrict__ x,
                       const float* __restrict__ w_dc,
                       const float* __restrict__ w_off,
                       const float* __restrict__ w_mod) {
    if (blockIdx.z < 8) {
        __shared__ float tile[32][33];
        int b   = blockIdx.z;
        int hw0 = blockIdx.x * 32;
        int c0  = blockIdx.y * 32;
        int tx = threadIdx.x, ty = threadIdx.y;
        #pragma unroll
        for (int j = 0; j < 4; j++) {
            int c = c0 + ty + j * 8;
            tile[ty + j * 8][tx] = x[((b * CIN) + c) * HWSZ + hw0 + tx];
        }
        __syncthreads();
        #pragma unroll
        for (int j = 0; j < 4; j++) {
            int hw = hw0 + ty + j * 8;
            size_t o = ((size_t)(b * HWSZ) + hw) * CIN + c0 + tx;
            g_xTh[o] = __float2half(tile[tx][ty + j * 8]);
        }
    } else {
        const int NWP  = COUT * CK;         // 294912
        const int NWC2 = 32 * CK;           // 36864
        int t = threadIdx.y * 32 + threadIdx.x;
        int gidx = (blockIdx.y * 128 + blockIdx.x) * 256 + t;
        for (int idx = gidx; idx < NWP + NWC2; idx += 512 * 256) {
            if (idx < NWP) {
                int o  = idx / CK;
                int r  = idx - o * CK;
                int kk = r >> 7;
                int c  = r & 127;
                g_Wh[idx] = __float2half(w_dc[(o * CIN + c) * KK9 + kk]);
            } else {
                int j  = idx - NWP;
                int oc = j / CK;
                int r  = j - oc * CK;
                int kk = r >> 7;
                int c  = r & 127;
                float v = 0.f;
                if (oc < 18)      v = w_off[(oc * CIN + c) * KK9 + kk];
                else if (oc < 27) v = w_mod[((oc - 18) * CIN + c) * KK9 + kk];
                g_Wch[j] = __float2half(v);
            }
        }
    }
}

// ---------------- 2) conv offsets/mod via tensor cores --------------------
#define RCWB   80
#define A2_B   (128 * RCWB)                 // 10240
#define B2_B   (32 * RCWB)                  // 2560
#define CSTG   (A2_B + B2_B)                // 12800
#define CONV_SMEM (2 * CSTG)                // 25600

__device__ __forceinline__ void conv_load_stage(uint32_t buf, int cn,
                                                int rowBlk, int tid) {
    int kk  = cn >> 2;
    int c0k = (cn & 3) * 32;
    int dy = kk / 3 - 1;
    int dx = kk % 3 - 1;
    {
        int row  = tid >> 1;
        int half = tid & 1;
        int pix = rowBlk * 128 + row;
        int b = pix >> 12;
        int h = (pix >> 6) & 63;
        int w = pix & 63;
        int h2 = h + dy, w2 = w + dx;
        bool valid = ((unsigned)h2 < 64u) & ((unsigned)w2 < 64u);
        size_t srcoff = valid
            ? (((size_t)b * HWSZ + h2 * 64 + w2) * CIN + c0k) * 2 : 0;
        uint32_t sz = valid ? 16u : 0u;
        const char* src = (const char*)g_xTh + srcoff + half * 32;
        uint32_t dst = buf + row * RCWB + half * 32;
        cp16z(dst,      src,      sz);
        cp16z(dst + 16, src + 16, sz);
    }
    if (tid < 128) {
        int row = tid >> 2;
        int q   = tid & 3;
        const char* src = (const char*)g_Wch + ((size_t)row * CK + cn * 32) * 2 + q * 16;
        cp16(buf + A2_B + row * RCWB + q * 16, src);
    }
}

__global__ void __launch_bounds__(256) k_conv_tc(const float* __restrict__ b_off,
                                                 const float* __restrict__ b_mod) {
    extern __shared__ __align__(128) char sm[];
    const uint32_t base = smem_u32(sm);
    const int tid  = threadIdx.x;
    const int lane = tid & 31;
    const int wid  = tid >> 5;
    const int rowBlk = blockIdx.x;

    const int lrow  = lane & 15;
    const int lhalf = (lane >> 4) * 16;

    float acc[4][4];
    #pragma unroll
    for (int i = 0; i < 4; i++)
        #pragma unroll
        for (int q = 0; q < 4; q++) acc[i][q] = 0.f;

    conv_load_stage(base, 0, rowBlk, tid);
    cp_commit();

    for (int cn = 0; cn < 36; cn++) {
        int s = cn & 1;
        if (cn + 1 < 36) {
            conv_load_stage(base + ((cn + 1) & 1) * CSTG, cn + 1, rowBlk, tid);
            cp_commit();
            cp_wait<1>();
        } else {
            cp_wait<0>();
        }
        __syncthreads();

        uint32_t bufA = base + s * CSTG;
        uint32_t bufB = bufA + A2_B;

        #pragma unroll
        for (int ks = 0; ks < 2; ks++) {
            uint32_t a[4];
            ldm_x4(a, bufA + (uint32_t)(wid * 16 + lrow) * RCWB + ks * 32 + lhalf);
            uint32_t bfr[2][4];
            #pragma unroll
            for (int pr = 0; pr < 2; pr++)
                ldm_x4(bfr[pr], bufB + (uint32_t)(pr * 16 + lrow) * RCWB + ks * 32 + lhalf);
            #pragma unroll
            for (int pr = 0; pr < 2; pr++) {
                mma_f16(acc[2 * pr],     a, bfr[pr][0], bfr[pr][2]);
                mma_f16(acc[2 * pr + 1], a, bfr[pr][1], bfr[pr][3]);
            }
        }
        __syncthreads();
    }

    int pix0 = rowBlk * 128 + wid * 16 + (lane >> 2);
    int b = pix0 >> 12;
    #pragma unroll
    for (int ni = 0; ni < 4; ni++) {
        #pragma unroll
        for (int q = 0; q < 4; q++) {
            int oc = ni * 8 + (lane & 3) * 2 + (q & 1);
            if (oc >= NOC) continue;
            int pix = pix0 + (q >> 1) * 8;
            float bias = (oc < 18) ? b_off[oc] : b_mod[oc - 18];
            float v = acc[ni][q] + bias;
            if (oc >= 18) v = 1.f / (1.f + __expf(-v));
            g_off[((size_t)b * NOC + oc) * HWSZ + (pix & 4095)] = v;
        }
    }
}

// ---------------- 3) bilinear sampling (fp16 src, 8 ch/thread) -----------
__global__ void __launch_bounds__(256) k_sample() {
    int tx  = threadIdx.x;                  // 0..15 channel octet
    int pos = blockIdx.x * 16 + threadIdx.y;
    int kk  = blockIdx.y;
    int b   = blockIdx.z;
    int h = pos >> 6, w = pos & 63;

    const float* offb = g_off + (b * NOC) * HWSZ;
    float dy = offb[(2 * kk)     * HWSZ + pos];
    float dx = offb[(2 * kk + 1) * HWSZ + pos];
    float m  = offb[(18 + kk)    * HWSZ + pos];

    float py = dy + (float)(h - 1 + kk / 3);
    float px = dx + (float)(w - 1 + kk % 3);
    float fy = floorf(py), fx = floorf(px);
    int y0 = (int)fy, x0 = (int)fx;
    float wy1 = py - fy, wx1 = px - fx;
    float wy0 = 1.f - wy1, wx0 = 1.f - wx1;

    const uint4* xb = (const uint4*)g_xTh + (size_t)(b * HWSZ) * 16;
    float acc[8];
    #pragma unroll
    for (int i = 0; i < 8; i++) acc[i] = 0.f;

    #pragma unroll
    for (int cn = 0; cn < 4; cn++) {
        int yi = y0 + (cn >> 1);
        int xi = x0 + (cn & 1);
        float wt = ((cn >> 1) ? wy1 : wy0) * ((cn & 1) ? wx1 : wx0);
        bool valid = (yi >= 0) & (yi < HH) & (xi >= 0) & (xi < WW);
        float wv = valid ? wt : 0.f;
        int yc = min(max(yi, 0), HH - 1);
        int xc = min(max(xi, 0), WW - 1);
        uint4 v = xb[(yc * WW + xc) * 16 + tx];
        __half2 h0 = *reinterpret_cast<__half2*>(&v.x);
        __half2 h1 = *reinterpret_cast<__half2*>(&v.y);
        __half2 h2 = *reinterpret_cast<__half2*>(&v.z);
        __half2 h3 = *reinterpret_cast<__half2*>(&v.w);
        float2 f0 = __half22float2(h0);
        float2 f1 = __half22float2(h1);
        float2 f2 = __half22float2(h2);
        float2 f3 = __half22float2(h3);
        acc[0] += wv * f0.x; acc[1] += wv * f0.y;
        acc[2] += wv * f1.x; acc[3] += wv * f1.y;
        acc[4] += wv * f2.x; acc[5] += wv * f2.y;
        acc[6] += wv * f3.x; acc[7] += wv * f3.y;
    }
    #pragma unroll
    for (int i = 0; i < 8; i++) acc[i] *= m;

    __half2 p0 = __floats2half2_rn(acc[0], acc[1]);
    __half2 p1 = __floats2half2_rn(acc[2], acc[3]);
    __half2 p2 = __floats2half2_rn(acc[4], acc[5]);
    __half2 p3 = __floats2half2_rn(acc[6], acc[7]);
    uint4 u;
    u.x = *reinterpret_cast<uint32_t*>(&p0);
    u.y = *reinterpret_cast<uint32_t*>(&p1);
    u.z = *reinterpret_cast<uint32_t*>(&p2);
    u.w = *reinterpret_cast<uint32_t*>(&p3);

    size_t e = ((size_t)(b * HWSZ) + pos) * CK + kk * 128 + tx * 8;
    *reinterpret_cast<uint4*>((char*)g_V + e * 2) = u;
}

// ---------------- 4) fp16 GEMM, 64x128 tiles, 3-stage ring, B pipelined ---
#define ROWB       80
#define A_BYTES    (64 * ROWB)         // 5120
#define B_BYTES    (128 * ROWB)        // 10240
#define STAGE_B    (A_BYTES + B_BYTES) // 15360
#define NSTG       3
#define GEMM_SMEM  (NSTG * STAGE_B)    // 46080

__device__ __forceinline__ void gemm_load_stage(uint32_t buf, int c,
                                                int rowBlk, int colBlk, int tid) {
    {
        int row = tid >> 2;
        int cc  = tid & 3;
        const char* src = (const char*)g_V
            + ((size_t)(rowBlk + row) * CK + c * 32) * 2 + cc * 16;
        cp16(buf + row * ROWB + cc * 16, src);
    }
    #pragma unroll
    for (int j = 0; j < 2; j++) {
        int rem = (j << 8) + tid;
        int row = rem >> 2;
        int cc  = rem & 3;
        const char* src = (const char*)g_Wh
            + ((size_t)(colBlk + row) * CK + c * 32) * 2 + cc * 16;
        cp16(buf + A_BYTES + row * ROWB + cc * 16, src);
    }
}

__global__ void __launch_bounds__(256, 4) k_gemm_f16() {
    extern __shared__ __align__(128) char sm[];
    const uint32_t base = smem_u32(sm);
    const int tid  = threadIdx.x;
    const int lane = tid & 31;
    const int wid  = tid >> 5;
    const int rowBlk = blockIdx.x * 64;
    const int colBlk = blockIdx.y * 128;

    const int warpRow = (wid & 3) * 16;     // 4 m-warps
    const int warpCol = (wid >> 2) * 64;    // 2 n-warp groups
    const int lrow  = lane & 15;
    const int lhalf = (lane >> 4) * 16;

    float acc[8][4];
    #pragma unroll
    for (int j = 0; j < 8; j++)
        #pragma unroll
        for (int q = 0; q < 4; q++) acc[j][q] = 0.f;

    gemm_load_stage(base, 0, rowBlk, colBlk, tid);
    cp_commit();
    gemm_load_stage(base + STAGE_B, 1, rowBlk, colBlk, tid);
    cp_commit();

    int st = 0;
    for (int c = 0; c < 36; c++) {
        if (c + 1 < 36) cp_wait<1>(); else cp_wait<0>();
        __syncthreads();

        if (c + 2 < 36) {
            int nst = st + 2; if (nst >= NSTG) nst -= NSTG;
            gemm_load_stage(base + nst * STAGE_B, c + 2, rowBlk, colBlk, tid);
            cp_commit();
        }

        uint32_t bufA = base + st * STAGE_B;
        uint32_t bufB = bufA + A_BYTES;
        uint32_t arow = bufA + (uint32_t)(warpRow + lrow) * ROWB + lhalf;

        uint32_t a0[4], a1[4];
        ldm_x4(a0, arow);
        ldm_x4(a1, arow + 32);

        uint32_t bcur[4], bnxt[4];
        ldm_x4(bcur, bufB + (uint32_t)(warpCol + lrow) * ROWB + lhalf);
        #pragma unroll
        for (int ks = 0; ks < 2; ks++) {
            const uint32_t* a = ks ? a1 : a0;
            #pragma unroll
            for (int pr = 0; pr < 4; pr++) {
                if (!(ks == 1 && pr == 3)) {
                    int nks = (pr < 3) ? ks : 1;
                    int npr = (pr < 3) ? pr + 1 : 0;
                    ldm_x4(bnxt, bufB + (uint32_t)(warpCol + npr * 16 + lrow) * ROWB
                                 + nks * 32 + lhalf);
                }
                mma_f16(acc[2 * pr],     a, bcur[0], bcur[2]);
                mma_f16(acc[2 * pr + 1], a, bcur[1], bcur[3]);
                #pragma unroll
                for (int q = 0; q < 4; q++) bcur[q] = bnxt[q];
            }
        }

        st++; if (st >= NSTG) st = 0;
    }
    __syncthreads();

    // ---- store C (warp m16 x n64)
    {
        int r0 = rowBlk + warpRow + lane / 4;
        #pragma unroll
        for (int ni = 0; ni < 8; ni++) {
            int c0 = colBlk + warpCol + ni * 8 + (lane & 3) * 2;
            float2 v0 = make_float2(acc[ni][0], acc[ni][1]);
            float2 v1 = make_float2(acc[ni][2], acc[ni][3]);
            *(float2*)&g_outT[(size_t)r0 * COUT + c0]       = v0;
            *(float2*)&g_outT[(size_t)(r0 + 8) * COUT + c0] = v1;
        }
    }

    // ---- fused BN partials (deterministic)
    float* red_s  = (float*)sm;            // [8][64]
    float* red_ss = red_s + 8 * 64;        // [8][64]
    float sl[16], ssl[16];
    #pragma unroll
    for (int ni = 0; ni < 8; ni++) {
        #pragma unroll
        for (int j = 0; j < 2; j++) {
            float v0 = acc[ni][j], v1 = acc[ni][2 + j];
            sl [ni * 2 + j] = v0 + v1;
            ssl[ni * 2 + j] = v0 * v0 + v1 * v1;
        }
    }
    #pragma unroll
    for (int k = 0; k < 16; k++) {
        #pragma unroll
        for (int o = 4; o < 32; o <<= 1) {
            sl [k] += __shfl_down_sync(0xFFFFFFFFu, sl [k], o);
            ssl[k] += __shfl_down_sync(0xFFFFFFFFu, ssl[k], o);
        }
    }
    if (lane < 4) {
        #pragma unroll
        for (int ni = 0; ni < 8; ni++) {
            #pragma unroll
            for (int j = 0; j < 2; j++) {
                int cl = ni * 8 + (lane & 3) * 2 + j;   // 0..63
                red_s [wid * 64 + cl] = sl [ni * 2 + j];
                red_ss[wid * 64 + cl] = ssl[ni * 2 + j];
            }
        }
    }
    __syncthreads();
    if (tid < 128) {
        int g   = tid >> 6;       // n-warp group
        int col = tid & 63;
        float s  = red_s [(g * 4 + 0) * 64 + col] + red_s [(g * 4 + 1) * 64 + col]
                 + red_s [(g * 4 + 2) * 64 + col] + red_s [(g * 4 + 3) * 64 + col];
        float ss = red_ss[(g * 4 + 0) * 64 + col] + red_ss[(g * 4 + 1) * 64 + col]
                 + red_ss[(g * 4 + 2) * 64 + col] + red_ss[(g * 4 + 3) * 64 + col];
        int ch = colBlk + g * 64 + col;
        g_part[blockIdx.x * 512 + ch]       = s;
        g_part[blockIdx.x * 512 + 256 + ch] = ss;
    }
}

// ---------------- 5) finalize BN scale/shift -----------------------------
__global__ void k_bn_final(const float* __restrict__ gamma,
                           const float* __restrict__ beta) {
    int t = threadIdx.x;
    float s = 0.f, ss = 0.f;
    for (int i = 0; i < 512; i++) {
        s  += g_part[i * 512 + t];
        ss += g_part[i * 512 + 256 + t];
    }
    const float invN = 1.f / 32768.f;
    float mean = s * invN;
    float var  = ss * invN - mean * mean;
    float inv  = rsqrtf(var + 1e-5f);
    float sc   = gamma[t] * inv;
    g_scale[t] = sc;
    g_shift[t] = beta[t] - mean * sc;
}

// ---------------- 6) affine + SiLU + transpose to NCHW -------------------
__global__ void k_epilogue(float* __restrict__ out) {
    __shared__ float tile[32][33];
    int tx = threadIdx.x, ty = threadIdx.y;
    int o0 = blockIdx.y * 32;
    int r0 = blockIdx.x * 32;
    int orq = o0 + tx;
    float sc = g_scale[orq], sh = g_shift[orq];
    #pragma unroll
    for (int j = 0; j < 4; j++) {
        int r = r0 + ty + j * 8;
        float v = g_outT[(size_t)r * COUT + orq] * sc + sh;
        v = v / (1.f + __expf(-v));
        tile[ty + j * 8][tx] = v;
    }
    __syncthreads();
    int rw = r0 + tx;
    int bb = rw >> 12;
    int hw = rw & 4095;
    #pragma unroll
    for (int j = 0; j < 4; j++) {
        int o = o0 + ty + j * 8;
        out[((size_t)(bb * COUT + o)) * HWSZ + hw] = tile[tx][ty + j * 8];
    }
}

// ---------------- launch ---------------------------------------------------
extern "C" void kernel_launch(void* const* d_in, const int* in_sizes, int n_in,
                              void* d_out, int out_size) {
    const float* x     = (const float*)d_in[0];
    const float* w_off = (const float*)d_in[1];
    const float* b_off = (const float*)d_in[2];
    const float* w_mod = (const float*)d_in[3];
    const float* b_mod = (const float*)d_in[4];
    const float* w_dc  = (const float*)d_in[5];
    const float* gamma = (const float*)d_in[6];
    const float* beta  = (const float*)d_in[7];
    float* out = (float*)d_out;

    cudaFuncSetAttribute(k_conv_tc,  cudaFuncAttributeMaxDynamicSharedMemorySize, CONV_SMEM);
    cudaFuncSetAttribute(k_gemm_f16, cudaFuncAttributeMaxDynamicSharedMemorySize, GEMM_SMEM);

    k_prep<<<dim3(HWSZ / 32, CIN / 32, 9), dim3(32, 8)>>>(x, w_dc, w_off, w_mod);

    k_conv_tc<<<256, 256, CONV_SMEM>>>(b_off, b_mod);

    k_sample<<<dim3(HWSZ / 16, KK9, BATCH), dim3(16, 16)>>>();

    k_gemm_f16<<<dim3(ROWS / 64, 2), 256, GEMM_SMEM>>>();

    k_bn_final<<<1, 256>>>(gamma, beta);

    k_epilogue<<<dim3((BATCH * HWSZ) / 32, COUT / 32), dim3(32, 8)>>>(out);
}

// round 11
// speedup vs baseline: 5.1740x; 1.0135x over previous
#include <cuda_runtime.h>
#include <cuda_fp16.h>
#include <stdint.h>
#include <math.h>

// ---------------- problem constants ----------------
#define BATCH 8
#define CIN   128
#define COUT  256
#define HH    64
#define WW    64
#define HWSZ  4096
#define KK9   9
#define CK    1152          // CIN*KK9
#define NOC   27            // 18 offset + 9 modulation channels
#define ROWS  (BATCH*HWSZ)  // 32768

// ---------------- scratch ------------------------------------------------
__device__ __half g_xTh[BATCH * HWSZ * CIN];        // x channels-last fp16
__device__ float  g_off[BATCH * NOC * HWSZ];        // offsets + modulation(sigmoid)
__device__ __half g_Wch[32 * CK];                   // conv weights fp16, padded to 32 oc
__device__ __half g_Wh [COUT * CK];                 // deform weights fp16
__device__ __half g_V  [(size_t)ROWS * CK];         // sampled*mod fp16
__device__ float  g_outT[(size_t)ROWS * COUT];
__device__ float  g_part[512 * 512];
__device__ float  g_scale[COUT];
__device__ float  g_shift[COUT];

// ---------------- ptx helpers (plain sm_80+ PTX only) --------------------
__device__ __forceinline__ uint32_t smem_u32(const void* p) {
    uint32_t a;
    asm("{ .reg .u64 t; cvta.to.shared.u64 t, %1; cvt.u32.u64 %0, t; }"
        : "=r"(a) : "l"(p));
    return a;
}
__device__ __forceinline__ void cp16(uint32_t dst, const void* src) {
    asm volatile("cp.async.cg.shared.global [%0], [%1], 16;" :: "r"(dst), "l"(src));
}
__device__ __forceinline__ void cp16z(uint32_t dst, const void* src, uint32_t sz) {
    asm volatile("cp.async.cg.shared.global [%0], [%1], 16, %2;"
                 :: "r"(dst), "l"(src), "r"(sz));
}
__device__ __forceinline__ void cp_commit() {
    asm volatile("cp.async.commit_group;" ::: "memory");
}
template <int N>
__device__ __forceinline__ void cp_wait() {
    asm volatile("cp.async.wait_group %0;" :: "n"(N) : "memory");
}
__device__ __forceinline__ void ldm_x4(uint32_t* r, uint32_t addr) {
    asm volatile("ldmatrix.sync.aligned.m8n8.x4.shared.b16 {%0,%1,%2,%3}, [%4];"
        : "=r"(r[0]), "=r"(r[1]), "=r"(r[2]), "=r"(r[3]) : "r"(addr));
}
__device__ __forceinline__ void mma_f16(float* d, const uint32_t* a,
                                        uint32_t b0, uint32_t b1) {
    asm volatile(
        "mma.sync.aligned.m16n8k16.row.col.f32.f16.f16.f32 "
        "{%0,%1,%2,%3}, {%4,%5,%6,%7}, {%8,%9}, {%0,%1,%2,%3};"
        : "+f"(d[0]), "+f"(d[1]), "+f"(d[2]), "+f"(d[3])
        : "r"(a[0]), "r"(a[1]), "r"(a[2]), "r"(a[3]), "r"(b0), "r"(b1));
}

// ---------------- 1) prep: transpose x -> fp16 channels-last + weights ---
__global__ void k_prep(const float* __restrict__ x,
                       const float* __restrict__ w_dc,
                       const float* __restrict__ w_off,
                       const float* __restrict__ w_mod) {
    if (blockIdx.z < 8) {
        __shared__ float tile[32][33];
        int b   = blockIdx.z;
        int hw0 = blockIdx.x * 32;
        int c0  = blockIdx.y * 32;
        int tx = threadIdx.x, ty = threadIdx.y;
        #pragma unroll
        for (int j = 0; j < 4; j++) {
            int c = c0 + ty + j * 8;
            tile[ty + j * 8][tx] = x[((b * CIN) + c) * HWSZ + hw0 + tx];
        }
        __syncthreads();
        #pragma unroll
        for (int j = 0; j < 4; j++) {
            int hw = hw0 + ty + j * 8;
            size_t o = ((size_t)(b * HWSZ) + hw) * CIN + c0 + tx;
            g_xTh[o] = __float2half(tile[tx][ty + j * 8]);
        }
    } else {
        const int NWP  = COUT * CK;         // 294912
        const int NWC2 = 32 * CK;           // 36864
        int t = threadIdx.y * 32 + threadIdx.x;
        int gidx = (blockIdx.y * 128 + blockIdx.x) * 256 + t;
        for (int idx = gidx; idx < NWP + NWC2; idx += 512 * 256) {
            if (idx < NWP) {
                int o  = idx / CK;
                int r  = idx - o * CK;
                int kk = r >> 7;
                int c  = r & 127;
                g_Wh[idx] = __float2half(w_dc[(o * CIN + c) * KK9 + kk]);
            } else {
                int j  = idx - NWP;
                int oc = j / CK;
                int r  = j - oc * CK;
                int kk = r >> 7;
                int c  = r & 127;
                float v = 0.f;
                if (oc < 18)      v = w_off[(oc * CIN + c) * KK9 + kk];
                else if (oc < 27) v = w_mod[((oc - 18) * CIN + c) * KK9 + kk];
                g_Wch[j] = __float2half(v);
            }
        }
    }
}

// ---------------- 2) conv offsets/mod via tensor cores --------------------
#define RCWB   80
#define A2_B   (128 * RCWB)                 // 10240
#define B2_B   (32 * RCWB)                  // 2560
#define CSTG   (A2_B + B2_B)                // 12800
#define CONV_SMEM (2 * CSTG)                // 25600

__device__ __forceinline__ void conv_load_stage(uint32_t buf, int cn,
                                                int rowBlk, int tid) {
    int kk  = cn >> 2;
    int c0k = (cn & 3) * 32;
    int dy = kk / 3 - 1;
    int dx = kk % 3 - 1;
    {
        int row  = tid >> 1;
        int half = tid & 1;
        int pix = rowBlk * 128 + row;
        int b = pix >> 12;
        int h = (pix >> 6) & 63;
        int w = pix & 63;
        int h2 = h + dy, w2 = w + dx;
        bool valid = ((unsigned)h2 < 64u) & ((unsigned)w2 < 64u);
        size_t srcoff = valid
            ? (((size_t)b * HWSZ + h2 * 64 + w2) * CIN + c0k) * 2 : 0;
        uint32_t sz = valid ? 16u : 0u;
        const char* src = (const char*)g_xTh + srcoff + half * 32;
        uint32_t dst = buf + row * RCWB + half * 32;
        cp16z(dst,      src,      sz);
        cp16z(dst + 16, src + 16, sz);
    }
    if (tid < 128) {
        int row = tid >> 2;
        int q   = tid & 3;
        const char* src = (const char*)g_Wch + ((size_t)row * CK + cn * 32) * 2 + q * 16;
        cp16(buf + A2_B + row * RCWB + q * 16, src);
    }
}

__global__ void __launch_bounds__(256) k_conv_tc(const float* __restrict__ b_off,
                                                 const float* __restrict__ b_mod) {
    extern __shared__ __align__(128) char sm[];
    const uint32_t base = smem_u32(sm);
    const int tid  = threadIdx.x;
    const int lane = tid & 31;
    const int wid  = tid >> 5;
    const int rowBlk = blockIdx.x;

    const int lrow  = lane & 15;
    const int lhalf = (lane >> 4) * 16;

    float acc[4][4];
    #pragma unroll
    for (int i = 0; i < 4; i++)
        #pragma unroll
        for (int q = 0; q < 4; q++) acc[i][q] = 0.f;

    conv_load_stage(base, 0, rowBlk, tid);
    cp_commit();

    for (int cn = 0; cn < 36; cn++) {
        int s = cn & 1;
        if (cn + 1 < 36) {
            conv_load_stage(base + ((cn + 1) & 1) * CSTG, cn + 1, rowBlk, tid);
            cp_commit();
            cp_wait<1>();
        } else {
            cp_wait<0>();
        }
        __syncthreads();

        uint32_t bufA = base + s * CSTG;
        uint32_t bufB = bufA + A2_B;

        #pragma unroll
        for (int ks = 0; ks < 2; ks++) {
            uint32_t a[4];
            ldm_x4(a, bufA + (uint32_t)(wid * 16 + lrow) * RCWB + ks * 32 + lhalf);
            uint32_t bfr[2][4];
            #pragma unroll
            for (int pr = 0; pr < 2; pr++)
                ldm_x4(bfr[pr], bufB + (uint32_t)(pr * 16 + lrow) * RCWB + ks * 32 + lhalf);
            #pragma unroll
            for (int pr = 0; pr < 2; pr++) {
                mma_f16(acc[2 * pr],     a, bfr[pr][0], bfr[pr][2]);
                mma_f16(acc[2 * pr + 1], a, bfr[pr][1], bfr[pr][3]);
            }
        }
        __syncthreads();
    }

    int pix0 = rowBlk * 128 + wid * 16 + (lane >> 2);
    int b = pix0 >> 12;
    #pragma unroll
    for (int ni = 0; ni < 4; ni++) {
        #pragma unroll
        for (int q = 0; q < 4; q++) {
            int oc = ni * 8 + (lane & 3) * 2 + (q & 1);
            if (oc >= NOC) continue;
            int pix = pix0 + (q >> 1) * 8;
            float bias = (oc < 18) ? b_off[oc] : b_mod[oc - 18];
            float v = acc[ni][q] + bias;
            if (oc >= 18) v = 1.f / (1.f + __expf(-v));
            g_off[((size_t)b * NOC + oc) * HWSZ + (pix & 4095)] = v;
        }
    }
}

// ---------------- 3) bilinear sampling (fp16 src, 8 ch/thread) -----------
__global__ void __launch_bounds__(256) k_sample() {
    int tx  = threadIdx.x;                  // 0..15 channel octet
    int pos = blockIdx.x * 16 + threadIdx.y;
    int kk  = blockIdx.y;
    int b   = blockIdx.z;
    int h = pos >> 6, w = pos & 63;

    const float* offb = g_off + (b * NOC) * HWSZ;
    float dy = offb[(2 * kk)     * HWSZ + pos];
    float dx = offb[(2 * kk + 1) * HWSZ + pos];
    float m  = offb[(18 + kk)    * HWSZ + pos];

    float py = dy + (float)(h - 1 + kk / 3);
    float px = dx + (float)(w - 1 + kk % 3);
    float fy = floorf(py), fx = floorf(px);
    int y0 = (int)fy, x0 = (int)fx;
    float wy1 = py - fy, wx1 = px - fx;
    float wy0 = 1.f - wy1, wx0 = 1.f - wx1;

    const uint4* xb = (const uint4*)g_xTh + (size_t)(b * HWSZ) * 16;
    float acc[8];
    #pragma unroll
    for (int i = 0; i < 8; i++) acc[i] = 0.f;

    #pragma unroll
    for (int cn = 0; cn < 4; cn++) {
        int yi = y0 + (cn >> 1);
        int xi = x0 + (cn & 1);
        float wt = ((cn >> 1) ? wy1 : wy0) * ((cn & 1) ? wx1 : wx0);
        bool valid = (yi >= 0) & (yi < HH) & (xi >= 0) & (xi < WW);
        float wv = valid ? wt : 0.f;
        int yc = min(max(yi, 0), HH - 1);
        int xc = min(max(xi, 0), WW - 1);
        uint4 v = xb[(yc * WW + xc) * 16 + tx];
        __half2 h0 = *reinterpret_cast<__half2*>(&v.x);
        __half2 h1 = *reinterpret_cast<__half2*>(&v.y);
        __half2 h2 = *reinterpret_cast<__half2*>(&v.z);
        __half2 h3 = *reinterpret_cast<__half2*>(&v.w);
        float2 f0 = __half22float2(h0);
        float2 f1 = __half22float2(h1);
        float2 f2 = __half22float2(h2);
        float2 f3 = __half22float2(h3);
        acc[0] += wv * f0.x; acc[1] += wv * f0.y;
        acc[2] += wv * f1.x; acc[3] += wv * f1.y;
        acc[4] += wv * f2.x; acc[5] += wv * f2.y;
        acc[6] += wv * f3.x; acc[7] += wv * f3.y;
    }
    #pragma unroll
    for (int i = 0; i < 8; i++) acc[i] *= m;

    __half2 p0 = __floats2half2_rn(acc[0], acc[1]);
    __half2 p1 = __floats2half2_rn(acc[2], acc[3]);
    __half2 p2 = __floats2half2_rn(acc[4], acc[5]);
    __half2 p3 = __floats2half2_rn(acc[6], acc[7]);
    uint4 u;
    u.x = *reinterpret_cast<uint32_t*>(&p0);
    u.y = *reinterpret_cast<uint32_t*>(&p1);
    u.z = *reinterpret_cast<uint32_t*>(&p2);
    u.w = *reinterpret_cast<uint32_t*>(&p3);

    size_t e = ((size_t)(b * HWSZ) + pos) * CK + kk * 128 + tx * 8;
    *reinterpret_cast<uint4*>((char*)g_V + e * 2) = u;
}

// ---------------- 4) fp16 GEMM, 64x128 CTA tile, m32n32 warp tile ---------
#define ROWB       80
#define A_BYTES    (64 * ROWB)         // 5120
#define B_BYTES    (128 * ROWB)        // 10240
#define STAGE_B    (A_BYTES + B_BYTES) // 15360
#define NSTG       3
#define GEMM_SMEM  (NSTG * STAGE_B)    // 46080

__device__ __forceinline__ void gemm_load_stage(uint32_t buf, int c,
                                                int rowBlk, int colBlk, int tid) {
    {
        int row = tid >> 2;
        int cc  = tid & 3;
        const char* src = (const char*)g_V
            + ((size_t)(rowBlk + row) * CK + c * 32) * 2 + cc * 16;
        cp16(buf + row * ROWB + cc * 16, src);
    }
    #pragma unroll
    for (int j = 0; j < 2; j++) {
        int rem = (j << 8) + tid;
        int row = rem >> 2;
        int cc  = rem & 3;
        const char* src = (const char*)g_Wh
            + ((size_t)(colBlk + row) * CK + c * 32) * 2 + cc * 16;
        cp16(buf + A_BYTES + row * ROWB + cc * 16, src);
    }
}

__global__ void __launch_bounds__(256, 4) k_gemm_f16() {
    extern __shared__ __align__(128) char sm[];
    const uint32_t base = smem_u32(sm);
    const int tid  = threadIdx.x;
    const int lane = tid & 31;
    const int wid  = tid >> 5;
    const int rowBlk = blockIdx.x * 64;
    const int colBlk = blockIdx.y * 128;

    const int warpRow = (wid & 1) * 32;     // 2 m-warps (m32 each)
    const int warpCol = (wid >> 1) * 32;    // 4 n-warps (n32 each)
    const int lrow  = lane & 15;
    const int lhalf = (lane >> 4) * 16;

    float acc[2][4][4];
    #pragma unroll
    for (int mi = 0; mi < 2; mi++)
        #pragma unroll
        for (int ni = 0; ni < 4; ni++)
            #pragma unroll
            for (int q = 0; q < 4; q++) acc[mi][ni][q] = 0.f;

    gemm_load_stage(base, 0, rowBlk, colBlk, tid);
    cp_commit();
    gemm_load_stage(base + STAGE_B, 1, rowBlk, colBlk, tid);
    cp_commit();

    int st = 0;
    for (int c = 0; c < 36; c++) {
        if (c + 1 < 36) cp_wait<1>(); else cp_wait<0>();
        __syncthreads();

        if (c + 2 < 36) {
            int nst = st + 2; if (nst >= NSTG) nst -= NSTG;
            gemm_load_stage(base + nst * STAGE_B, c + 2, rowBlk, colBlk, tid);
            cp_commit();
        }

        uint32_t bufA = base + st * STAGE_B;
        uint32_t bufB = bufA + A_BYTES;

        #pragma unroll
        for (int ks = 0; ks < 2; ks++) {
            uint32_t koff = ks * 32 + lhalf;
            uint32_t a0[4], a1[4], b0[4], b1[4];
            ldm_x4(a0, bufA + (uint32_t)(warpRow + lrow) * ROWB + koff);
            ldm_x4(a1, bufA + (uint32_t)(warpRow + 16 + lrow) * ROWB + koff);
            ldm_x4(b0, bufB + (uint32_t)(warpCol + lrow) * ROWB + koff);
            ldm_x4(b1, bufB + (uint32_t)(warpCol + 16 + lrow) * ROWB + koff);
            // 8 MMAs on 8 distinct accumulators
            mma_f16(acc[0][0], a0, b0[0], b0[2]);
            mma_f16(acc[0][1], a0, b0[1], b0[3]);
            mma_f16(acc[0][2], a0, b1[0], b1[2]);
            mma_f16(acc[0][3], a0, b1[1], b1[3]);
            mma_f16(acc[1][0], a1, b0[0], b0[2]);
            mma_f16(acc[1][1], a1, b0[1], b0[3]);
            mma_f16(acc[1][2], a1, b1[0], b1[2]);
            mma_f16(acc[1][3], a1, b1[1], b1[3]);
        }

        st++; if (st >= NSTG) st = 0;
    }
    __syncthreads();

    // ---- store C (warp m32 x n32)
    #pragma unroll
    for (int mi = 0; mi < 2; mi++) {
        int r0 = rowBlk + warpRow + mi * 16 + lane / 4;
        #pragma unroll
        for (int ni = 0; ni < 4; ni++) {
            int c0 = colBlk + warpCol + ni * 8 + (lane & 3) * 2;
            float2 v0 = make_float2(acc[mi][ni][0], acc[mi][ni][1]);
            float2 v1 = make_float2(acc[mi][ni][2], acc[mi][ni][3]);
            *(float2*)&g_outT[(size_t)r0 * COUT + c0]       = v0;
            *(float2*)&g_outT[(size_t)(r0 + 8) * COUT + c0] = v1;
        }
    }

    // ---- fused BN partials (deterministic)
    float* red_s  = (float*)sm;            // [8][32]
    float* red_ss = red_s + 8 * 32;        // [8][32]
    float sl[8], ssl[8];
    #pragma unroll
    for (int ni = 0; ni < 4; ni++) {
        #pragma unroll
        for (int j = 0; j < 2; j++) {
            float v0 = acc[0][ni][j], v1 = acc[0][ni][2 + j];
            float v2 = acc[1][ni][j], v3 = acc[1][ni][2 + j];
            sl [ni * 2 + j] = v0 + v1 + v2 + v3;
            ssl[ni * 2 + j] = v0 * v0 + v1 * v1 + v2 * v2 + v3 * v3;
        }
    }
    #pragma unroll
    for (int k = 0; k < 8; k++) {
        #pragma unroll
        for (int o = 4; o < 32; o <<= 1) {
            sl [k] += __shfl_down_sync(0xFFFFFFFFu, sl [k], o);
            ssl[k] += __shfl_down_sync(0xFFFFFFFFu, ssl[k], o);
        }
    }
    if (lane < 4) {
        #pragma unroll
        for (int ni = 0; ni < 4; ni++) {
            #pragma unroll
            for (int j = 0; j < 2; j++) {
                int cl = ni * 8 + lane * 2 + j;      // 0..31 within warp's n32
                red_s [wid * 32 + cl] = sl [ni * 2 + j];
                red_ss[wid * 32 + cl] = ssl[ni * 2 + j];
            }
        }
    }
    __syncthreads();
    if (tid < 128) {
        int col = tid;                 // 0..127 within colBlk
        int g   = col >> 5;            // which n-warp pair
        int cl  = col & 31;
        float s  = red_s [(2 * g) * 32 + cl] + red_s [(2 * g + 1) * 32 + cl];
        float ss = red_ss[(2 * g) * 32 + cl] + red_ss[(2 * g + 1) * 32 + cl];
        int ch = colBlk + col;
        g_part[blockIdx.x * 512 + ch]       = s;
        g_part[blockIdx.x * 512 + 256 + ch] = ss;
    }
}

// ---------------- 5) finalize BN scale/shift -----------------------------
__global__ void k_bn_final(const float* __restrict__ gamma,
                           const float* __restrict__ beta) {
    int t = threadIdx.x;
    float s = 0.f, ss = 0.f;
    for (int i = 0; i < 512; i++) {
        s  += g_part[i * 512 + t];
        ss += g_part[i * 512 + 256 + t];
    }
    const float invN = 1.f / 32768.f;
    float mean = s * invN;
    float var  = ss * invN - mean * mean;
    float inv  = rsqrtf(var + 1e-5f);
    float sc   = gamma[t] * inv;
    g_scale[t] = sc;
    g_shift[t] = beta[t] - mean * sc;
}

// ---------------- 6) affine + SiLU + transpose to NCHW -------------------
__global__ void k_epilogue(float* __restrict__ out) {
    __shared__ float tile[32][33];
    int tx = threadIdx.x, ty = threadIdx.y;
    int o0 = blockIdx.y * 32;
    int r0 = blockIdx.x * 32;
    int orq = o0 + tx;
    float sc = g_scale[orq], sh = g_shift[orq];
    #pragma unroll
    for (int j = 0; j < 4; j++) {
        int r = r0 + ty + j * 8;
        float v = g_outT[(size_t)r * COUT + orq] * sc + sh;
        v = v / (1.f + __expf(-v));
        tile[ty + j * 8][tx] = v;
    }
    __syncthreads();
    int rw = r0 + tx;
    int bb = rw >> 12;
    int hw = rw & 4095;
    #pragma unroll
    for (int j = 0; j < 4; j++) {
        int o = o0 + ty + j * 8;
        out[((size_t)(bb * COUT + o)) * HWSZ + hw] = tile[tx][ty + j * 8];
    }
}

// ---------------- launch ---------------------------------------------------
extern "C" void kernel_launch(void* const* d_in, const int* in_sizes, int n_in,
                              void* d_out, int out_size) {
    const float* x     = (const float*)d_in[0];
    const float* w_off = (const float*)d_in[1];
    const float* b_off = (const float*)d_in[2];
    const float* w_mod = (const float*)d_in[3];
    const float* b_mod = (const float*)d_in[4];
    const float* w_dc  = (const float*)d_in[5];
    const float* gamma = (const float*)d_in[6];
    const float* beta  = (const float*)d_in[7];
    float* out = (float*)d_out;

    cudaFuncSetAttribute(k_conv_tc,  cudaFuncAttributeMaxDynamicSharedMemorySize, CONV_SMEM);
    cudaFuncSetAttribute(k_gemm_f16, cudaFuncAttributeMaxDynamicSharedMemorySize, GEMM_SMEM);

    k_prep<<<dim3(HWSZ / 32, CIN / 32, 9), dim3(32, 8)>>>(x, w_dc, w_off, w_mod);

    k_conv_tc<<<256, 256, CONV_SMEM>>>(b_off, b_mod);

    k_sample<<<dim3(HWSZ / 16, KK9, BATCH), dim3(16, 16)>>>();

    k_gemm_f16<<<dim3(ROWS / 64, 2), 256, GEMM_SMEM>>>();

    k_bn_final<<<1, 256>>>(gamma, beta);

    k_epilogue<<<dim3((BATCH * HWSZ) / 32, COUT / 32), dim3(32, 8)>>>(out);
}

// round 12
// speedup vs baseline: 5.2572x; 1.0161x over previous
#include <cuda_runtime.h>
#include <cuda_fp16.h>
#include <stdint.h>
#include <math.h>

// ---------------- problem constants ----------------
#define BATCH 8
#define CIN   128
#define COUT  256
#define HH    64
#define WW    64
#define HWSZ  4096
#define KK9   9
#define CK    1152          // CIN*KK9
#define NOC   27            // 18 offset + 9 modulation channels
#define ROWS  (BATCH*HWSZ)  // 32768

// ---------------- scratch ------------------------------------------------
__device__ __half g_xTh[BATCH * HWSZ * CIN];        // x channels-last fp16
__device__ float  g_off[BATCH * NOC * HWSZ];        // offsets + modulation(sigmoid)
__device__ __half g_Wch[32 * CK];                   // conv weights fp16, padded to 32 oc
__device__ __half g_Wh [COUT * CK];                 // deform weights fp16
__device__ __half g_V  [(size_t)ROWS * CK];         // sampled*mod fp16
__device__ float  g_outT[(size_t)ROWS * COUT];
__device__ float  g_part[512 * 512];
__device__ float  g_scale[COUT];
__device__ float  g_shift[COUT];

// ---------------- ptx helpers (plain sm_80+ PTX only) --------------------
__device__ __forceinline__ uint32_t smem_u32(const void* p) {
    uint32_t a;
    asm("{ .reg .u64 t; cvta.to.shared.u64 t, %1; cvt.u32.u64 %0, t; }"
        : "=r"(a) : "l"(p));
    return a;
}
__device__ __forceinline__ void cp16(uint32_t dst, const void* src) {
    asm volatile("cp.async.cg.shared.global [%0], [%1], 16;" :: "r"(dst), "l"(src));
}
__device__ __forceinline__ void cp16z(uint32_t dst, const void* src, uint32_t sz) {
    asm volatile("cp.async.cg.shared.global [%0], [%1], 16, %2;"
                 :: "r"(dst), "l"(src), "r"(sz));
}
__device__ __forceinline__ void cp_commit() {
    asm volatile("cp.async.commit_group;" ::: "memory");
}
template <int N>
__device__ __forceinline__ void cp_wait() {
    asm volatile("cp.async.wait_group %0;" :: "n"(N) : "memory");
}
__device__ __forceinline__ void ldm_x4(uint32_t* r, uint32_t addr) {
    asm volatile("ldmatrix.sync.aligned.m8n8.x4.shared.b16 {%0,%1,%2,%3}, [%4];"
        : "=r"(r[0]), "=r"(r[1]), "=r"(r[2]), "=r"(r[3]) : "r"(addr));
}
__device__ __forceinline__ void mma_f16(float* d, const uint32_t* a,
                                        uint32_t b0, uint32_t b1) {
    asm volatile(
        "mma.sync.aligned.m16n8k16.row.col.f32.f16.f16.f32 "
        "{%0,%1,%2,%3}, {%4,%5,%6,%7}, {%8,%9}, {%0,%1,%2,%3};"
        : "+f"(d[0]), "+f"(d[1]), "+f"(d[2]), "+f"(d[3])
        : "r"(a[0]), "r"(a[1]), "r"(a[2]), "r"(a[3]), "r"(b0), "r"(b1));
}

// ---------------- 1) prep: transpose x -> fp16 channels-last + weights ---
__global__ void k_prep(const float* __restrict__ x,
                       const float* __restrict__ w_dc,
                       const float* __restrict__ w_off,
                       const float* __restrict__ w_mod) {
    if (blockIdx.z < 8) {
        __shared__ float tile[32][33];
        int b   = blockIdx.z;
        int hw0 = blockIdx.x * 32;
        int c0  = blockIdx.y * 32;
        int tx = threadIdx.x, ty = threadIdx.y;
        #pragma unroll
        for (int j = 0; j < 4; j++) {
            int c = c0 + ty + j * 8;
            tile[ty + j * 8][tx] = x[((b * CIN) + c) * HWSZ + hw0 + tx];
        }
        __syncthreads();
        #pragma unroll
        for (int j = 0; j < 4; j++) {
            int hw = hw0 + ty + j * 8;
            size_t o = ((size_t)(b * HWSZ) + hw) * CIN + c0 + tx;
            g_xTh[o] = __float2half(tile[tx][ty + j * 8]);
        }
    } else {
        const int NWP  = COUT * CK;         // 294912
        const int NWC2 = 32 * CK;           // 36864
        int t = threadIdx.y * 32 + threadIdx.x;
        int gidx = (blockIdx.y * 128 + blockIdx.x) * 256 + t;
        for (int idx = gidx; idx < NWP + NWC2; idx += 512 * 256) {
            if (idx < NWP) {
                int o  = idx / CK;
                int r  = idx - o * CK;
                int kk = r >> 7;
                int c  = r & 127;
                g_Wh[idx] = __float2half(w_dc[(o * CIN + c) * KK9 + kk]);
            } else {
                int j  = idx - NWP;
                int oc = j / CK;
                int r  = j - oc * CK;
                int kk = r >> 7;
                int c  = r & 127;
                float v = 0.f;
                if (oc < 18)      v = w_off[(oc * CIN + c) * KK9 + kk];
                else if (oc < 27) v = w_mod[((oc - 18) * CIN + c) * KK9 + kk];
                g_Wch[j] = __float2half(v);
            }
        }
    }
}

// ---------------- 2) conv offsets/mod via tensor cores --------------------
#define RCWB   80
#define A2_B   (128 * RCWB)                 // 10240
#define B2_B   (32 * RCWB)                  // 2560
#define CSTG   (A2_B + B2_B)                // 12800
#define CONV_SMEM (2 * CSTG)                // 25600

__device__ __forceinline__ void conv_load_stage(uint32_t buf, int cn,
                                                int rowBlk, int tid) {
    int kk  = cn >> 2;
    int c0k = (cn & 3) * 32;
    int dy = kk / 3 - 1;
    int dx = kk % 3 - 1;
    {
        int row  = tid >> 1;
        int half = tid & 1;
        int pix = rowBlk * 128 + row;
        int b = pix >> 12;
        int h = (pix >> 6) & 63;
        int w = pix & 63;
        int h2 = h + dy, w2 = w + dx;
        bool valid = ((unsigned)h2 < 64u) & ((unsigned)w2 < 64u);
        size_t srcoff = valid
            ? (((size_t)b * HWSZ + h2 * 64 + w2) * CIN + c0k) * 2 : 0;
        uint32_t sz = valid ? 16u : 0u;
        const char* src = (const char*)g_xTh + srcoff + half * 32;
        uint32_t dst = buf + row * RCWB + half * 32;
        cp16z(dst,      src,      sz);
        cp16z(dst + 16, src + 16, sz);
    }
    if (tid < 128) {
        int row = tid >> 2;
        int q   = tid & 3;
        const char* src = (const char*)g_Wch + ((size_t)row * CK + cn * 32) * 2 + q * 16;
        cp16(buf + A2_B + row * RCWB + q * 16, src);
    }
}

__global__ void __launch_bounds__(256) k_conv_tc(const float* __restrict__ b_off,
                                                 const float* __restrict__ b_mod) {
    extern __shared__ __align__(128) char sm[];
    const uint32_t base = smem_u32(sm);
    const int tid  = threadIdx.x;
    const int lane = tid & 31;
    const int wid  = tid >> 5;
    const int rowBlk = blockIdx.x;

    const int lrow  = lane & 15;
    const int lhalf = (lane >> 4) * 16;

    float acc[4][4];
    #pragma unroll
    for (int i = 0; i < 4; i++)
        #pragma unroll
        for (int q = 0; q < 4; q++) acc[i][q] = 0.f;

    conv_load_stage(base, 0, rowBlk, tid);
    cp_commit();

    for (int cn = 0; cn < 36; cn++) {
        int s = cn & 1;
        if (cn + 1 < 36) {
            conv_load_stage(base + ((cn + 1) & 1) * CSTG, cn + 1, rowBlk, tid);
            cp_commit();
            cp_wait<1>();
        } else {
            cp_wait<0>();
        }
        __syncthreads();

        uint32_t bufA = base + s * CSTG;
        uint32_t bufB = bufA + A2_B;

        #pragma unroll
        for (int ks = 0; ks < 2; ks++) {
            uint32_t a[4];
            ldm_x4(a, bufA + (uint32_t)(wid * 16 + lrow) * RCWB + ks * 32 + lhalf);
            uint32_t bfr[2][4];
            #pragma unroll
            for (int pr = 0; pr < 2; pr++)
                ldm_x4(bfr[pr], bufB + (uint32_t)(pr * 16 + lrow) * RCWB + ks * 32 + lhalf);
            #pragma unroll
            for (int pr = 0; pr < 2; pr++) {
                mma_f16(acc[2 * pr],     a, bfr[pr][0], bfr[pr][2]);
                mma_f16(acc[2 * pr + 1], a, bfr[pr][1], bfr[pr][3]);
            }
        }
        __syncthreads();
    }

    int pix0 = rowBlk * 128 + wid * 16 + (lane >> 2);
    int b = pix0 >> 12;
    #pragma unroll
    for (int ni = 0; ni < 4; ni++) {
        #pragma unroll
        for (int q = 0; q < 4; q++) {
            int oc = ni * 8 + (lane & 3) * 2 + (q & 1);
            if (oc >= NOC) continue;
            int pix = pix0 + (q >> 1) * 8;
            float bias = (oc < 18) ? b_off[oc] : b_mod[oc - 18];
            float v = acc[ni][q] + bias;
            if (oc >= 18) v = 1.f / (1.f + __expf(-v));
            g_off[((size_t)b * NOC + oc) * HWSZ + (pix & 4095)] = v;
        }
    }
}

// ---------------- 3) bilinear sampling (fp16 src, 8 ch/thread) -----------
__global__ void __launch_bounds__(256) k_sample() {
    int tx  = threadIdx.x;                  // 0..15 channel octet
    int pos = blockIdx.x * 16 + threadIdx.y;
    int kk  = blockIdx.y;
    int b   = blockIdx.z;
    int h = pos >> 6, w = pos & 63;

    const float* offb = g_off + (b * NOC) * HWSZ;
    float dy = offb[(2 * kk)     * HWSZ + pos];
    float dx = offb[(2 * kk + 1) * HWSZ + pos];
    float m  = offb[(18 + kk)    * HWSZ + pos];

    float py = dy + (float)(h - 1 + kk / 3);
    float px = dx + (float)(w - 1 + kk % 3);
    float fy = floorf(py), fx = floorf(px);
    int y0 = (int)fy, x0 = (int)fx;
    float wy1 = py - fy, wx1 = px - fx;
    float wy0 = 1.f - wy1, wx0 = 1.f - wx1;

    const uint4* xb = (const uint4*)g_xTh + (size_t)(b * HWSZ) * 16;
    float acc[8];
    #pragma unroll
    for (int i = 0; i < 8; i++) acc[i] = 0.f;

    #pragma unroll
    for (int cn = 0; cn < 4; cn++) {
        int yi = y0 + (cn >> 1);
        int xi = x0 + (cn & 1);
        float wt = ((cn >> 1) ? wy1 : wy0) * ((cn & 1) ? wx1 : wx0);
        bool valid = (yi >= 0) & (yi < HH) & (xi >= 0) & (xi < WW);
        float wv = valid ? wt : 0.f;
        int yc = min(max(yi, 0), HH - 1);
        int xc = min(max(xi, 0), WW - 1);
        uint4 v = xb[(yc * WW + xc) * 16 + tx];
        __half2 h0 = *reinterpret_cast<__half2*>(&v.x);
        __half2 h1 = *reinterpret_cast<__half2*>(&v.y);
        __half2 h2 = *reinterpret_cast<__half2*>(&v.z);
        __half2 h3 = *reinterpret_cast<__half2*>(&v.w);
        float2 f0 = __half22float2(h0);
        float2 f1 = __half22float2(h1);
        float2 f2 = __half22float2(h2);
        float2 f3 = __half22float2(h3);
        acc[0] += wv * f0.x; acc[1] += wv * f0.y;
        acc[2] += wv * f1.x; acc[3] += wv * f1.y;
        acc[4] += wv * f2.x; acc[5] += wv * f2.y;
        acc[6] += wv * f3.x; acc[7] += wv * f3.y;
    }
    #pragma unroll
    for (int i = 0; i < 8; i++) acc[i] *= m;

    __half2 p0 = __floats2half2_rn(acc[0], acc[1]);
    __half2 p1 = __floats2half2_rn(acc[2], acc[3]);
    __half2 p2 = __floats2half2_rn(acc[4], acc[5]);
    __half2 p3 = __floats2half2_rn(acc[6], acc[7]);
    uint4 u;
    u.x = *reinterpret_cast<uint32_t*>(&p0);
    u.y = *reinterpret_cast<uint32_t*>(&p1);
    u.z = *reinterpret_cast<uint32_t*>(&p2);
    u.w = *reinterpret_cast<uint32_t*>(&p3);

    size_t e = ((size_t)(b * HWSZ) + pos) * CK + kk * 128 + tx * 8;
    *reinterpret_cast<uint4*>((char*)g_V + e * 2) = u;
}

// ---------------- 4) fp16 GEMM, m32n32 warps, hoisted ptrs, frag prefetch -
#define ROWB       80
#define A_BYTES    (64 * ROWB)         // 5120
#define B_BYTES    (128 * ROWB)        // 10240
#define STAGE_B    (A_BYTES + B_BYTES) // 15360
#define NSTG       3
#define GEMM_SMEM  (NSTG * STAGE_B)    // 46080
#define ROWSKIP    ((size_t)64 * CK * 2)   // 64-row global stride in bytes

__global__ void __launch_bounds__(256, 4) k_gemm_f16() {
    extern __shared__ __align__(128) char sm[];
    const uint32_t base = smem_u32(sm);
    const int tid  = threadIdx.x;
    const int lane = tid & 31;
    const int wid  = tid >> 5;
    const int rowBlk = blockIdx.x * 64;
    const int colBlk = blockIdx.y * 128;

    const int warpRow = (wid & 1) * 32;     // 2 m-warps (m32 each)
    const int warpCol = (wid >> 1) * 32;    // 4 n-warps (n32 each)
    const int lrow  = lane & 15;
    const int lhalf = (lane >> 4) * 16;

    // ---- loader: fixed per-thread coordinates, pointers advance +64B/chunk
    const int ldrow = tid >> 2;             // 0..63
    const int ldcc  = (tid & 3) * 16;       // 0/16/32/48
    const char* pa = (const char*)g_V
        + ((size_t)(rowBlk + ldrow) * CK) * 2 + ldcc;
    const char* pb = (const char*)g_Wh
        + ((size_t)(colBlk + ldrow) * CK) * 2 + ldcc;
    const uint32_t dA = (uint32_t)ldrow * ROWB + ldcc;
    const uint32_t dB = A_BYTES + (uint32_t)ldrow * ROWB + ldcc;

    float acc[2][4][4];
    #pragma unroll
    for (int mi = 0; mi < 2; mi++)
        #pragma unroll
        for (int ni = 0; ni < 4; ni++)
            #pragma unroll
            for (int q = 0; q < 4; q++) acc[mi][ni][q] = 0.f;

    // prologue: stages 0,1
    #pragma unroll
    for (int p = 0; p < 2; p++) {
        uint32_t buf = base + p * STAGE_B;
        cp16(buf + dA,                 pa);
        cp16(buf + dB,                 pb);
        cp16(buf + dB + 64 * ROWB,     pb + ROWSKIP);
        cp_commit();
        pa += 64; pb += 64;
    }

    int st = 0;
    for (int c = 0; c < 36; c++) {
        if (c + 1 < 36) cp_wait<1>(); else cp_wait<0>();
        __syncthreads();

        if (c + 2 < 36) {
            int nst = st + 2; if (nst >= NSTG) nst -= NSTG;
            uint32_t buf = base + nst * STAGE_B;
            cp16(buf + dA,             pa);
            cp16(buf + dB,             pb);
            cp16(buf + dB + 64 * ROWB, pb + ROWSKIP);
            cp_commit();
            pa += 64; pb += 64;
        }

        uint32_t bufA = base + st * STAGE_B;
        uint32_t bufB = bufA + A_BYTES;
        uint32_t arow0 = bufA + (uint32_t)(warpRow + lrow) * ROWB + lhalf;
        uint32_t brow0 = bufB + (uint32_t)(warpCol + lrow) * ROWB + lhalf;

        // prefetch: a-frags both ks + b-frags ks0
        uint32_t a00[4], a01[4], a10[4], a11[4], b0[4], b1[4];
        ldm_x4(a00, arow0);
        ldm_x4(a01, arow0 + 16 * ROWB);
        ldm_x4(b0,  brow0);
        ldm_x4(b1,  brow0 + 16 * ROWB);
        ldm_x4(a10, arow0 + 32);
        ldm_x4(a11, arow0 + 16 * ROWB + 32);

        // ks0: 8 MMAs (operands loaded >= 2 LDSM ago)
        mma_f16(acc[0][0], a00, b0[0], b0[2]);
        mma_f16(acc[0][1], a00, b0[1], b0[3]);
        mma_f16(acc[0][2], a00, b1[0], b1[2]);
        mma_f16(acc[0][3], a00, b1[1], b1[3]);
        mma_f16(acc[1][0], a01, b0[0], b0[2]);
        mma_f16(acc[1][1], a01, b0[1], b0[3]);
        mma_f16(acc[1][2], a01, b1[0], b1[2]);
        mma_f16(acc[1][3], a01, b1[1], b1[3]);

        // ks1 b-frags then 8 MMAs
        ldm_x4(b0, brow0 + 32);
        ldm_x4(b1, brow0 + 16 * ROWB + 32);
        mma_f16(acc[0][0], a10, b0[0], b0[2]);
        mma_f16(acc[0][1], a10, b0[1], b0[3]);
        mma_f16(acc[0][2], a10, b1[0], b1[2]);
        mma_f16(acc[0][3], a10, b1[1], b1[3]);
        mma_f16(acc[1][0], a11, b0[0], b0[2]);
        mma_f16(acc[1][1], a11, b0[1], b0[3]);
        mma_f16(acc[1][2], a11, b1[0], b1[2]);
        mma_f16(acc[1][3], a11, b1[1], b1[3]);

        st++; if (st >= NSTG) st = 0;
    }
    __syncthreads();

    // ---- store C (warp m32 x n32)
    #pragma unroll
    for (int mi = 0; mi < 2; mi++) {
        int r0 = rowBlk + warpRow + mi * 16 + lane / 4;
        #pragma unroll
        for (int ni = 0; ni < 4; ni++) {
            int c0 = colBlk + warpCol + ni * 8 + (lane & 3) * 2;
            float2 v0 = make_float2(acc[mi][ni][0], acc[mi][ni][1]);
            float2 v1 = make_float2(acc[mi][ni][2], acc[mi][ni][3]);
            *(float2*)&g_outT[(size_t)r0 * COUT + c0]       = v0;
            *(float2*)&g_outT[(size_t)(r0 + 8) * COUT + c0] = v1;
        }
    }

    // ---- fused BN partials (deterministic)
    float* red_s  = (float*)sm;            // [8][32]
    float* red_ss = red_s + 8 * 32;        // [8][32]
    float sl[8], ssl[8];
    #pragma unroll
    for (int ni = 0; ni < 4; ni++) {
        #pragma unroll
        for (int j = 0; j < 2; j++) {
            float v0 = acc[0][ni][j], v1 = acc[0][ni][2 + j];
            float v2 = acc[1][ni][j], v3 = acc[1][ni][2 + j];
            sl [ni * 2 + j] = v0 + v1 + v2 + v3;
            ssl[ni * 2 + j] = v0 * v0 + v1 * v1 + v2 * v2 + v3 * v3;
        }
    }
    #pragma unroll
    for (int k = 0; k < 8; k++) {
        #pragma unroll
        for (int o = 4; o < 32; o <<= 1) {
            sl [k] += __shfl_down_sync(0xFFFFFFFFu, sl [k], o);
            ssl[k] += __shfl_down_sync(0xFFFFFFFFu, ssl[k], o);
        }
    }
    if (lane < 4) {
        #pragma unroll
        for (int ni = 0; ni < 4; ni++) {
            #pragma unroll
            for (int j = 0; j < 2; j++) {
                int cl = ni * 8 + lane * 2 + j;      // 0..31 within warp's n32
                red_s [wid * 32 + cl] = sl [ni * 2 + j];
                red_ss[wid * 32 + cl] = ssl[ni * 2 + j];
            }
        }
    }
    __syncthreads();
    if (tid < 128) {
        int col = tid;                 // 0..127 within colBlk
        int g   = col >> 5;            // which n-warp pair
        int cl  = col & 31;
        float s  = red_s [(2 * g) * 32 + cl] + red_s [(2 * g + 1) * 32 + cl];
        float ss = red_ss[(2 * g) * 32 + cl] + red_ss[(2 * g + 1) * 32 + cl];
        int ch = colBlk + col;
        g_part[blockIdx.x * 512 + ch]       = s;
        g_part[blockIdx.x * 512 + 256 + ch] = ss;
    }
}

// ---------------- 5) finalize BN scale/shift -----------------------------
__global__ void k_bn_final(const float* __restrict__ gamma,
                           const float* __restrict__ beta) {
    int t = threadIdx.x;
    float s = 0.f, ss = 0.f;
    for (int i = 0; i < 512; i++) {
        s  += g_part[i * 512 + t];
        ss += g_part[i * 512 + 256 + t];
    }
    const float invN = 1.f / 32768.f;
    float mean = s * invN;
    float var  = ss * invN - mean * mean;
    float inv  = rsqrtf(var + 1e-5f);
    float sc   = gamma[t] * inv;
    g_scale[t] = sc;
    g_shift[t] = beta[t] - mean * sc;
}

// ---------------- 6) affine + SiLU + transpose to NCHW -------------------
__global__ void k_epilogue(float* __restrict__ out) {
    __shared__ float tile[32][33];
    int tx = threadIdx.x, ty = threadIdx.y;
    int o0 = blockIdx.y * 32;
    int r0 = blockIdx.x * 32;
    int orq = o0 + tx;
    float sc = g_scale[orq], sh = g_shift[orq];
    #pragma unroll
    for (int j = 0; j < 4; j++) {
        int r = r0 + ty + j * 8;
        float v = g_outT[(size_t)r * COUT + orq] * sc + sh;
        v = v / (1.f + __expf(-v));
        tile[ty + j * 8][tx] = v;
    }
    __syncthreads();
    int rw = r0 + tx;
    int bb = rw >> 12;
    int hw = rw & 4095;
    #pragma unroll
    for (int j = 0; j < 4; j++) {
        int o = o0 + ty + j * 8;
        out[((size_t)(bb * COUT + o)) * HWSZ + hw] = tile[tx][ty + j * 8];
    }
}

// ---------------- launch ---------------------------------------------------
extern "C" void kernel_launch(void* const* d_in, const int* in_sizes, int n_in,
                              void* d_out, int out_size) {
    const float* x     = (const float*)d_in[0];
    const float* w_off = (const float*)d_in[1];
    const float* b_off = (const float*)d_in[2];
    const float* w_mod = (const float*)d_in[3];
    const float* b_mod = (const float*)d_in[4];
    const float* w_dc  = (const float*)d_in[5];
    const float* gamma = (const float*)d_in[6];
    const float* beta  = (const float*)d_in[7];
    float* out = (float*)d_out;

    cudaFuncSetAttribute(k_conv_tc,  cudaFuncAttributeMaxDynamicSharedMemorySize, CONV_SMEM);
    cudaFuncSetAttribute(k_gemm_f16, cudaFuncAttributeMaxDynamicSharedMemorySize, GEMM_SMEM);

    k_prep<<<dim3(HWSZ / 32, CIN / 32, 9), dim3(32, 8)>>>(x, w_dc, w_off, w_mod);

    k_conv_tc<<<256, 256, CONV_SMEM>>>(b_off, b_mod);

    k_sample<<<dim3(HWSZ / 16, KK9, BATCH), dim3(16, 16)>>>();

    k_gemm_f16<<<dim3(ROWS / 64, 2), 256, GEMM_SMEM>>>();

    k_bn_final<<<1, 256>>>(gamma, beta);

    k_epilogue<<<dim3((BATCH * HWSZ) / 32, COUT / 32), dim3(32, 8)>>>(out);
}